// round 2
// baseline (speedup 1.0000x reference)
#include <cuda_runtime.h>
#include <cuda_bf16.h>
#include <math.h>

// Problem constants
#define D_MODEL 1024
#define N_HEADS 16
#define N_GROUPS 4
#define HEAD_DIM 64
#define KV_HEADS 4
#define D_KV 256
#define BATCH 2
#define SEQ 2048
#define BS (BATCH * SEQ)   // 4096

// Scratch buffers (device globals: no allocation allowed)
__device__ float g_Q[BS * D_MODEL];   // 16 MB
__device__ float g_K[BS * D_KV];      // 4 MB
__device__ float g_V[BS * D_KV];      // 4 MB
__device__ float g_O[BS * D_MODEL];   // 16 MB

// ---------------------------------------------------------------------------
// Tiled SGEMM: C[M,N] = A[M,K] @ B[K,N] + bias[N]
// BM=64, BN=64, BK=16, 256 threads, each computes 4x4.
// Assumes 64 | M, 64 | N, 16 | K.
// ---------------------------------------------------------------------------
__global__ __launch_bounds__(256) void sgemm_bias_kernel(
    const float* __restrict__ A, const float* __restrict__ B,
    const float* __restrict__ bias, float* __restrict__ C,
    int M, int N, int K)
{
    __shared__ float As[64][16];
    __shared__ float Bs[16][64];

    int tid = threadIdx.x;
    int ty = tid >> 4;      // 0..15
    int tx = tid & 15;      // 0..15
    int row0 = blockIdx.y * 64;
    int col0 = blockIdx.x * 64;

    // load indices
    int ar = tid >> 2;            // 0..63
    int ac = (tid & 3) * 4;       // 0,4,8,12
    int br = tid >> 4;            // 0..15
    int bc = (tid & 15) * 4;      // 0..60

    float acc[4][4];
    #pragma unroll
    for (int i = 0; i < 4; i++)
        #pragma unroll
        for (int j = 0; j < 4; j++) acc[i][j] = 0.f;

    for (int k0 = 0; k0 < K; k0 += 16) {
        float4 av = *(const float4*)(A + (size_t)(row0 + ar) * K + k0 + ac);
        float4 bv = *(const float4*)(B + (size_t)(k0 + br) * N + col0 + bc);
        *(float4*)(&As[ar][ac]) = av;
        *(float4*)(&Bs[br][bc]) = bv;
        __syncthreads();

        #pragma unroll
        for (int kk = 0; kk < 16; kk++) {
            float a[4], b[4];
            #pragma unroll
            for (int i = 0; i < 4; i++) a[i] = As[ty * 4 + i][kk];
            #pragma unroll
            for (int j = 0; j < 4; j++) b[j] = Bs[kk][tx * 4 + j];
            #pragma unroll
            for (int i = 0; i < 4; i++)
                #pragma unroll
                for (int j = 0; j < 4; j++)
                    acc[i][j] = fmaf(a[i], b[j], acc[i][j]);
        }
        __syncthreads();
    }

    #pragma unroll
    for (int i = 0; i < 4; i++) {
        int r = row0 + ty * 4 + i;
        #pragma unroll
        for (int j = 0; j < 4; j++) {
            int c = col0 + tx * 4 + j;
            C[(size_t)r * N + c] = acc[i][j] + bias[c];
        }
    }
}

// ---------------------------------------------------------------------------
// Flash attention (causal, GQA). One CTA = (b, h, 64-row q-tile).
// 128 threads. S=QK^T and O+=PV both use 4x8 register tiling (ty=tid/8,
// tx=tid%8). Softmax row-stats handled by thread pairs (tid/2 = row).
// ---------------------------------------------------------------------------
#define PAD 68   // row pitch (floats) for 64-wide smem tiles

__global__ __launch_bounds__(128) void fa_kernel(
    const float* __restrict__ Qb, const float* __restrict__ Kb,
    const float* __restrict__ Vb, float* __restrict__ Ob)
{
    extern __shared__ float sm[];
    float* Qs = sm;                    // 64*PAD
    float* Ks = sm + 64 * PAD;
    float* Vs = sm + 2 * 64 * PAD;
    float* Ss = sm + 3 * 64 * PAD;
    float* alpha_s = sm + 4 * 64 * PAD; // 64
    float* l_s = alpha_s + 64;          // 64

    int bh = blockIdx.x;               // 0..31
    int b = bh >> 4;
    int h = bh & 15;
    int kh = h >> 2;                   // kv head = h / N_GROUPS
    int qt = blockIdx.y;
    int q0 = qt * 64;
    int tid = threadIdx.x;

    // load Q tile [64 x 64]
    const float* Qg = Qb + ((size_t)(b * SEQ + q0)) * D_MODEL + h * HEAD_DIM;
    for (int idx = tid; idx < 64 * 64; idx += 128) {
        int r = idx >> 6, d = idx & 63;
        Qs[r * PAD + d] = Qg[(size_t)r * D_MODEL + d];
    }

    // softmax-owner mapping: 2 threads per row
    int srow = tid >> 1, shalf = tid & 1;
    float m_run = -INFINITY, l_run = 0.f;

    // gemm-tile mapping: 16x8 thread grid, each 4 rows x 8 cols
    int ty = tid >> 3, tx = tid & 7;
    int r0 = ty * 4, c0 = tx * 8;
    float acc[4][8];
    #pragma unroll
    for (int i = 0; i < 4; i++)
        #pragma unroll
        for (int j = 0; j < 8; j++) acc[i][j] = 0.f;

    const float scale = 0.125f;   // 1/sqrt(64)

    for (int kt = 0; kt <= qt; kt++) {
        int k0 = kt * 64;
        __syncthreads();   // protect K/V/Ss against previous iter readers

        const float* Kg = Kb + ((size_t)(b * SEQ + k0)) * D_KV + kh * HEAD_DIM;
        const float* Vg = Vb + ((size_t)(b * SEQ + k0)) * D_KV + kh * HEAD_DIM;
        for (int idx = tid; idx < 64 * 64; idx += 128) {
            int r = idx >> 6, d = idx & 63;
            Ks[r * PAD + d] = Kg[(size_t)r * D_KV + d];
            Vs[r * PAD + d] = Vg[(size_t)r * D_KV + d];
        }
        __syncthreads();

        // ---- S = Q K^T (register tiled) ----
        float s[4][8];
        #pragma unroll
        for (int i = 0; i < 4; i++)
            #pragma unroll
            for (int j = 0; j < 8; j++) s[i][j] = 0.f;

        #pragma unroll 8
        for (int d = 0; d < 64; d++) {
            float a[4], bb[8];
            #pragma unroll
            for (int i = 0; i < 4; i++) a[i] = Qs[(r0 + i) * PAD + d];
            #pragma unroll
            for (int j = 0; j < 8; j++) bb[j] = Ks[(c0 + j) * PAD + d];
            #pragma unroll
            for (int i = 0; i < 4; i++)
                #pragma unroll
                for (int j = 0; j < 8; j++)
                    s[i][j] = fmaf(a[i], bb[j], s[i][j]);
        }

        bool diag = (kt == qt);
        #pragma unroll
        for (int i = 0; i < 4; i++) {
            #pragma unroll
            for (int j = 0; j < 8; j++) {
                float v = s[i][j] * scale;
                if (diag && (c0 + j > r0 + i)) v = -INFINITY;  // k0==q0 on diag
                Ss[(r0 + i) * PAD + c0 + j] = v;
            }
        }
        __syncthreads();

        // ---- online softmax (2 threads per row) ----
        float pv[32];
        {
            const float* rowp = Ss + srow * PAD + shalf * 32;
            float tmax = -INFINITY;
            #pragma unroll
            for (int k = 0; k < 32; k++) {
                pv[k] = rowp[k];
                tmax = fmaxf(tmax, pv[k]);
            }
            tmax = fmaxf(tmax, __shfl_xor_sync(0xffffffffu, tmax, 1));
            float mnew = fmaxf(m_run, tmax);
            float tsum = 0.f;
            #pragma unroll
            for (int k = 0; k < 32; k++) {
                pv[k] = __expf(pv[k] - mnew);
                tsum += pv[k];
            }
            tsum += __shfl_xor_sync(0xffffffffu, tsum, 1);
            float alpha = __expf(m_run - mnew);
            l_run = l_run * alpha + tsum;
            m_run = mnew;
            float* roww = Ss + srow * PAD + shalf * 32;
            #pragma unroll
            for (int k = 0; k < 32; k++) roww[k] = pv[k];
            if (shalf == 0) alpha_s[srow] = alpha;
        }
        __syncthreads();

        // ---- O = alpha*O + P V (register tiled) ----
        float al[4];
        #pragma unroll
        for (int i = 0; i < 4; i++) al[i] = alpha_s[r0 + i];
        #pragma unroll
        for (int i = 0; i < 4; i++)
            #pragma unroll
            for (int j = 0; j < 8; j++) acc[i][j] *= al[i];

        #pragma unroll 8
        for (int j2 = 0; j2 < 64; j2++) {
            float p4[4], v8[8];
            #pragma unroll
            for (int i = 0; i < 4; i++) p4[i] = Ss[(r0 + i) * PAD + j2];
            #pragma unroll
            for (int j = 0; j < 8; j++) v8[j] = Vs[j2 * PAD + c0 + j];
            #pragma unroll
            for (int i = 0; i < 4; i++)
                #pragma unroll
                for (int j = 0; j < 8; j++)
                    acc[i][j] = fmaf(p4[i], v8[j], acc[i][j]);
        }
    }

    // publish row sums, normalize, write out
    if (shalf == 0) l_s[srow] = l_run;
    __syncthreads();

    float linv[4];
    #pragma unroll
    for (int i = 0; i < 4; i++) linv[i] = 1.0f / l_s[r0 + i];

    float* Og = Ob + ((size_t)(b * SEQ + q0)) * D_MODEL + h * HEAD_DIM;
    #pragma unroll
    for (int i = 0; i < 4; i++)
        #pragma unroll
        for (int j = 0; j < 8; j++)
            Og[(size_t)(r0 + i) * D_MODEL + c0 + j] = acc[i][j] * linv[i];
}

// ---------------------------------------------------------------------------
// Launch
// ---------------------------------------------------------------------------
extern "C" void kernel_launch(void* const* d_in, const int* in_sizes, int n_in,
                              void* d_out, int out_size)
{
    const float* x  = (const float*)d_in[0];
    const float* Wq = (const float*)d_in[1];
    const float* bq = (const float*)d_in[2];
    const float* Wk = (const float*)d_in[3];
    const float* bk = (const float*)d_in[4];
    const float* Wv = (const float*)d_in[5];
    const float* bv = (const float*)d_in[6];
    const float* Wo = (const float*)d_in[7];
    const float* bo = (const float*)d_in[8];
    // d_in[9] = mask (causal; computed implicitly)
    float* out = (float*)d_out;

    float *Qp, *Kp, *Vp, *Op;
    cudaGetSymbolAddress((void**)&Qp, g_Q);
    cudaGetSymbolAddress((void**)&Kp, g_K);
    cudaGetSymbolAddress((void**)&Vp, g_V);
    cudaGetSymbolAddress((void**)&Op, g_O);

    // projections
    {
        dim3 gq(D_MODEL / 64, BS / 64);
        sgemm_bias_kernel<<<gq, 256>>>(x, Wq, bq, Qp, BS, D_MODEL, D_MODEL);
        dim3 gkv(D_KV / 64, BS / 64);
        sgemm_bias_kernel<<<gkv, 256>>>(x, Wk, bk, Kp, BS, D_KV, D_MODEL);
        sgemm_bias_kernel<<<gkv, 256>>>(x, Wv, bv, Vp, BS, D_KV, D_MODEL);
    }

    // flash attention
    {
        size_t smem = (4 * 64 * PAD + 128) * sizeof(float);
        static bool attr_set = false;
        // setting an attribute is idempotent & deterministic; cheap to repeat
        cudaFuncSetAttribute(fa_kernel, cudaFuncAttributeMaxDynamicSharedMemorySize,
                             (int)smem);
        (void)attr_set;
        dim3 g(BATCH * N_HEADS, SEQ / 64);
        fa_kernel<<<g, 128, smem>>>(Qp, Kp, Vp, Op);
    }

    // output projection
    {
        dim3 go(D_MODEL / 64, BS / 64);
        sgemm_bias_kernel<<<go, 256>>>(Op, Wo, bo, out, BS, D_MODEL, D_MODEL);
    }
}

// round 3
// speedup vs baseline: 1.0040x; 1.0040x over previous
#include <cuda_runtime.h>
#include <cuda_bf16.h>
#include <math.h>

// Problem constants
#define D_MODEL 1024
#define N_HEADS 16
#define N_GROUPS 4
#define HEAD_DIM 64
#define KV_HEADS 4
#define D_KV 256
#define BATCH 2
#define SEQ 2048
#define BS (BATCH * SEQ)   // 4096

// Scratch buffers (device globals: no allocation allowed)
__device__ float g_Q[BS * D_MODEL];   // 16 MB
__device__ float g_K[BS * D_KV];      // 4 MB
__device__ float g_V[BS * D_KV];      // 4 MB
__device__ float g_O[BS * D_MODEL];   // 16 MB

// ---------------------------------------------------------------------------
// Tiled SGEMM: C[M,N] = A[M,K] @ B[K,N] + bias[N]
// BM=64, BN=64, BK=16, 256 threads, each computes 4x4.
// Assumes 64 | M, 64 | N, 16 | K.
// ---------------------------------------------------------------------------
__global__ __launch_bounds__(256) void sgemm_bias_kernel(
    const float* __restrict__ A, const float* __restrict__ B,
    const float* __restrict__ bias, float* __restrict__ C,
    int M, int N, int K)
{
    __shared__ float As[64][16];
    __shared__ float Bs[16][64];

    int tid = threadIdx.x;
    int ty = tid >> 4;      // 0..15
    int tx = tid & 15;      // 0..15
    int row0 = blockIdx.y * 64;
    int col0 = blockIdx.x * 64;

    // load indices
    int ar = tid >> 2;            // 0..63
    int ac = (tid & 3) * 4;       // 0,4,8,12
    int br = tid >> 4;            // 0..15
    int bc = (tid & 15) * 4;      // 0..60

    float acc[4][4];
    #pragma unroll
    for (int i = 0; i < 4; i++)
        #pragma unroll
        for (int j = 0; j < 4; j++) acc[i][j] = 0.f;

    for (int k0 = 0; k0 < K; k0 += 16) {
        float4 av = *(const float4*)(A + (size_t)(row0 + ar) * K + k0 + ac);
        float4 bv = *(const float4*)(B + (size_t)(k0 + br) * N + col0 + bc);
        *(float4*)(&As[ar][ac]) = av;
        *(float4*)(&Bs[br][bc]) = bv;
        __syncthreads();

        #pragma unroll
        for (int kk = 0; kk < 16; kk++) {
            float a[4], b[4];
            #pragma unroll
            for (int i = 0; i < 4; i++) a[i] = As[ty * 4 + i][kk];
            #pragma unroll
            for (int j = 0; j < 4; j++) b[j] = Bs[kk][tx * 4 + j];
            #pragma unroll
            for (int i = 0; i < 4; i++)
                #pragma unroll
                for (int j = 0; j < 4; j++)
                    acc[i][j] = fmaf(a[i], b[j], acc[i][j]);
        }
        __syncthreads();
    }

    #pragma unroll
    for (int i = 0; i < 4; i++) {
        int r = row0 + ty * 4 + i;
        #pragma unroll
        for (int j = 0; j < 4; j++) {
            int c = col0 + tx * 4 + j;
            C[(size_t)r * N + c] = acc[i][j] + bias[c];
        }
    }
}

// ---------------------------------------------------------------------------
// Flash attention (causal, GQA). One CTA = (b, h, 64-row q-tile).
// 128 threads. S=QK^T and O+=PV both use 4x8 register tiling (ty=tid/8,
// tx=tid%8). Softmax row-stats handled by thread pairs (tid/2 = row).
// ---------------------------------------------------------------------------
#define PAD 68   // row pitch (floats) for 64-wide smem tiles

__global__ __launch_bounds__(128) void fa_kernel(
    const float* __restrict__ Qb, const float* __restrict__ Kb,
    const float* __restrict__ Vb, float* __restrict__ Ob)
{
    extern __shared__ float sm[];
    float* Qs = sm;                    // 64*PAD
    float* Ks = sm + 64 * PAD;
    float* Vs = sm + 2 * 64 * PAD;
    float* Ss = sm + 3 * 64 * PAD;
    float* alpha_s = sm + 4 * 64 * PAD; // 64
    float* l_s = alpha_s + 64;          // 64

    int bh = blockIdx.x;               // 0..31
    int b = bh >> 4;
    int h = bh & 15;
    int kh = h >> 2;                   // kv head = h / N_GROUPS
    int qt = blockIdx.y;
    int q0 = qt * 64;
    int tid = threadIdx.x;

    // load Q tile [64 x 64]
    const float* Qg = Qb + ((size_t)(b * SEQ + q0)) * D_MODEL + h * HEAD_DIM;
    for (int idx = tid; idx < 64 * 64; idx += 128) {
        int r = idx >> 6, d = idx & 63;
        Qs[r * PAD + d] = Qg[(size_t)r * D_MODEL + d];
    }

    // softmax-owner mapping: 2 threads per row
    int srow = tid >> 1, shalf = tid & 1;
    float m_run = -INFINITY, l_run = 0.f;

    // gemm-tile mapping: 16x8 thread grid, each 4 rows x 8 cols
    int ty = tid >> 3, tx = tid & 7;
    int r0 = ty * 4, c0 = tx * 8;
    float acc[4][8];
    #pragma unroll
    for (int i = 0; i < 4; i++)
        #pragma unroll
        for (int j = 0; j < 8; j++) acc[i][j] = 0.f;

    const float scale = 0.125f;   // 1/sqrt(64)

    for (int kt = 0; kt <= qt; kt++) {
        int k0 = kt * 64;
        __syncthreads();   // protect K/V/Ss against previous iter readers

        const float* Kg = Kb + ((size_t)(b * SEQ + k0)) * D_KV + kh * HEAD_DIM;
        const float* Vg = Vb + ((size_t)(b * SEQ + k0)) * D_KV + kh * HEAD_DIM;
        for (int idx = tid; idx < 64 * 64; idx += 128) {
            int r = idx >> 6, d = idx & 63;
            Ks[r * PAD + d] = Kg[(size_t)r * D_KV + d];
            Vs[r * PAD + d] = Vg[(size_t)r * D_KV + d];
        }
        __syncthreads();

        // ---- S = Q K^T (register tiled) ----
        float s[4][8];
        #pragma unroll
        for (int i = 0; i < 4; i++)
            #pragma unroll
            for (int j = 0; j < 8; j++) s[i][j] = 0.f;

        #pragma unroll 8
        for (int d = 0; d < 64; d++) {
            float a[4], bb[8];
            #pragma unroll
            for (int i = 0; i < 4; i++) a[i] = Qs[(r0 + i) * PAD + d];
            #pragma unroll
            for (int j = 0; j < 8; j++) bb[j] = Ks[(c0 + j) * PAD + d];
            #pragma unroll
            for (int i = 0; i < 4; i++)
                #pragma unroll
                for (int j = 0; j < 8; j++)
                    s[i][j] = fmaf(a[i], bb[j], s[i][j]);
        }

        bool diag = (kt == qt);
        #pragma unroll
        for (int i = 0; i < 4; i++) {
            #pragma unroll
            for (int j = 0; j < 8; j++) {
                float v = s[i][j] * scale;
                if (diag && (c0 + j > r0 + i)) v = -INFINITY;  // k0==q0 on diag
                Ss[(r0 + i) * PAD + c0 + j] = v;
            }
        }
        __syncthreads();

        // ---- online softmax (2 threads per row) ----
        float pv[32];
        {
            const float* rowp = Ss + srow * PAD + shalf * 32;
            float tmax = -INFINITY;
            #pragma unroll
            for (int k = 0; k < 32; k++) {
                pv[k] = rowp[k];
                tmax = fmaxf(tmax, pv[k]);
            }
            tmax = fmaxf(tmax, __shfl_xor_sync(0xffffffffu, tmax, 1));
            float mnew = fmaxf(m_run, tmax);
            float tsum = 0.f;
            #pragma unroll
            for (int k = 0; k < 32; k++) {
                pv[k] = __expf(pv[k] - mnew);
                tsum += pv[k];
            }
            tsum += __shfl_xor_sync(0xffffffffu, tsum, 1);
            float alpha = __expf(m_run - mnew);
            l_run = l_run * alpha + tsum;
            m_run = mnew;
            float* roww = Ss + srow * PAD + shalf * 32;
            #pragma unroll
            for (int k = 0; k < 32; k++) roww[k] = pv[k];
            if (shalf == 0) alpha_s[srow] = alpha;
        }
        __syncthreads();

        // ---- O = alpha*O + P V (register tiled) ----
        float al[4];
        #pragma unroll
        for (int i = 0; i < 4; i++) al[i] = alpha_s[r0 + i];
        #pragma unroll
        for (int i = 0; i < 4; i++)
            #pragma unroll
            for (int j = 0; j < 8; j++) acc[i][j] *= al[i];

        #pragma unroll 8
        for (int j2 = 0; j2 < 64; j2++) {
            float p4[4], v8[8];
            #pragma unroll
            for (int i = 0; i < 4; i++) p4[i] = Ss[(r0 + i) * PAD + j2];
            #pragma unroll
            for (int j = 0; j < 8; j++) v8[j] = Vs[j2 * PAD + c0 + j];
            #pragma unroll
            for (int i = 0; i < 4; i++)
                #pragma unroll
                for (int j = 0; j < 8; j++)
                    acc[i][j] = fmaf(p4[i], v8[j], acc[i][j]);
        }
    }

    // publish row sums, normalize, write out
    if (shalf == 0) l_s[srow] = l_run;
    __syncthreads();

    float linv[4];
    #pragma unroll
    for (int i = 0; i < 4; i++) linv[i] = 1.0f / l_s[r0 + i];

    float* Og = Ob + ((size_t)(b * SEQ + q0)) * D_MODEL + h * HEAD_DIM;
    #pragma unroll
    for (int i = 0; i < 4; i++)
        #pragma unroll
        for (int j = 0; j < 8; j++)
            Og[(size_t)(r0 + i) * D_MODEL + c0 + j] = acc[i][j] * linv[i];
}

// ---------------------------------------------------------------------------
// Launch
// ---------------------------------------------------------------------------
extern "C" void kernel_launch(void* const* d_in, const int* in_sizes, int n_in,
                              void* d_out, int out_size)
{
    const float* x  = (const float*)d_in[0];
    const float* Wq = (const float*)d_in[1];
    const float* bq = (const float*)d_in[2];
    const float* Wk = (const float*)d_in[3];
    const float* bk = (const float*)d_in[4];
    const float* Wv = (const float*)d_in[5];
    const float* bv = (const float*)d_in[6];
    const float* Wo = (const float*)d_in[7];
    const float* bo = (const float*)d_in[8];
    // d_in[9] = mask (causal; computed implicitly)
    float* out = (float*)d_out;

    float *Qp, *Kp, *Vp, *Op;
    cudaGetSymbolAddress((void**)&Qp, g_Q);
    cudaGetSymbolAddress((void**)&Kp, g_K);
    cudaGetSymbolAddress((void**)&Vp, g_V);
    cudaGetSymbolAddress((void**)&Op, g_O);

    // projections
    {
        dim3 gq(D_MODEL / 64, BS / 64);
        sgemm_bias_kernel<<<gq, 256>>>(x, Wq, bq, Qp, BS, D_MODEL, D_MODEL);
        dim3 gkv(D_KV / 64, BS / 64);
        sgemm_bias_kernel<<<gkv, 256>>>(x, Wk, bk, Kp, BS, D_KV, D_MODEL);
        sgemm_bias_kernel<<<gkv, 256>>>(x, Wv, bv, Vp, BS, D_KV, D_MODEL);
    }

    // flash attention
    {
        size_t smem = (4 * 64 * PAD + 128) * sizeof(float);
        static bool attr_set = false;
        // setting an attribute is idempotent & deterministic; cheap to repeat
        cudaFuncSetAttribute(fa_kernel, cudaFuncAttributeMaxDynamicSharedMemorySize,
                             (int)smem);
        (void)attr_set;
        dim3 g(BATCH * N_HEADS, SEQ / 64);
        fa_kernel<<<g, 128, smem>>>(Qp, Kp, Vp, Op);
    }

    // output projection
    {
        dim3 go(D_MODEL / 64, BS / 64);
        sgemm_bias_kernel<<<go, 256>>>(Op, Wo, bo, out, BS, D_MODEL, D_MODEL);
    }
}

// round 4
// speedup vs baseline: 1.2444x; 1.2395x over previous
#include <cuda_runtime.h>
#include <cuda_bf16.h>
#include <math.h>
#include <stdint.h>

// Problem constants
#define D_MODEL 1024
#define N_HEADS 16
#define N_GROUPS 4
#define HEAD_DIM 64
#define KV_HEADS 4
#define D_KV 256
#define BATCH 2
#define SEQ 2048
#define BS (BATCH * SEQ)   // 4096

// Scratch buffers (device globals: no allocation allowed)
__device__ float g_Q[BS * D_MODEL];   // 16 MB
__device__ float g_K[BS * D_KV];      // 4 MB
__device__ float g_V[BS * D_KV];      // 4 MB
__device__ float g_O[BS * D_MODEL];   // 16 MB

// ---------------------------------------------------------------------------
// TF32 tensor-core GEMM: C[M,N] = A[M,K] @ B[K,N] + bias[N]
// BM=128, BN=128, BK=32. 256 threads = 8 warps in a 2(M) x 4(N) grid.
// Warp tile 64x32 = 4x4 m16n8k8 atoms. Register-prefetch pipeline.
// Requires 128|M, 128|N, 32|K.
// ---------------------------------------------------------------------------
#define GBM 128
#define GBN 128
#define GBK 32
#define AST 36    // As row stride (floats): 32 + 4 pad -> conflict-free frag loads
#define BST 136   // Bs row stride (floats): 128 + 8 pad -> conflict-free frag loads

__device__ __forceinline__ uint32_t f2tf32(float f) {
    uint32_t u;
    asm("cvt.rna.tf32.f32 %0, %1;" : "=r"(u) : "f"(f));
    return u;
}

__device__ __forceinline__ void mma_tf32(float c[4], const uint32_t a[4], const uint32_t b[2]) {
    asm volatile(
        "mma.sync.aligned.m16n8k8.row.col.f32.tf32.tf32.f32 "
        "{%0,%1,%2,%3}, {%4,%5,%6,%7}, {%8,%9}, {%0,%1,%2,%3};"
        : "+f"(c[0]), "+f"(c[1]), "+f"(c[2]), "+f"(c[3])
        : "r"(a[0]), "r"(a[1]), "r"(a[2]), "r"(a[3]), "r"(b[0]), "r"(b[1]));
}

__global__ __launch_bounds__(256) void gemm_tf32_bias(
    const float* __restrict__ A, const float* __restrict__ B,
    const float* __restrict__ bias, float* __restrict__ C,
    int M, int N, int K)
{
    __shared__ uint32_t As[GBM][AST];   // tf32 bits, [m][k]
    __shared__ uint32_t Bs[GBK][BST];   // tf32 bits, [k][n]

    const int tid = threadIdx.x;
    const int lane = tid & 31;
    const int wid = tid >> 5;
    const int warp_m = wid & 1;        // 0..1
    const int warp_n = wid >> 1;       // 0..3
    const int row0 = blockIdx.y * GBM;
    const int col0 = blockIdx.x * GBN;

    // global->reg load mapping
    const int a_r = tid >> 3;          // 0..31 (4 passes of +32 rows)
    const int a_c = (tid & 7) * 4;     // 0..28
    const int b_r = tid >> 5;          // 0..7  (4 passes of +8 rows)
    const int b_c = (tid & 31) * 4;    // 0..124

    const int gid = lane >> 2;         // groupID 0..7
    const int tig = lane & 3;          // thread-in-group 0..3

    float acc[4][4][4];
    #pragma unroll
    for (int i = 0; i < 4; i++)
        #pragma unroll
        for (int j = 0; j < 4; j++)
            #pragma unroll
            for (int r = 0; r < 4; r++) acc[i][j][r] = 0.f;

    float4 av[4], bv[4];

    // prologue: load tile k0=0
    #pragma unroll
    for (int p = 0; p < 4; p++) {
        av[p] = *(const float4*)(A + (size_t)(row0 + a_r + p * 32) * K + a_c);
        bv[p] = *(const float4*)(B + (size_t)(b_r + p * 8) * N + col0 + b_c);
    }

    for (int k0 = 0; k0 < K; k0 += GBK) {
        // store prefetched regs -> smem (with tf32 rounding)
        #pragma unroll
        for (int p = 0; p < 4; p++) {
            uint32_t* as = &As[a_r + p * 32][a_c];
            as[0] = f2tf32(av[p].x); as[1] = f2tf32(av[p].y);
            as[2] = f2tf32(av[p].z); as[3] = f2tf32(av[p].w);
            uint32_t* bs = &Bs[b_r + p * 8][b_c];
            bs[0] = f2tf32(bv[p].x); bs[1] = f2tf32(bv[p].y);
            bs[2] = f2tf32(bv[p].z); bs[3] = f2tf32(bv[p].w);
        }
        __syncthreads();

        // prefetch next tile
        int kn = k0 + GBK;
        if (kn < K) {
            #pragma unroll
            for (int p = 0; p < 4; p++) {
                av[p] = *(const float4*)(A + (size_t)(row0 + a_r + p * 32) * K + kn + a_c);
                bv[p] = *(const float4*)(B + (size_t)(kn + b_r + p * 8) * N + col0 + b_c);
            }
        }

        // compute: 4 k-steps of 8
        #pragma unroll
        for (int kk = 0; kk < 4; kk++) {
            uint32_t afr[4][4], bfr[4][2];
            #pragma unroll
            for (int i = 0; i < 4; i++) {
                int mr = warp_m * 64 + i * 16 + gid;
                int kc = kk * 8 + tig;
                afr[i][0] = As[mr][kc];
                afr[i][1] = As[mr + 8][kc];
                afr[i][2] = As[mr][kc + 4];
                afr[i][3] = As[mr + 8][kc + 4];
            }
            #pragma unroll
            for (int j = 0; j < 4; j++) {
                int nc = warp_n * 32 + j * 8 + gid;
                int kr = kk * 8 + tig;
                bfr[j][0] = Bs[kr][nc];
                bfr[j][1] = Bs[kr + 4][nc];
            }
            #pragma unroll
            for (int i = 0; i < 4; i++)
                #pragma unroll
                for (int j = 0; j < 4; j++)
                    mma_tf32(acc[i][j], afr[i], bfr[j]);
        }
        __syncthreads();
    }

    // epilogue: C = acc + bias
    #pragma unroll
    for (int i = 0; i < 4; i++) {
        int r = row0 + warp_m * 64 + i * 16 + gid;
        #pragma unroll
        for (int j = 0; j < 4; j++) {
            int c = col0 + warp_n * 32 + j * 8 + tig * 2;
            float b0 = bias[c], b1 = bias[c + 1];
            float2 v0 = make_float2(acc[i][j][0] + b0, acc[i][j][1] + b1);
            float2 v1 = make_float2(acc[i][j][2] + b0, acc[i][j][3] + b1);
            *(float2*)(C + (size_t)r * N + c) = v0;
            *(float2*)(C + (size_t)(r + 8) * N + c) = v1;
        }
    }
}

// ---------------------------------------------------------------------------
// Flash attention (causal, GQA). One CTA = (b, h, 64-row q-tile).
// 128 threads. (unchanged from round 0; converted to mma next round)
// ---------------------------------------------------------------------------
#define PAD 68   // row pitch (floats) for 64-wide smem tiles

__global__ __launch_bounds__(128) void fa_kernel(
    const float* __restrict__ Qb, const float* __restrict__ Kb,
    const float* __restrict__ Vb, float* __restrict__ Ob)
{
    extern __shared__ float sm[];
    float* Qs = sm;                    // 64*PAD
    float* Ks = sm + 64 * PAD;
    float* Vs = sm + 2 * 64 * PAD;
    float* Ss = sm + 3 * 64 * PAD;
    float* alpha_s = sm + 4 * 64 * PAD; // 64
    float* l_s = alpha_s + 64;          // 64

    int bh = blockIdx.x;               // 0..31
    int b = bh >> 4;
    int h = bh & 15;
    int kh = h >> 2;                   // kv head = h / N_GROUPS
    int qt = blockIdx.y;
    int q0 = qt * 64;
    int tid = threadIdx.x;

    // load Q tile [64 x 64]
    const float* Qg = Qb + ((size_t)(b * SEQ + q0)) * D_MODEL + h * HEAD_DIM;
    for (int idx = tid; idx < 64 * 64; idx += 128) {
        int r = idx >> 6, d = idx & 63;
        Qs[r * PAD + d] = Qg[(size_t)r * D_MODEL + d];
    }

    // softmax-owner mapping: 2 threads per row
    int srow = tid >> 1, shalf = tid & 1;
    float m_run = -INFINITY, l_run = 0.f;

    // gemm-tile mapping: 16x8 thread grid, each 4 rows x 8 cols
    int ty = tid >> 3, tx = tid & 7;
    int r0 = ty * 4, c0 = tx * 8;
    float acc[4][8];
    #pragma unroll
    for (int i = 0; i < 4; i++)
        #pragma unroll
        for (int j = 0; j < 8; j++) acc[i][j] = 0.f;

    const float scale = 0.125f;   // 1/sqrt(64)

    for (int kt = 0; kt <= qt; kt++) {
        int k0 = kt * 64;
        __syncthreads();   // protect K/V/Ss against previous iter readers

        const float* Kg = Kb + ((size_t)(b * SEQ + k0)) * D_KV + kh * HEAD_DIM;
        const float* Vg = Vb + ((size_t)(b * SEQ + k0)) * D_KV + kh * HEAD_DIM;
        for (int idx = tid; idx < 64 * 64; idx += 128) {
            int r = idx >> 6, d = idx & 63;
            Ks[r * PAD + d] = Kg[(size_t)r * D_KV + d];
            Vs[r * PAD + d] = Vg[(size_t)r * D_KV + d];
        }
        __syncthreads();

        // ---- S = Q K^T (register tiled) ----
        float s[4][8];
        #pragma unroll
        for (int i = 0; i < 4; i++)
            #pragma unroll
            for (int j = 0; j < 8; j++) s[i][j] = 0.f;

        #pragma unroll 8
        for (int d = 0; d < 64; d++) {
            float a[4], bb[8];
            #pragma unroll
            for (int i = 0; i < 4; i++) a[i] = Qs[(r0 + i) * PAD + d];
            #pragma unroll
            for (int j = 0; j < 8; j++) bb[j] = Ks[(c0 + j) * PAD + d];
            #pragma unroll
            for (int i = 0; i < 4; i++)
                #pragma unroll
                for (int j = 0; j < 8; j++)
                    s[i][j] = fmaf(a[i], bb[j], s[i][j]);
        }

        bool diag = (kt == qt);
        #pragma unroll
        for (int i = 0; i < 4; i++) {
            #pragma unroll
            for (int j = 0; j < 8; j++) {
                float v = s[i][j] * scale;
                if (diag && (c0 + j > r0 + i)) v = -INFINITY;  // k0==q0 on diag
                Ss[(r0 + i) * PAD + c0 + j] = v;
            }
        }
        __syncthreads();

        // ---- online softmax (2 threads per row) ----
        float pv[32];
        {
            const float* rowp = Ss + srow * PAD + shalf * 32;
            float tmax = -INFINITY;
            #pragma unroll
            for (int k = 0; k < 32; k++) {
                pv[k] = rowp[k];
                tmax = fmaxf(tmax, pv[k]);
            }
            tmax = fmaxf(tmax, __shfl_xor_sync(0xffffffffu, tmax, 1));
            float mnew = fmaxf(m_run, tmax);
            float tsum = 0.f;
            #pragma unroll
            for (int k = 0; k < 32; k++) {
                pv[k] = __expf(pv[k] - mnew);
                tsum += pv[k];
            }
            tsum += __shfl_xor_sync(0xffffffffu, tsum, 1);
            float alpha = __expf(m_run - mnew);
            l_run = l_run * alpha + tsum;
            m_run = mnew;
            float* roww = Ss + srow * PAD + shalf * 32;
            #pragma unroll
            for (int k = 0; k < 32; k++) roww[k] = pv[k];
            if (shalf == 0) alpha_s[srow] = alpha;
        }
        __syncthreads();

        // ---- O = alpha*O + P V (register tiled) ----
        float al[4];
        #pragma unroll
        for (int i = 0; i < 4; i++) al[i] = alpha_s[r0 + i];
        #pragma unroll
        for (int i = 0; i < 4; i++)
            #pragma unroll
            for (int j = 0; j < 8; j++) acc[i][j] *= al[i];

        #pragma unroll 8
        for (int j2 = 0; j2 < 64; j2++) {
            float p4[4], v8[8];
            #pragma unroll
            for (int i = 0; i < 4; i++) p4[i] = Ss[(r0 + i) * PAD + j2];
            #pragma unroll
            for (int j = 0; j < 8; j++) v8[j] = Vs[j2 * PAD + c0 + j];
            #pragma unroll
            for (int i = 0; i < 4; i++)
                #pragma unroll
                for (int j = 0; j < 8; j++)
                    acc[i][j] = fmaf(p4[i], v8[j], acc[i][j]);
        }
    }

    // publish row sums, normalize, write out
    if (shalf == 0) l_s[srow] = l_run;
    __syncthreads();

    float linv[4];
    #pragma unroll
    for (int i = 0; i < 4; i++) linv[i] = 1.0f / l_s[r0 + i];

    float* Og = Ob + ((size_t)(b * SEQ + q0)) * D_MODEL + h * HEAD_DIM;
    #pragma unroll
    for (int i = 0; i < 4; i++)
        #pragma unroll
        for (int j = 0; j < 8; j++)
            Og[(size_t)(r0 + i) * D_MODEL + c0 + j] = acc[i][j] * linv[i];
}

// ---------------------------------------------------------------------------
// Launch
// ---------------------------------------------------------------------------
extern "C" void kernel_launch(void* const* d_in, const int* in_sizes, int n_in,
                              void* d_out, int out_size)
{
    const float* x  = (const float*)d_in[0];
    const float* Wq = (const float*)d_in[1];
    const float* bq = (const float*)d_in[2];
    const float* Wk = (const float*)d_in[3];
    const float* bk = (const float*)d_in[4];
    const float* Wv = (const float*)d_in[5];
    const float* bv = (const float*)d_in[6];
    const float* Wo = (const float*)d_in[7];
    const float* bo = (const float*)d_in[8];
    // d_in[9] = mask (causal; computed implicitly)
    float* out = (float*)d_out;

    float *Qp, *Kp, *Vp, *Op;
    cudaGetSymbolAddress((void**)&Qp, g_Q);
    cudaGetSymbolAddress((void**)&Kp, g_K);
    cudaGetSymbolAddress((void**)&Vp, g_V);
    cudaGetSymbolAddress((void**)&Op, g_O);

    // projections (tf32 tensor cores)
    {
        dim3 gq(D_MODEL / GBN, BS / GBM);
        gemm_tf32_bias<<<gq, 256>>>(x, Wq, bq, Qp, BS, D_MODEL, D_MODEL);
        dim3 gkv(D_KV / GBN, BS / GBM);
        gemm_tf32_bias<<<gkv, 256>>>(x, Wk, bk, Kp, BS, D_KV, D_MODEL);
        gemm_tf32_bias<<<gkv, 256>>>(x, Wv, bv, Vp, BS, D_KV, D_MODEL);
    }

    // flash attention
    {
        size_t smem = (4 * 64 * PAD + 128) * sizeof(float);
        cudaFuncSetAttribute(fa_kernel, cudaFuncAttributeMaxDynamicSharedMemorySize,
                             (int)smem);
        dim3 g(BATCH * N_HEADS, SEQ / 64);
        fa_kernel<<<g, 128, smem>>>(Qp, Kp, Vp, Op);
    }

    // output projection (tf32 tensor cores)
    {
        dim3 go(D_MODEL / GBN, BS / GBM);
        gemm_tf32_bias<<<go, 256>>>(Op, Wo, bo, out, BS, D_MODEL, D_MODEL);
    }
}

// round 5
// speedup vs baseline: 3.7992x; 3.0529x over previous
#include <cuda_runtime.h>
#include <cuda_bf16.h>
#include <math.h>
#include <stdint.h>

// Problem constants
#define D_MODEL 1024
#define N_HEADS 16
#define N_GROUPS 4
#define HEAD_DIM 64
#define KV_HEADS 4
#define D_KV 256
#define BATCH 2
#define SEQ 2048
#define BS (BATCH * SEQ)   // 4096

// Scratch buffers (device globals: no allocation allowed)
__device__ float g_Q[BS * D_MODEL];   // 16 MB
__device__ float g_K[BS * D_KV];      // 4 MB
__device__ float g_V[BS * D_KV];      // 4 MB
__device__ float g_O[BS * D_MODEL];   // 16 MB

// ---------------------------------------------------------------------------
// Common tf32 helpers
// ---------------------------------------------------------------------------
__device__ __forceinline__ uint32_t f2tf32(float f) {
    uint32_t u;
    asm("cvt.rna.tf32.f32 %0, %1;" : "=r"(u) : "f"(f));
    return u;
}

__device__ __forceinline__ void mma_tf32(float c[4], const uint32_t a[4], const uint32_t b[2]) {
    asm volatile(
        "mma.sync.aligned.m16n8k8.row.col.f32.tf32.tf32.f32 "
        "{%0,%1,%2,%3}, {%4,%5,%6,%7}, {%8,%9}, {%0,%1,%2,%3};"
        : "+f"(c[0]), "+f"(c[1]), "+f"(c[2]), "+f"(c[3])
        : "r"(a[0]), "r"(a[1]), "r"(a[2]), "r"(a[3]), "r"(b[0]), "r"(b[1]));
}

// ---------------------------------------------------------------------------
// TF32 tensor-core GEMM: C[M,N] = A[M,K] @ B[K,N] + bias[N]
// BM=128, BN=128, BK=32. 256 threads = 8 warps (2x4). Warp tile 64x32.
// ---------------------------------------------------------------------------
#define GBM 128
#define GBN 128
#define GBK 32
#define AST 36
#define BST 136

__global__ __launch_bounds__(256) void gemm_tf32_bias(
    const float* __restrict__ A, const float* __restrict__ B,
    const float* __restrict__ bias, float* __restrict__ C,
    int M, int N, int K)
{
    __shared__ uint32_t As[GBM][AST];
    __shared__ uint32_t Bs[GBK][BST];

    const int tid = threadIdx.x;
    const int lane = tid & 31;
    const int wid = tid >> 5;
    const int warp_m = wid & 1;
    const int warp_n = wid >> 1;
    const int row0 = blockIdx.y * GBM;
    const int col0 = blockIdx.x * GBN;

    const int a_r = tid >> 3;
    const int a_c = (tid & 7) * 4;
    const int b_r = tid >> 5;
    const int b_c = (tid & 31) * 4;

    const int gid = lane >> 2;
    const int tig = lane & 3;

    float acc[4][4][4];
    #pragma unroll
    for (int i = 0; i < 4; i++)
        #pragma unroll
        for (int j = 0; j < 4; j++)
            #pragma unroll
            for (int r = 0; r < 4; r++) acc[i][j][r] = 0.f;

    float4 av[4], bv[4];

    #pragma unroll
    for (int p = 0; p < 4; p++) {
        av[p] = *(const float4*)(A + (size_t)(row0 + a_r + p * 32) * K + a_c);
        bv[p] = *(const float4*)(B + (size_t)(b_r + p * 8) * N + col0 + b_c);
    }

    for (int k0 = 0; k0 < K; k0 += GBK) {
        #pragma unroll
        for (int p = 0; p < 4; p++) {
            uint32_t* as = &As[a_r + p * 32][a_c];
            as[0] = f2tf32(av[p].x); as[1] = f2tf32(av[p].y);
            as[2] = f2tf32(av[p].z); as[3] = f2tf32(av[p].w);
            uint32_t* bs = &Bs[b_r + p * 8][b_c];
            bs[0] = f2tf32(bv[p].x); bs[1] = f2tf32(bv[p].y);
            bs[2] = f2tf32(bv[p].z); bs[3] = f2tf32(bv[p].w);
        }
        __syncthreads();

        int kn = k0 + GBK;
        if (kn < K) {
            #pragma unroll
            for (int p = 0; p < 4; p++) {
                av[p] = *(const float4*)(A + (size_t)(row0 + a_r + p * 32) * K + kn + a_c);
                bv[p] = *(const float4*)(B + (size_t)(kn + b_r + p * 8) * N + col0 + b_c);
            }
        }

        #pragma unroll
        for (int kk = 0; kk < 4; kk++) {
            uint32_t afr[4][4], bfr[4][2];
            #pragma unroll
            for (int i = 0; i < 4; i++) {
                int mr = warp_m * 64 + i * 16 + gid;
                int kc = kk * 8 + tig;
                afr[i][0] = As[mr][kc];
                afr[i][1] = As[mr + 8][kc];
                afr[i][2] = As[mr][kc + 4];
                afr[i][3] = As[mr + 8][kc + 4];
            }
            #pragma unroll
            for (int j = 0; j < 4; j++) {
                int nc = warp_n * 32 + j * 8 + gid;
                int kr = kk * 8 + tig;
                bfr[j][0] = Bs[kr][nc];
                bfr[j][1] = Bs[kr + 4][nc];
            }
            #pragma unroll
            for (int i = 0; i < 4; i++)
                #pragma unroll
                for (int j = 0; j < 4; j++)
                    mma_tf32(acc[i][j], afr[i], bfr[j]);
        }
        __syncthreads();
    }

    #pragma unroll
    for (int i = 0; i < 4; i++) {
        int r = row0 + warp_m * 64 + i * 16 + gid;
        #pragma unroll
        for (int j = 0; j < 4; j++) {
            int c = col0 + warp_n * 32 + j * 8 + tig * 2;
            float b0 = bias[c], b1 = bias[c + 1];
            float2 v0 = make_float2(acc[i][j][0] + b0, acc[i][j][1] + b1);
            float2 v1 = make_float2(acc[i][j][2] + b0, acc[i][j][3] + b1);
            *(float2*)(C + (size_t)r * N + c) = v0;
            *(float2*)(C + (size_t)(r + 8) * N + c) = v1;
        }
    }
}

// ---------------------------------------------------------------------------
// Flash attention with tensor cores (causal, GQA).
// One CTA = (b, h, 64-row q-tile). 128 threads = 4 warps, warp w owns rows
// [w*16, w*16+16). QK^T in tf32x3 (hi/lo split), PV in single tf32.
// S and O accumulators live in registers (m16n8 c-fragment layout); online
// softmax fully in registers via shfl over the 4 lanes sharing each row.
// ---------------------------------------------------------------------------
#define FPAD 68   // word pitch for arrays loaded with gid-row fragments (Q,K,P)
#define VPAD 72   // word pitch for arrays loaded with tig-row fragments (V)

__global__ __launch_bounds__(128) void fa_mma_kernel(
    const float* __restrict__ Qb, const float* __restrict__ Kb,
    const float* __restrict__ Vb, float* __restrict__ Ob)
{
    extern __shared__ uint32_t smu[];
    uint32_t* Qhi = smu;                  // 64*FPAD
    uint32_t* Qlo = Qhi + 64 * FPAD;
    uint32_t* Khi = Qlo + 64 * FPAD;
    uint32_t* Klo = Khi + 64 * FPAD;
    uint32_t* Ps  = Klo + 64 * FPAD;
    uint32_t* Vs  = Ps  + 64 * FPAD;      // 64*VPAD

    const int bh = blockIdx.x;            // 0..31
    const int b  = bh >> 4;
    const int h  = bh & 15;
    const int kh = h >> 2;
    const int qt = blockIdx.y;
    const int q0 = qt * 64;
    const int tid = threadIdx.x;
    const int lane = tid & 31;
    const int w = tid >> 5;
    const int gid = lane >> 2;            // 0..7
    const int tig = lane & 3;             // 0..3

    // ---- load Q tile, fold softmax scale (1/8, exact), split hi/lo ----
    const float* Qg = Qb + ((size_t)(b * SEQ + q0)) * D_MODEL + h * HEAD_DIM;
    for (int idx = tid; idx < 64 * 64; idx += 128) {
        int r = idx >> 6, d = idx & 63;
        float q = Qg[(size_t)r * D_MODEL + d] * 0.125f;
        uint32_t hi = f2tf32(q);
        Qhi[r * FPAD + d] = hi;
        Qlo[r * FPAD + d] = f2tf32(q - __uint_as_float(hi));
    }

    float m0 = -INFINITY, m1 = -INFINITY, l0 = 0.f, l1 = 0.f;
    float oacc[8][4];
    #pragma unroll
    for (int na = 0; na < 8; na++)
        #pragma unroll
        for (int c = 0; c < 4; c++) oacc[na][c] = 0.f;

    for (int kt = 0; kt <= qt; kt++) {
        int k0 = kt * 64;
        __syncthreads();   // prior iter's Ks/Vs/Ps readers done

        // ---- load K (hi/lo) and V (tf32) tiles ----
        const float* Kg = Kb + ((size_t)(b * SEQ + k0)) * D_KV + kh * HEAD_DIM;
        const float* Vg = Vb + ((size_t)(b * SEQ + k0)) * D_KV + kh * HEAD_DIM;
        for (int idx = tid; idx < 64 * 64; idx += 128) {
            int r = idx >> 6, d = idx & 63;
            float kv = Kg[(size_t)r * D_KV + d];
            uint32_t hi = f2tf32(kv);
            Khi[r * FPAD + d] = hi;
            Klo[r * FPAD + d] = f2tf32(kv - __uint_as_float(hi));
            Vs[r * VPAD + d] = f2tf32(Vg[(size_t)r * D_KV + d]);
        }
        __syncthreads();

        // ---- S = Q K^T (tf32x3) ----
        float sacc[8][4];
        #pragma unroll
        for (int na = 0; na < 8; na++)
            #pragma unroll
            for (int c = 0; c < 4; c++) sacc[na][c] = 0.f;

        #pragma unroll
        for (int kk = 0; kk < 8; kk++) {
            uint32_t ahi[4], alo[4];
            int ar = w * 16 + gid;
            int ac = kk * 8 + tig;
            ahi[0] = Qhi[ar * FPAD + ac];       ahi[1] = Qhi[(ar + 8) * FPAD + ac];
            ahi[2] = Qhi[ar * FPAD + ac + 4];   ahi[3] = Qhi[(ar + 8) * FPAD + ac + 4];
            alo[0] = Qlo[ar * FPAD + ac];       alo[1] = Qlo[(ar + 8) * FPAD + ac];
            alo[2] = Qlo[ar * FPAD + ac + 4];   alo[3] = Qlo[(ar + 8) * FPAD + ac + 4];
            #pragma unroll
            for (int na = 0; na < 8; na++) {
                int kr = na * 8 + gid;          // key row
                int kc = kk * 8 + tig;          // d
                uint32_t bhi[2] = { Khi[kr * FPAD + kc], Khi[kr * FPAD + kc + 4] };
                uint32_t blo[2] = { Klo[kr * FPAD + kc], Klo[kr * FPAD + kc + 4] };
                mma_tf32(sacc[na], ahi, bhi);
                mma_tf32(sacc[na], alo, bhi);
                mma_tf32(sacc[na], ahi, blo);
            }
        }

        // ---- causal mask on the diagonal tile ----
        if (kt == qt) {
            int rbase = w * 16 + gid;
            #pragma unroll
            for (int na = 0; na < 8; na++) {
                int cbase = na * 8 + tig * 2;
                if (cbase     > rbase)     sacc[na][0] = -INFINITY;
                if (cbase + 1 > rbase)     sacc[na][1] = -INFINITY;
                if (cbase     > rbase + 8) sacc[na][2] = -INFINITY;
                if (cbase + 1 > rbase + 8) sacc[na][3] = -INFINITY;
            }
        }

        // ---- online softmax in registers (rows gid, gid+8 of warp strip) ----
        float tm0 = -INFINITY, tm1 = -INFINITY;
        #pragma unroll
        for (int na = 0; na < 8; na++) {
            tm0 = fmaxf(tm0, fmaxf(sacc[na][0], sacc[na][1]));
            tm1 = fmaxf(tm1, fmaxf(sacc[na][2], sacc[na][3]));
        }
        tm0 = fmaxf(tm0, __shfl_xor_sync(0xffffffffu, tm0, 1));
        tm0 = fmaxf(tm0, __shfl_xor_sync(0xffffffffu, tm0, 2));
        tm1 = fmaxf(tm1, __shfl_xor_sync(0xffffffffu, tm1, 1));
        tm1 = fmaxf(tm1, __shfl_xor_sync(0xffffffffu, tm1, 2));

        float mn0 = fmaxf(m0, tm0), mn1 = fmaxf(m1, tm1);
        float ts0 = 0.f, ts1 = 0.f;
        #pragma unroll
        for (int na = 0; na < 8; na++) {
            sacc[na][0] = __expf(sacc[na][0] - mn0); ts0 += sacc[na][0];
            sacc[na][1] = __expf(sacc[na][1] - mn0); ts0 += sacc[na][1];
            sacc[na][2] = __expf(sacc[na][2] - mn1); ts1 += sacc[na][2];
            sacc[na][3] = __expf(sacc[na][3] - mn1); ts1 += sacc[na][3];
        }
        ts0 += __shfl_xor_sync(0xffffffffu, ts0, 1);
        ts0 += __shfl_xor_sync(0xffffffffu, ts0, 2);
        ts1 += __shfl_xor_sync(0xffffffffu, ts1, 1);
        ts1 += __shfl_xor_sync(0xffffffffu, ts1, 2);

        float a0 = __expf(m0 - mn0), a1 = __expf(m1 - mn1);
        l0 = l0 * a0 + ts0;
        l1 = l1 * a1 + ts1;
        m0 = mn0; m1 = mn1;

        #pragma unroll
        for (int na = 0; na < 8; na++) {
            oacc[na][0] *= a0; oacc[na][1] *= a0;
            oacc[na][2] *= a1; oacc[na][3] *= a1;
        }

        // ---- write P (tf32) to smem for A-fragment relayout ----
        {
            int pr = w * 16 + gid;
            #pragma unroll
            for (int na = 0; na < 8; na++) {
                int pc = na * 8 + tig * 2;
                Ps[pr * FPAD + pc]           = f2tf32(sacc[na][0]);
                Ps[pr * FPAD + pc + 1]       = f2tf32(sacc[na][1]);
                Ps[(pr + 8) * FPAD + pc]     = f2tf32(sacc[na][2]);
                Ps[(pr + 8) * FPAD + pc + 1] = f2tf32(sacc[na][3]);
            }
        }
        __syncthreads();

        // ---- O += P V ----
        #pragma unroll
        for (int kk = 0; kk < 8; kk++) {
            uint32_t ap[4];
            int ar = w * 16 + gid;
            int ac = kk * 8 + tig;
            ap[0] = Ps[ar * FPAD + ac];       ap[1] = Ps[(ar + 8) * FPAD + ac];
            ap[2] = Ps[ar * FPAD + ac + 4];   ap[3] = Ps[(ar + 8) * FPAD + ac + 4];
            #pragma unroll
            for (int na = 0; na < 8; na++) {
                uint32_t bv[2] = { Vs[(kk * 8 + tig) * VPAD + na * 8 + gid],
                                   Vs[(kk * 8 + tig + 4) * VPAD + na * 8 + gid] };
                mma_tf32(oacc[na], ap, bv);
            }
        }
    }

    // ---- normalize + write out ----
    float inv0 = 1.0f / l0, inv1 = 1.0f / l1;
    float* Og = Ob + ((size_t)(b * SEQ + q0)) * D_MODEL + h * HEAD_DIM;
    int r = w * 16 + gid;
    #pragma unroll
    for (int na = 0; na < 8; na++) {
        int c = na * 8 + tig * 2;
        float2 v0 = make_float2(oacc[na][0] * inv0, oacc[na][1] * inv0);
        float2 v1 = make_float2(oacc[na][2] * inv1, oacc[na][3] * inv1);
        *(float2*)(Og + (size_t)r * D_MODEL + c) = v0;
        *(float2*)(Og + (size_t)(r + 8) * D_MODEL + c) = v1;
    }
}

// ---------------------------------------------------------------------------
// Launch
// ---------------------------------------------------------------------------
extern "C" void kernel_launch(void* const* d_in, const int* in_sizes, int n_in,
                              void* d_out, int out_size)
{
    const float* x  = (const float*)d_in[0];
    const float* Wq = (const float*)d_in[1];
    const float* bq = (const float*)d_in[2];
    const float* Wk = (const float*)d_in[3];
    const float* bk = (const float*)d_in[4];
    const float* Wv = (const float*)d_in[5];
    const float* bv = (const float*)d_in[6];
    const float* Wo = (const float*)d_in[7];
    const float* bo = (const float*)d_in[8];
    // d_in[9] = mask (causal; computed implicitly)
    float* out = (float*)d_out;

    float *Qp, *Kp, *Vp, *Op;
    cudaGetSymbolAddress((void**)&Qp, g_Q);
    cudaGetSymbolAddress((void**)&Kp, g_K);
    cudaGetSymbolAddress((void**)&Vp, g_V);
    cudaGetSymbolAddress((void**)&Op, g_O);

    // projections (tf32 tensor cores)
    {
        dim3 gq(D_MODEL / GBN, BS / GBM);
        gemm_tf32_bias<<<gq, 256>>>(x, Wq, bq, Qp, BS, D_MODEL, D_MODEL);
        dim3 gkv(D_KV / GBN, BS / GBM);
        gemm_tf32_bias<<<gkv, 256>>>(x, Wk, bk, Kp, BS, D_KV, D_MODEL);
        gemm_tf32_bias<<<gkv, 256>>>(x, Wv, bv, Vp, BS, D_KV, D_MODEL);
    }

    // flash attention (tensor cores)
    {
        size_t smem = (size_t)(5 * 64 * FPAD + 64 * VPAD) * sizeof(uint32_t);
        cudaFuncSetAttribute(fa_mma_kernel, cudaFuncAttributeMaxDynamicSharedMemorySize,
                             (int)smem);
        dim3 g(BATCH * N_HEADS, SEQ / 64);
        fa_mma_kernel<<<g, 128, smem>>>(Qp, Kp, Vp, Op);
    }

    // output projection (tf32 tensor cores)
    {
        dim3 go(D_MODEL / GBN, BS / GBM);
        gemm_tf32_bias<<<go, 256>>>(Op, Wo, bo, out, BS, D_MODEL, D_MODEL);
    }
}

// round 6
// speedup vs baseline: 4.5450x; 1.1963x over previous
#include <cuda_runtime.h>
#include <cuda_bf16.h>
#include <math.h>
#include <stdint.h>

// Problem constants
#define D_MODEL 1024
#define N_HEADS 16
#define N_GROUPS 4
#define HEAD_DIM 64
#define KV_HEADS 4
#define D_KV 256
#define BATCH 2
#define SEQ 2048
#define BS (BATCH * SEQ)   // 4096

// Scratch buffers (device globals: no allocation allowed)
__device__ float g_Q[BS * D_MODEL];   // 16 MB
__device__ float g_K[BS * D_KV];      // 4 MB
__device__ float g_V[BS * D_KV];      // 4 MB
__device__ float g_O[BS * D_MODEL];   // 16 MB

// ---------------------------------------------------------------------------
// Common tf32 helpers
// ---------------------------------------------------------------------------
__device__ __forceinline__ uint32_t f2tf32(float f) {
    uint32_t u;
    asm("cvt.rna.tf32.f32 %0, %1;" : "=r"(u) : "f"(f));
    return u;
}

__device__ __forceinline__ void mma_tf32(float c[4], const uint32_t a[4], const uint32_t b[2]) {
    asm volatile(
        "mma.sync.aligned.m16n8k8.row.col.f32.tf32.tf32.f32 "
        "{%0,%1,%2,%3}, {%4,%5,%6,%7}, {%8,%9}, {%0,%1,%2,%3};"
        : "+f"(c[0]), "+f"(c[1]), "+f"(c[2]), "+f"(c[3])
        : "r"(a[0]), "r"(a[1]), "r"(a[2]), "r"(a[3]), "r"(b[0]), "r"(b[1]));
}

// ---------------------------------------------------------------------------
// TF32 tensor-core GEMM: C[M,N] = A[M,K] @ B[K,N] + bias[N]
// BM=128, BN=128, BK=32. 256 threads = 8 warps (2x4). Warp tile 64x32.
// ---------------------------------------------------------------------------
#define GBM 128
#define GBN 128
#define GBK 32
#define AST 36
#define BST 136

__global__ __launch_bounds__(256) void gemm_tf32_bias(
    const float* __restrict__ A, const float* __restrict__ B,
    const float* __restrict__ bias, float* __restrict__ C,
    int M, int N, int K)
{
    __shared__ uint32_t As[GBM][AST];
    __shared__ uint32_t Bs[GBK][BST];

    const int tid = threadIdx.x;
    const int lane = tid & 31;
    const int wid = tid >> 5;
    const int warp_m = wid & 1;
    const int warp_n = wid >> 1;
    const int row0 = blockIdx.y * GBM;
    const int col0 = blockIdx.x * GBN;

    const int a_r = tid >> 3;
    const int a_c = (tid & 7) * 4;
    const int b_r = tid >> 5;
    const int b_c = (tid & 31) * 4;

    const int gid = lane >> 2;
    const int tig = lane & 3;

    float acc[4][4][4];
    #pragma unroll
    for (int i = 0; i < 4; i++)
        #pragma unroll
        for (int j = 0; j < 4; j++)
            #pragma unroll
            for (int r = 0; r < 4; r++) acc[i][j][r] = 0.f;

    float4 av[4], bv[4];

    #pragma unroll
    for (int p = 0; p < 4; p++) {
        av[p] = *(const float4*)(A + (size_t)(row0 + a_r + p * 32) * K + a_c);
        bv[p] = *(const float4*)(B + (size_t)(b_r + p * 8) * N + col0 + b_c);
    }

    for (int k0 = 0; k0 < K; k0 += GBK) {
        #pragma unroll
        for (int p = 0; p < 4; p++) {
            uint32_t* as = &As[a_r + p * 32][a_c];
            as[0] = f2tf32(av[p].x); as[1] = f2tf32(av[p].y);
            as[2] = f2tf32(av[p].z); as[3] = f2tf32(av[p].w);
            uint32_t* bs = &Bs[b_r + p * 8][b_c];
            bs[0] = f2tf32(bv[p].x); bs[1] = f2tf32(bv[p].y);
            bs[2] = f2tf32(bv[p].z); bs[3] = f2tf32(bv[p].w);
        }
        __syncthreads();

        int kn = k0 + GBK;
        if (kn < K) {
            #pragma unroll
            for (int p = 0; p < 4; p++) {
                av[p] = *(const float4*)(A + (size_t)(row0 + a_r + p * 32) * K + kn + a_c);
                bv[p] = *(const float4*)(B + (size_t)(kn + b_r + p * 8) * N + col0 + b_c);
            }
        }

        #pragma unroll
        for (int kk = 0; kk < 4; kk++) {
            uint32_t afr[4][4], bfr[4][2];
            #pragma unroll
            for (int i = 0; i < 4; i++) {
                int mr = warp_m * 64 + i * 16 + gid;
                int kc = kk * 8 + tig;
                afr[i][0] = As[mr][kc];
                afr[i][1] = As[mr + 8][kc];
                afr[i][2] = As[mr][kc + 4];
                afr[i][3] = As[mr + 8][kc + 4];
            }
            #pragma unroll
            for (int j = 0; j < 4; j++) {
                int nc = warp_n * 32 + j * 8 + gid;
                int kr = kk * 8 + tig;
                bfr[j][0] = Bs[kr][nc];
                bfr[j][1] = Bs[kr + 4][nc];
            }
            #pragma unroll
            for (int i = 0; i < 4; i++)
                #pragma unroll
                for (int j = 0; j < 4; j++)
                    mma_tf32(acc[i][j], afr[i], bfr[j]);
        }
        __syncthreads();
    }

    #pragma unroll
    for (int i = 0; i < 4; i++) {
        int r = row0 + warp_m * 64 + i * 16 + gid;
        #pragma unroll
        for (int j = 0; j < 4; j++) {
            int c = col0 + warp_n * 32 + j * 8 + tig * 2;
            float b0 = bias[c], b1 = bias[c + 1];
            float2 v0 = make_float2(acc[i][j][0] + b0, acc[i][j][1] + b1);
            float2 v1 = make_float2(acc[i][j][2] + b0, acc[i][j][3] + b1);
            *(float2*)(C + (size_t)r * N + c) = v0;
            *(float2*)(C + (size_t)(r + 8) * N + c) = v1;
        }
    }
}

// ---------------------------------------------------------------------------
// Flash attention with tensor cores (causal, GQA).
// One CTA = (b, h, 64-row q-tile). 128 threads = 4 warps, warp w owns rows
// [w*16, w*16+16). QK^T in tf32x3, PV in tf32.
//  - Q hi/lo fragments live in registers (hoisted out of the kt loop)
//  - P C-fragment -> A-fragment relayout done with shuffles (no smem, no sync)
//  - smem holds only Khi/Klo/Vs (53 KB) -> 3 CTAs/SM
// ---------------------------------------------------------------------------
#define FPAD 68   // word pitch for K tiles (conflict-free gid-row frag loads)
#define VPAD 72   // word pitch for V tile (conflict-free tig-row frag loads)

__global__ __launch_bounds__(128, 3) void fa_mma_kernel(
    const float* __restrict__ Qb, const float* __restrict__ Kb,
    const float* __restrict__ Vb, float* __restrict__ Ob)
{
    extern __shared__ uint32_t smu[];
    uint32_t* Khi = smu;                  // 64*FPAD
    uint32_t* Klo = Khi + 64 * FPAD;
    uint32_t* Vs  = Klo + 64 * FPAD;      // 64*VPAD

    const int bh = blockIdx.x;            // 0..31
    const int b  = bh >> 4;
    const int h  = bh & 15;
    const int kh = h >> 2;
    const int qt = blockIdx.y;
    const int q0 = qt * 64;
    const int tid = threadIdx.x;
    const int lane = tid & 31;
    const int w = tid >> 5;
    const int gid = lane >> 2;            // 0..7
    const int tig = lane & 3;             // 0..3

    // ---- Q fragments in registers: scale by 1/8 (exact), hi/lo tf32 split ----
    uint32_t qhi[8][4], qlo[8][4];
    {
        const float* Qg = Qb + ((size_t)(b * SEQ + q0 + w * 16)) * D_MODEL + h * HEAD_DIM;
        #pragma unroll
        for (int kk = 0; kk < 8; kk++) {
            int c0 = kk * 8 + tig;
            float v[4];
            v[0] = Qg[(size_t)gid * D_MODEL + c0] * 0.125f;
            v[1] = Qg[(size_t)(gid + 8) * D_MODEL + c0] * 0.125f;
            v[2] = Qg[(size_t)gid * D_MODEL + c0 + 4] * 0.125f;
            v[3] = Qg[(size_t)(gid + 8) * D_MODEL + c0 + 4] * 0.125f;
            #pragma unroll
            for (int e = 0; e < 4; e++) {
                uint32_t hi = f2tf32(v[e]);
                qhi[kk][e] = hi;
                qlo[kk][e] = f2tf32(v[e] - __uint_as_float(hi));
            }
        }
    }

    float m0 = -INFINITY, m1 = -INFINITY, l0 = 0.f, l1 = 0.f;
    float oacc[8][4];
    #pragma unroll
    for (int na = 0; na < 8; na++)
        #pragma unroll
        for (int c = 0; c < 4; c++) oacc[na][c] = 0.f;

    const int src1 = gid * 4 + (tig >> 1);
    const int src2 = src1 + 2;
    const bool odd = tig & 1;

    for (int kt = 0; kt <= qt; kt++) {
        int k0 = kt * 64;
        __syncthreads();   // previous iter's K/V readers done

        // ---- cooperative load: K (hi/lo split) and V (tf32), float4 path ----
        const float* Kg = Kb + ((size_t)(b * SEQ + k0)) * D_KV + kh * HEAD_DIM;
        const float* Vg = Vb + ((size_t)(b * SEQ + k0)) * D_KV + kh * HEAD_DIM;
        #pragma unroll
        for (int p = 0; p < 8; p++) {
            int qi = tid + p * 128;       // 0..1023
            int r = qi >> 4, j4 = (qi & 15) * 4;
            float4 kv = *(const float4*)(Kg + (size_t)r * D_KV + j4);
            uint4 hi, lo;
            hi.x = f2tf32(kv.x); lo.x = f2tf32(kv.x - __uint_as_float(hi.x));
            hi.y = f2tf32(kv.y); lo.y = f2tf32(kv.y - __uint_as_float(hi.y));
            hi.z = f2tf32(kv.z); lo.z = f2tf32(kv.z - __uint_as_float(hi.z));
            hi.w = f2tf32(kv.w); lo.w = f2tf32(kv.w - __uint_as_float(hi.w));
            *(uint4*)(Khi + r * FPAD + j4) = hi;
            *(uint4*)(Klo + r * FPAD + j4) = lo;
            float4 vv = *(const float4*)(Vg + (size_t)r * D_KV + j4);
            uint4 vt;
            vt.x = f2tf32(vv.x); vt.y = f2tf32(vv.y);
            vt.z = f2tf32(vv.z); vt.w = f2tf32(vv.w);
            *(uint4*)(Vs + r * VPAD + j4) = vt;
        }
        __syncthreads();

        // ---- S = Q K^T (tf32x3) ----
        float sacc[8][4];
        #pragma unroll
        for (int na = 0; na < 8; na++)
            #pragma unroll
            for (int c = 0; c < 4; c++) sacc[na][c] = 0.f;

        #pragma unroll
        for (int kk = 0; kk < 8; kk++) {
            int kc = kk * 8 + tig;
            #pragma unroll
            for (int na = 0; na < 8; na++) {
                int kr = na * 8 + gid;
                uint32_t bhi[2] = { Khi[kr * FPAD + kc], Khi[kr * FPAD + kc + 4] };
                uint32_t blo[2] = { Klo[kr * FPAD + kc], Klo[kr * FPAD + kc + 4] };
                mma_tf32(sacc[na], qhi[kk], bhi);
                mma_tf32(sacc[na], qlo[kk], bhi);
                mma_tf32(sacc[na], qhi[kk], blo);
            }
        }

        // ---- causal mask on the diagonal tile ----
        if (kt == qt) {
            int rbase = w * 16 + gid;
            #pragma unroll
            for (int na = 0; na < 8; na++) {
                int cbase = na * 8 + tig * 2;
                if (cbase     > rbase)     sacc[na][0] = -INFINITY;
                if (cbase + 1 > rbase)     sacc[na][1] = -INFINITY;
                if (cbase     > rbase + 8) sacc[na][2] = -INFINITY;
                if (cbase + 1 > rbase + 8) sacc[na][3] = -INFINITY;
            }
        }

        // ---- online softmax (registers + 4-lane shfl reductions) ----
        float tm0 = -INFINITY, tm1 = -INFINITY;
        #pragma unroll
        for (int na = 0; na < 8; na++) {
            tm0 = fmaxf(tm0, fmaxf(sacc[na][0], sacc[na][1]));
            tm1 = fmaxf(tm1, fmaxf(sacc[na][2], sacc[na][3]));
        }
        tm0 = fmaxf(tm0, __shfl_xor_sync(0xffffffffu, tm0, 1));
        tm0 = fmaxf(tm0, __shfl_xor_sync(0xffffffffu, tm0, 2));
        tm1 = fmaxf(tm1, __shfl_xor_sync(0xffffffffu, tm1, 1));
        tm1 = fmaxf(tm1, __shfl_xor_sync(0xffffffffu, tm1, 2));

        float mn0 = fmaxf(m0, tm0), mn1 = fmaxf(m1, tm1);
        float ts0 = 0.f, ts1 = 0.f;
        #pragma unroll
        for (int na = 0; na < 8; na++) {
            sacc[na][0] = __expf(sacc[na][0] - mn0); ts0 += sacc[na][0];
            sacc[na][1] = __expf(sacc[na][1] - mn0); ts0 += sacc[na][1];
            sacc[na][2] = __expf(sacc[na][2] - mn1); ts1 += sacc[na][2];
            sacc[na][3] = __expf(sacc[na][3] - mn1); ts1 += sacc[na][3];
        }
        ts0 += __shfl_xor_sync(0xffffffffu, ts0, 1);
        ts0 += __shfl_xor_sync(0xffffffffu, ts0, 2);
        ts1 += __shfl_xor_sync(0xffffffffu, ts1, 1);
        ts1 += __shfl_xor_sync(0xffffffffu, ts1, 2);

        float a0 = __expf(m0 - mn0), a1 = __expf(m1 - mn1);
        l0 = l0 * a0 + ts0;
        l1 = l1 * a1 + ts1;
        m0 = mn0; m1 = mn1;

        #pragma unroll
        for (int na = 0; na < 8; na++) {
            oacc[na][0] *= a0; oacc[na][1] *= a0;
            oacc[na][2] *= a1; oacc[na][3] *= a1;
        }

        // ---- O += P V : P relayout C-frag -> A-frag via shuffles ----
        #pragma unroll
        for (int kk = 0; kk < 8; kk++) {
            float e0 = __shfl_sync(0xffffffffu, sacc[kk][0], src1);
            float e1 = __shfl_sync(0xffffffffu, sacc[kk][1], src1);
            float e2 = __shfl_sync(0xffffffffu, sacc[kk][2], src1);
            float e3 = __shfl_sync(0xffffffffu, sacc[kk][3], src1);
            float f0 = __shfl_sync(0xffffffffu, sacc[kk][0], src2);
            float f1 = __shfl_sync(0xffffffffu, sacc[kk][1], src2);
            float f2 = __shfl_sync(0xffffffffu, sacc[kk][2], src2);
            float f3 = __shfl_sync(0xffffffffu, sacc[kk][3], src2);
            uint32_t ap[4];
            ap[0] = f2tf32(odd ? e1 : e0);   // P[gid][kk*8+tig]
            ap[1] = f2tf32(odd ? e3 : e2);   // P[gid+8][kk*8+tig]
            ap[2] = f2tf32(odd ? f1 : f0);   // P[gid][kk*8+tig+4]
            ap[3] = f2tf32(odd ? f3 : f2);   // P[gid+8][kk*8+tig+4]
            int vr = kk * 8 + tig;
            #pragma unroll
            for (int na = 0; na < 8; na++) {
                uint32_t bv[2] = { Vs[vr * VPAD + na * 8 + gid],
                                   Vs[(vr + 4) * VPAD + na * 8 + gid] };
                mma_tf32(oacc[na], ap, bv);
            }
        }
    }

    // ---- normalize + write out ----
    float inv0 = 1.0f / l0, inv1 = 1.0f / l1;
    float* Og = Ob + ((size_t)(b * SEQ + q0)) * D_MODEL + h * HEAD_DIM;
    int r = w * 16 + gid;
    #pragma unroll
    for (int na = 0; na < 8; na++) {
        int c = na * 8 + tig * 2;
        float2 v0 = make_float2(oacc[na][0] * inv0, oacc[na][1] * inv0);
        float2 v1 = make_float2(oacc[na][2] * inv1, oacc[na][3] * inv1);
        *(float2*)(Og + (size_t)r * D_MODEL + c) = v0;
        *(float2*)(Og + (size_t)(r + 8) * D_MODEL + c) = v1;
    }
}

// ---------------------------------------------------------------------------
// Launch
// ---------------------------------------------------------------------------
extern "C" void kernel_launch(void* const* d_in, const int* in_sizes, int n_in,
                              void* d_out, int out_size)
{
    const float* x  = (const float*)d_in[0];
    const float* Wq = (const float*)d_in[1];
    const float* bq = (const float*)d_in[2];
    const float* Wk = (const float*)d_in[3];
    const float* bk = (const float*)d_in[4];
    const float* Wv = (const float*)d_in[5];
    const float* bv = (const float*)d_in[6];
    const float* Wo = (const float*)d_in[7];
    const float* bo = (const float*)d_in[8];
    // d_in[9] = mask (causal; computed implicitly)
    float* out = (float*)d_out;

    float *Qp, *Kp, *Vp, *Op;
    cudaGetSymbolAddress((void**)&Qp, g_Q);
    cudaGetSymbolAddress((void**)&Kp, g_K);
    cudaGetSymbolAddress((void**)&Vp, g_V);
    cudaGetSymbolAddress((void**)&Op, g_O);

    // projections (tf32 tensor cores)
    {
        dim3 gq(D_MODEL / GBN, BS / GBM);
        gemm_tf32_bias<<<gq, 256>>>(x, Wq, bq, Qp, BS, D_MODEL, D_MODEL);
        dim3 gkv(D_KV / GBN, BS / GBM);
        gemm_tf32_bias<<<gkv, 256>>>(x, Wk, bk, Kp, BS, D_KV, D_MODEL);
        gemm_tf32_bias<<<gkv, 256>>>(x, Wv, bv, Vp, BS, D_KV, D_MODEL);
    }

    // flash attention (tensor cores)
    {
        size_t smem = (size_t)(2 * 64 * FPAD + 64 * VPAD) * sizeof(uint32_t);
        cudaFuncSetAttribute(fa_mma_kernel, cudaFuncAttributeMaxDynamicSharedMemorySize,
                             (int)smem);
        dim3 g(BATCH * N_HEADS, SEQ / 64);
        fa_mma_kernel<<<g, 128, smem>>>(Qp, Kp, Vp, Op);
    }

    // output projection (tf32 tensor cores)
    {
        dim3 go(D_MODEL / GBN, BS / GBM);
        gemm_tf32_bias<<<go, 256>>>(Op, Wo, bo, out, BS, D_MODEL, D_MODEL);
    }
}

// round 7
// speedup vs baseline: 5.6938x; 1.2528x over previous
#include <cuda_runtime.h>
#include <cuda_bf16.h>
#include <math.h>
#include <stdint.h>

// Problem constants
#define D_MODEL 1024
#define N_HEADS 16
#define N_GROUPS 4
#define HEAD_DIM 64
#define KV_HEADS 4
#define D_KV 256
#define BATCH 2
#define SEQ 2048
#define BS (BATCH * SEQ)   // 4096

// Scratch buffers (device globals: no allocation allowed)
__device__ float g_Q[BS * D_MODEL];   // 16 MB
__device__ float g_K[BS * D_KV];      // 4 MB
__device__ float g_V[BS * D_KV];      // 4 MB
__device__ float g_O[BS * D_MODEL];   // 16 MB

// ---------------------------------------------------------------------------
// Common tf32 helpers
// ---------------------------------------------------------------------------
__device__ __forceinline__ uint32_t f2tf32(float f) {
    uint32_t u;
    asm("cvt.rna.tf32.f32 %0, %1;" : "=r"(u) : "f"(f));
    return u;
}

__device__ __forceinline__ void mma_tf32(float c[4], const uint32_t a[4], const uint32_t b[2]) {
    asm volatile(
        "mma.sync.aligned.m16n8k8.row.col.f32.tf32.tf32.f32 "
        "{%0,%1,%2,%3}, {%4,%5,%6,%7}, {%8,%9}, {%0,%1,%2,%3};"
        : "+f"(c[0]), "+f"(c[1]), "+f"(c[2]), "+f"(c[3])
        : "r"(a[0]), "r"(a[1]), "r"(a[2]), "r"(a[3]), "r"(b[0]), "r"(b[1]));
}

// ---------------------------------------------------------------------------
// TF32 tensor-core GEMM body: C[M,N] = A[M,K] @ B[K,N] + bias[N]
// BM=128, BN=128, BK=32. 256 threads = 8 warps (2x4). Warp tile 64x32.
// ---------------------------------------------------------------------------
#define GBM 128
#define GBN 128
#define GBK 32
#define AST 36
#define BST 136

__device__ __forceinline__ void gemm_body(
    const float* __restrict__ A, const float* __restrict__ B,
    const float* __restrict__ bias, float* __restrict__ C,
    int N, int K, int row0, int col0,
    uint32_t (*As)[AST], uint32_t (*Bs)[BST])
{
    const int tid = threadIdx.x;
    const int lane = tid & 31;
    const int wid = tid >> 5;
    const int warp_m = wid & 1;
    const int warp_n = wid >> 1;

    const int a_r = tid >> 3;
    const int a_c = (tid & 7) * 4;
    const int b_r = tid >> 5;
    const int b_c = (tid & 31) * 4;

    const int gid = lane >> 2;
    const int tig = lane & 3;

    float acc[4][4][4];
    #pragma unroll
    for (int i = 0; i < 4; i++)
        #pragma unroll
        for (int j = 0; j < 4; j++)
            #pragma unroll
            for (int r = 0; r < 4; r++) acc[i][j][r] = 0.f;

    float4 av[4], bv[4];

    #pragma unroll
    for (int p = 0; p < 4; p++) {
        av[p] = *(const float4*)(A + (size_t)(row0 + a_r + p * 32) * K + a_c);
        bv[p] = *(const float4*)(B + (size_t)(b_r + p * 8) * N + col0 + b_c);
    }

    for (int k0 = 0; k0 < K; k0 += GBK) {
        #pragma unroll
        for (int p = 0; p < 4; p++) {
            uint32_t* as = &As[a_r + p * 32][a_c];
            as[0] = f2tf32(av[p].x); as[1] = f2tf32(av[p].y);
            as[2] = f2tf32(av[p].z); as[3] = f2tf32(av[p].w);
            uint32_t* bs = &Bs[b_r + p * 8][b_c];
            bs[0] = f2tf32(bv[p].x); bs[1] = f2tf32(bv[p].y);
            bs[2] = f2tf32(bv[p].z); bs[3] = f2tf32(bv[p].w);
        }
        __syncthreads();

        int kn = k0 + GBK;
        if (kn < K) {
            #pragma unroll
            for (int p = 0; p < 4; p++) {
                av[p] = *(const float4*)(A + (size_t)(row0 + a_r + p * 32) * K + kn + a_c);
                bv[p] = *(const float4*)(B + (size_t)(kn + b_r + p * 8) * N + col0 + b_c);
            }
        }

        #pragma unroll
        for (int kk = 0; kk < 4; kk++) {
            uint32_t afr[4][4], bfr[4][2];
            #pragma unroll
            for (int i = 0; i < 4; i++) {
                int mr = warp_m * 64 + i * 16 + gid;
                int kc = kk * 8 + tig;
                afr[i][0] = As[mr][kc];
                afr[i][1] = As[mr + 8][kc];
                afr[i][2] = As[mr][kc + 4];
                afr[i][3] = As[mr + 8][kc + 4];
            }
            #pragma unroll
            for (int j = 0; j < 4; j++) {
                int nc = warp_n * 32 + j * 8 + gid;
                int kr = kk * 8 + tig;
                bfr[j][0] = Bs[kr][nc];
                bfr[j][1] = Bs[kr + 4][nc];
            }
            #pragma unroll
            for (int i = 0; i < 4; i++)
                #pragma unroll
                for (int j = 0; j < 4; j++)
                    mma_tf32(acc[i][j], afr[i], bfr[j]);
        }
        __syncthreads();
    }

    #pragma unroll
    for (int i = 0; i < 4; i++) {
        int r = row0 + warp_m * 64 + i * 16 + gid;
        #pragma unroll
        for (int j = 0; j < 4; j++) {
            int c = col0 + warp_n * 32 + j * 8 + tig * 2;
            float b0 = bias[c], b1 = bias[c + 1];
            float2 v0 = make_float2(acc[i][j][0] + b0, acc[i][j][1] + b1);
            float2 v1 = make_float2(acc[i][j][2] + b0, acc[i][j][3] + b1);
            *(float2*)(C + (size_t)r * N + c) = v0;
            *(float2*)(C + (size_t)(r + 8) * N + c) = v1;
        }
    }
}

// Fused QKV projection: blockIdx.x 0..7 -> Q cols, 8..9 -> K, 10..11 -> V
__global__ __launch_bounds__(256) void gemm_qkv_fused(
    const float* __restrict__ x,
    const float* __restrict__ Wq, const float* __restrict__ bq, float* __restrict__ Qo,
    const float* __restrict__ Wk, const float* __restrict__ bk, float* __restrict__ Ko,
    const float* __restrict__ Wv, const float* __restrict__ bv, float* __restrict__ Vo)
{
    __shared__ uint32_t As[GBM][AST];
    __shared__ uint32_t Bs[GBK][BST];

    const int bx = blockIdx.x;
    const int row0 = blockIdx.y * GBM;

    const float* B; const float* bias; float* C; int N, col0;
    if (bx < 8)       { B = Wq; bias = bq; C = Qo; N = D_MODEL; col0 = bx * GBN; }
    else if (bx < 10) { B = Wk; bias = bk; C = Ko; N = D_KV;    col0 = (bx - 8) * GBN; }
    else              { B = Wv; bias = bv; C = Vo; N = D_KV;    col0 = (bx - 10) * GBN; }

    gemm_body(x, B, bias, C, N, D_MODEL, row0, col0, As, Bs);
}

// Plain GEMM (output projection)
__global__ __launch_bounds__(256) void gemm_tf32_bias(
    const float* __restrict__ A, const float* __restrict__ B,
    const float* __restrict__ bias, float* __restrict__ C,
    int M, int N, int K)
{
    __shared__ uint32_t As[GBM][AST];
    __shared__ uint32_t Bs[GBK][BST];
    gemm_body(A, B, bias, C, N, K, blockIdx.y * GBM, blockIdx.x * GBN, As, Bs);
}

// ---------------------------------------------------------------------------
// Flash attention with tensor cores (causal, GQA).
// One CTA = (b, h, 64-row q-tile). 128 threads = 4 warps, warp w owns rows
// [w*16, w*16+16).
//  - QK^T in tf32x2: Q hi/lo split (exact) in registers, K single tf32 in smem
//  - PV in single tf32
//  - P C-frag -> A-frag relayout via shuffles (no smem round trip)
//  - smem: Ks + Vs only (35 KB)
// ---------------------------------------------------------------------------
#define FPAD 68   // word pitch for K tile (conflict-free gid-row frag loads)
#define VPAD 72   // word pitch for V tile (conflict-free tig-row frag loads)

__global__ __launch_bounds__(128, 3) void fa_mma_kernel(
    const float* __restrict__ Qb, const float* __restrict__ Kb,
    const float* __restrict__ Vb, float* __restrict__ Ob)
{
    extern __shared__ uint32_t smu[];
    uint32_t* Ks = smu;                   // 64*FPAD
    uint32_t* Vs = Ks + 64 * FPAD;        // 64*VPAD

    const int bh = blockIdx.x;            // 0..31
    const int b  = bh >> 4;
    const int h  = bh & 15;
    const int kh = h >> 2;
    const int qt = blockIdx.y;
    const int q0 = qt * 64;
    const int tid = threadIdx.x;
    const int lane = tid & 31;
    const int w = tid >> 5;
    const int gid = lane >> 2;            // 0..7
    const int tig = lane & 3;             // 0..3

    // ---- Q fragments in registers: scale by 1/8 (exact), hi/lo tf32 split ----
    uint32_t qhi[8][4], qlo[8][4];
    {
        const float* Qg = Qb + ((size_t)(b * SEQ + q0 + w * 16)) * D_MODEL + h * HEAD_DIM;
        #pragma unroll
        for (int kk = 0; kk < 8; kk++) {
            int c0 = kk * 8 + tig;
            float v[4];
            v[0] = Qg[(size_t)gid * D_MODEL + c0] * 0.125f;
            v[1] = Qg[(size_t)(gid + 8) * D_MODEL + c0] * 0.125f;
            v[2] = Qg[(size_t)gid * D_MODEL + c0 + 4] * 0.125f;
            v[3] = Qg[(size_t)(gid + 8) * D_MODEL + c0 + 4] * 0.125f;
            #pragma unroll
            for (int e = 0; e < 4; e++) {
                uint32_t hi = f2tf32(v[e]);
                qhi[kk][e] = hi;
                qlo[kk][e] = f2tf32(v[e] - __uint_as_float(hi));
            }
        }
    }

    float m0 = -INFINITY, m1 = -INFINITY, l0 = 0.f, l1 = 0.f;
    float oacc[8][4];
    #pragma unroll
    for (int na = 0; na < 8; na++)
        #pragma unroll
        for (int c = 0; c < 4; c++) oacc[na][c] = 0.f;

    const int src1 = gid * 4 + (tig >> 1);
    const int src2 = src1 + 2;
    const bool odd = tig & 1;

    for (int kt = 0; kt <= qt; kt++) {
        int k0 = kt * 64;
        __syncthreads();   // previous iter's K/V readers done

        // ---- cooperative load: K (single tf32) and V (tf32), float4 path ----
        const float* Kg = Kb + ((size_t)(b * SEQ + k0)) * D_KV + kh * HEAD_DIM;
        const float* Vg = Vb + ((size_t)(b * SEQ + k0)) * D_KV + kh * HEAD_DIM;
        #pragma unroll
        for (int p = 0; p < 8; p++) {
            int qi = tid + p * 128;       // 0..1023
            int r = qi >> 4, j4 = (qi & 15) * 4;
            float4 kv = *(const float4*)(Kg + (size_t)r * D_KV + j4);
            uint4 kt4;
            kt4.x = f2tf32(kv.x); kt4.y = f2tf32(kv.y);
            kt4.z = f2tf32(kv.z); kt4.w = f2tf32(kv.w);
            *(uint4*)(Ks + r * FPAD + j4) = kt4;
            float4 vv = *(const float4*)(Vg + (size_t)r * D_KV + j4);
            uint4 vt;
            vt.x = f2tf32(vv.x); vt.y = f2tf32(vv.y);
            vt.z = f2tf32(vv.z); vt.w = f2tf32(vv.w);
            *(uint4*)(Vs + r * VPAD + j4) = vt;
        }
        __syncthreads();

        // ---- S = Q K^T (tf32x2: exact Q, single-rounded K) ----
        float sacc[8][4];
        #pragma unroll
        for (int na = 0; na < 8; na++)
            #pragma unroll
            for (int c = 0; c < 4; c++) sacc[na][c] = 0.f;

        #pragma unroll
        for (int kk = 0; kk < 8; kk++) {
            int kc = kk * 8 + tig;
            #pragma unroll
            for (int na = 0; na < 8; na++) {
                int kr = na * 8 + gid;
                uint32_t bf[2] = { Ks[kr * FPAD + kc], Ks[kr * FPAD + kc + 4] };
                mma_tf32(sacc[na], qhi[kk], bf);
                mma_tf32(sacc[na], qlo[kk], bf);
            }
        }

        // ---- causal mask on the diagonal tile ----
        if (kt == qt) {
            int rbase = w * 16 + gid;
            #pragma unroll
            for (int na = 0; na < 8; na++) {
                int cbase = na * 8 + tig * 2;
                if (cbase     > rbase)     sacc[na][0] = -INFINITY;
                if (cbase + 1 > rbase)     sacc[na][1] = -INFINITY;
                if (cbase     > rbase + 8) sacc[na][2] = -INFINITY;
                if (cbase + 1 > rbase + 8) sacc[na][3] = -INFINITY;
            }
        }

        // ---- online softmax (registers + 4-lane shfl reductions) ----
        float tm0 = -INFINITY, tm1 = -INFINITY;
        #pragma unroll
        for (int na = 0; na < 8; na++) {
            tm0 = fmaxf(tm0, fmaxf(sacc[na][0], sacc[na][1]));
            tm1 = fmaxf(tm1, fmaxf(sacc[na][2], sacc[na][3]));
        }
        tm0 = fmaxf(tm0, __shfl_xor_sync(0xffffffffu, tm0, 1));
        tm0 = fmaxf(tm0, __shfl_xor_sync(0xffffffffu, tm0, 2));
        tm1 = fmaxf(tm1, __shfl_xor_sync(0xffffffffu, tm1, 1));
        tm1 = fmaxf(tm1, __shfl_xor_sync(0xffffffffu, tm1, 2));

        float mn0 = fmaxf(m0, tm0), mn1 = fmaxf(m1, tm1);
        float ts0 = 0.f, ts1 = 0.f;
        #pragma unroll
        for (int na = 0; na < 8; na++) {
            sacc[na][0] = __expf(sacc[na][0] - mn0); ts0 += sacc[na][0];
            sacc[na][1] = __expf(sacc[na][1] - mn0); ts0 += sacc[na][1];
            sacc[na][2] = __expf(sacc[na][2] - mn1); ts1 += sacc[na][2];
            sacc[na][3] = __expf(sacc[na][3] - mn1); ts1 += sacc[na][3];
        }
        ts0 += __shfl_xor_sync(0xffffffffu, ts0, 1);
        ts0 += __shfl_xor_sync(0xffffffffu, ts0, 2);
        ts1 += __shfl_xor_sync(0xffffffffu, ts1, 1);
        ts1 += __shfl_xor_sync(0xffffffffu, ts1, 2);

        float a0 = __expf(m0 - mn0), a1 = __expf(m1 - mn1);
        l0 = l0 * a0 + ts0;
        l1 = l1 * a1 + ts1;
        m0 = mn0; m1 = mn1;

        #pragma unroll
        for (int na = 0; na < 8; na++) {
            oacc[na][0] *= a0; oacc[na][1] *= a0;
            oacc[na][2] *= a1; oacc[na][3] *= a1;
        }

        // ---- O += P V : P relayout C-frag -> A-frag via shuffles ----
        #pragma unroll
        for (int kk = 0; kk < 8; kk++) {
            float e0 = __shfl_sync(0xffffffffu, sacc[kk][0], src1);
            float e1 = __shfl_sync(0xffffffffu, sacc[kk][1], src1);
            float e2 = __shfl_sync(0xffffffffu, sacc[kk][2], src1);
            float e3 = __shfl_sync(0xffffffffu, sacc[kk][3], src1);
            float f0 = __shfl_sync(0xffffffffu, sacc[kk][0], src2);
            float f1 = __shfl_sync(0xffffffffu, sacc[kk][1], src2);
            float f2 = __shfl_sync(0xffffffffu, sacc[kk][2], src2);
            float f3 = __shfl_sync(0xffffffffu, sacc[kk][3], src2);
            uint32_t ap[4];
            ap[0] = f2tf32(odd ? e1 : e0);   // P[gid][kk*8+tig]
            ap[1] = f2tf32(odd ? e3 : e2);   // P[gid+8][kk*8+tig]
            ap[2] = f2tf32(odd ? f1 : f0);   // P[gid][kk*8+tig+4]
            ap[3] = f2tf32(odd ? f3 : f2);   // P[gid+8][kk*8+tig+4]
            int vr = kk * 8 + tig;
            #pragma unroll
            for (int na = 0; na < 8; na++) {
                uint32_t bv[2] = { Vs[vr * VPAD + na * 8 + gid],
                                   Vs[(vr + 4) * VPAD + na * 8 + gid] };
                mma_tf32(oacc[na], ap, bv);
            }
        }
    }

    // ---- normalize + write out ----
    float inv0 = 1.0f / l0, inv1 = 1.0f / l1;
    float* Og = Ob + ((size_t)(b * SEQ + q0)) * D_MODEL + h * HEAD_DIM;
    int r = w * 16 + gid;
    #pragma unroll
    for (int na = 0; na < 8; na++) {
        int c = na * 8 + tig * 2;
        float2 v0 = make_float2(oacc[na][0] * inv0, oacc[na][1] * inv0);
        float2 v1 = make_float2(oacc[na][2] * inv1, oacc[na][3] * inv1);
        *(float2*)(Og + (size_t)r * D_MODEL + c) = v0;
        *(float2*)(Og + (size_t)(r + 8) * D_MODEL + c) = v1;
    }
}

// ---------------------------------------------------------------------------
// Launch
// ---------------------------------------------------------------------------
extern "C" void kernel_launch(void* const* d_in, const int* in_sizes, int n_in,
                              void* d_out, int out_size)
{
    const float* x  = (const float*)d_in[0];
    const float* Wq = (const float*)d_in[1];
    const float* bq = (const float*)d_in[2];
    const float* Wk = (const float*)d_in[3];
    const float* bk = (const float*)d_in[4];
    const float* Wv = (const float*)d_in[5];
    const float* bv = (const float*)d_in[6];
    const float* Wo = (const float*)d_in[7];
    const float* bo = (const float*)d_in[8];
    // d_in[9] = mask (causal; computed implicitly)
    float* out = (float*)d_out;

    float *Qp, *Kp, *Vp, *Op;
    cudaGetSymbolAddress((void**)&Qp, g_Q);
    cudaGetSymbolAddress((void**)&Kp, g_K);
    cudaGetSymbolAddress((void**)&Vp, g_V);
    cudaGetSymbolAddress((void**)&Op, g_O);

    // fused QKV projection (tf32 tensor cores)
    {
        dim3 g(12, BS / GBM);   // 8 Q col-blocks + 2 K + 2 V
        gemm_qkv_fused<<<g, 256>>>(x, Wq, bq, Qp, Wk, bk, Kp, Wv, bv, Vp);
    }

    // flash attention (tensor cores)
    {
        size_t smem = (size_t)(64 * FPAD + 64 * VPAD) * sizeof(uint32_t);
        cudaFuncSetAttribute(fa_mma_kernel, cudaFuncAttributeMaxDynamicSharedMemorySize,
                             (int)smem);
        dim3 g(BATCH * N_HEADS, SEQ / 64);
        fa_mma_kernel<<<g, 128, smem>>>(Qp, Kp, Vp, Op);
    }

    // output projection (tf32 tensor cores)
    {
        dim3 go(D_MODEL / GBN, BS / GBM);
        gemm_tf32_bias<<<go, 256>>>(Op, Wo, bo, out, BS, D_MODEL, D_MODEL);
    }
}

// round 8
// speedup vs baseline: 6.0795x; 1.0677x over previous
#include <cuda_runtime.h>
#include <cuda_bf16.h>
#include <math.h>
#include <stdint.h>

// Problem constants
#define D_MODEL 1024
#define N_HEADS 16
#define N_GROUPS 4
#define HEAD_DIM 64
#define KV_HEADS 4
#define D_KV 256
#define BATCH 2
#define SEQ 2048
#define BS (BATCH * SEQ)   // 4096

// Scratch buffers (device globals: no allocation allowed)
__device__ float g_Q[BS * D_MODEL];   // 16 MB
__device__ float g_K[BS * D_KV];      // 4 MB (tf32-rounded values)
__device__ float g_V[BS * D_KV];      // 4 MB (tf32-rounded values)
__device__ float g_O[BS * D_MODEL];   // 16 MB

// ---------------------------------------------------------------------------
// Common tf32 helpers
// ---------------------------------------------------------------------------
__device__ __forceinline__ uint32_t f2tf32(float f) {
    uint32_t u;
    asm("cvt.rna.tf32.f32 %0, %1;" : "=r"(u) : "f"(f));
    return u;
}

__device__ __forceinline__ void mma_tf32(float c[4], const uint32_t a[4], const uint32_t b[2]) {
    asm volatile(
        "mma.sync.aligned.m16n8k8.row.col.f32.tf32.tf32.f32 "
        "{%0,%1,%2,%3}, {%4,%5,%6,%7}, {%8,%9}, {%0,%1,%2,%3};"
        : "+f"(c[0]), "+f"(c[1]), "+f"(c[2]), "+f"(c[3])
        : "r"(a[0]), "r"(a[1]), "r"(a[2]), "r"(a[3]), "r"(b[0]), "r"(b[1]));
}

__device__ __forceinline__ void cp16(uint32_t dst_smem, const void* src) {
    asm volatile("cp.async.cg.shared.global [%0], [%1], 16;" :: "r"(dst_smem), "l"(src));
}
__device__ __forceinline__ void cp_commit() {
    asm volatile("cp.async.commit_group;");
}
__device__ __forceinline__ void cp_wait_all() {
    asm volatile("cp.async.wait_group 0;");
}

// ---------------------------------------------------------------------------
// TF32 tensor-core GEMM body: C[M,N] = A[M,K] @ B[K,N] + bias[N]
// BM=128, BN=128, BK=32. 256 threads = 8 warps (2x4). Warp tile 64x32.
// round_out: store tf32-rounded fp32 (for K/V consumed by cp.async in fa).
// ---------------------------------------------------------------------------
#define GBM 128
#define GBN 128
#define GBK 32
#define AST 36
#define BST 136

__device__ __forceinline__ void gemm_body(
    const float* __restrict__ A, const float* __restrict__ B,
    const float* __restrict__ bias, float* __restrict__ C,
    int N, int K, int row0, int col0, bool round_out,
    uint32_t (*As)[AST], uint32_t (*Bs)[BST])
{
    const int tid = threadIdx.x;
    const int lane = tid & 31;
    const int wid = tid >> 5;
    const int warp_m = wid & 1;
    const int warp_n = wid >> 1;

    const int a_r = tid >> 3;
    const int a_c = (tid & 7) * 4;
    const int b_r = tid >> 5;
    const int b_c = (tid & 31) * 4;

    const int gid = lane >> 2;
    const int tig = lane & 3;

    float acc[4][4][4];
    #pragma unroll
    for (int i = 0; i < 4; i++)
        #pragma unroll
        for (int j = 0; j < 4; j++)
            #pragma unroll
            for (int r = 0; r < 4; r++) acc[i][j][r] = 0.f;

    float4 av[4], bv[4];

    #pragma unroll
    for (int p = 0; p < 4; p++) {
        av[p] = *(const float4*)(A + (size_t)(row0 + a_r + p * 32) * K + a_c);
        bv[p] = *(const float4*)(B + (size_t)(b_r + p * 8) * N + col0 + b_c);
    }

    for (int k0 = 0; k0 < K; k0 += GBK) {
        #pragma unroll
        for (int p = 0; p < 4; p++) {
            uint32_t* as = &As[a_r + p * 32][a_c];
            as[0] = f2tf32(av[p].x); as[1] = f2tf32(av[p].y);
            as[2] = f2tf32(av[p].z); as[3] = f2tf32(av[p].w);
            uint32_t* bs = &Bs[b_r + p * 8][b_c];
            bs[0] = f2tf32(bv[p].x); bs[1] = f2tf32(bv[p].y);
            bs[2] = f2tf32(bv[p].z); bs[3] = f2tf32(bv[p].w);
        }
        __syncthreads();

        int kn = k0 + GBK;
        if (kn < K) {
            #pragma unroll
            for (int p = 0; p < 4; p++) {
                av[p] = *(const float4*)(A + (size_t)(row0 + a_r + p * 32) * K + kn + a_c);
                bv[p] = *(const float4*)(B + (size_t)(kn + b_r + p * 8) * N + col0 + b_c);
            }
        }

        #pragma unroll
        for (int kk = 0; kk < 4; kk++) {
            uint32_t afr[4][4], bfr[4][2];
            #pragma unroll
            for (int i = 0; i < 4; i++) {
                int mr = warp_m * 64 + i * 16 + gid;
                int kc = kk * 8 + tig;
                afr[i][0] = As[mr][kc];
                afr[i][1] = As[mr + 8][kc];
                afr[i][2] = As[mr][kc + 4];
                afr[i][3] = As[mr + 8][kc + 4];
            }
            #pragma unroll
            for (int j = 0; j < 4; j++) {
                int nc = warp_n * 32 + j * 8 + gid;
                int kr = kk * 8 + tig;
                bfr[j][0] = Bs[kr][nc];
                bfr[j][1] = Bs[kr + 4][nc];
            }
            #pragma unroll
            for (int i = 0; i < 4; i++)
                #pragma unroll
                for (int j = 0; j < 4; j++)
                    mma_tf32(acc[i][j], afr[i], bfr[j]);
        }
        __syncthreads();
    }

    #pragma unroll
    for (int i = 0; i < 4; i++) {
        int r = row0 + warp_m * 64 + i * 16 + gid;
        #pragma unroll
        for (int j = 0; j < 4; j++) {
            int c = col0 + warp_n * 32 + j * 8 + tig * 2;
            float b0 = bias[c], b1 = bias[c + 1];
            float o00 = acc[i][j][0] + b0, o01 = acc[i][j][1] + b1;
            float o10 = acc[i][j][2] + b0, o11 = acc[i][j][3] + b1;
            if (round_out) {
                o00 = __uint_as_float(f2tf32(o00));
                o01 = __uint_as_float(f2tf32(o01));
                o10 = __uint_as_float(f2tf32(o10));
                o11 = __uint_as_float(f2tf32(o11));
            }
            *(float2*)(C + (size_t)r * N + c) = make_float2(o00, o01);
            *(float2*)(C + (size_t)(r + 8) * N + c) = make_float2(o10, o11);
        }
    }
}

// Fused QKV projection: blockIdx.x 0..7 -> Q cols, 8..9 -> K, 10..11 -> V
// K and V outputs are stored tf32-rounded (fa loads them raw via cp.async).
__global__ __launch_bounds__(256) void gemm_qkv_fused(
    const float* __restrict__ x,
    const float* __restrict__ Wq, const float* __restrict__ bq, float* __restrict__ Qo,
    const float* __restrict__ Wk, const float* __restrict__ bk, float* __restrict__ Ko,
    const float* __restrict__ Wv, const float* __restrict__ bv, float* __restrict__ Vo)
{
    __shared__ uint32_t As[GBM][AST];
    __shared__ uint32_t Bs[GBK][BST];

    const int bx = blockIdx.x;
    const int row0 = blockIdx.y * GBM;

    const float* B; const float* bias; float* C; int N, col0; bool rnd;
    if (bx < 8)       { B = Wq; bias = bq; C = Qo; N = D_MODEL; col0 = bx * GBN;        rnd = false; }
    else if (bx < 10) { B = Wk; bias = bk; C = Ko; N = D_KV;    col0 = (bx - 8) * GBN;  rnd = true;  }
    else              { B = Wv; bias = bv; C = Vo; N = D_KV;    col0 = (bx - 10) * GBN; rnd = true;  }

    gemm_body(x, B, bias, C, N, D_MODEL, row0, col0, rnd, As, Bs);
}

// Plain GEMM (output projection)
__global__ __launch_bounds__(256) void gemm_tf32_bias(
    const float* __restrict__ A, const float* __restrict__ B,
    const float* __restrict__ bias, float* __restrict__ C,
    int M, int N, int K)
{
    __shared__ uint32_t As[GBM][AST];
    __shared__ uint32_t Bs[GBK][BST];
    gemm_body(A, B, bias, C, N, K, blockIdx.y * GBM, blockIdx.x * GBN, false, As, Bs);
}

// ---------------------------------------------------------------------------
// Flash attention with tensor cores (causal, GQA).
// One CTA = (b, h, 64-row q-tile). 128 threads = 4 warps.
//  - QK^T tf32x2 (Q hi/lo in regs, K single tf32), PV tf32
//  - K/V tiles arrive pre-tf32-rounded -> cp.async (no cvt, no LDG/STS)
//  - double-buffered smem, ONE __syncthreads per ktile, loads overlap compute
// ---------------------------------------------------------------------------
#define FPAD 68   // word pitch for K tile (row = 272 B, 16B-aligned)
#define VPAD 72   // word pitch for V tile (row = 288 B, 16B-aligned)
#define STAGE_WORDS (64 * FPAD + 64 * VPAD)   // 8960 words = 35840 B

__global__ __launch_bounds__(128, 3) void fa_mma_kernel(
    const float* __restrict__ Qb, const float* __restrict__ Kb,
    const float* __restrict__ Vb, float* __restrict__ Ob)
{
    extern __shared__ uint32_t smu[];   // [2][STAGE_WORDS]: Ks then Vs per stage

    const int bh = blockIdx.x;            // 0..31
    const int b  = bh >> 4;
    const int h  = bh & 15;
    const int kh = h >> 2;
    const int qt = blockIdx.y;
    const int q0 = qt * 64;
    const int tid = threadIdx.x;
    const int lane = tid & 31;
    const int w = tid >> 5;
    const int gid = lane >> 2;            // 0..7
    const int tig = lane & 3;             // 0..3

    const uint32_t smem_base = (uint32_t)__cvta_generic_to_shared(smu);

    const float* Kh = Kb + (size_t)b * SEQ * D_KV + kh * HEAD_DIM;
    const float* Vh = Vb + (size_t)b * SEQ * D_KV + kh * HEAD_DIM;

    // per-thread cp.async slice: fixed column chunk, 8 row-strided rows
    const int rr = tid >> 4;              // 0..7
    const int j4 = (tid & 15) * 4;        // 0..60

    // ---- issue K/V tile kt into stage st ----
    auto issue_tile = [&](int kt, int st) {
        const float* Kg = Kh + (size_t)(kt * 64) * D_KV;
        const float* Vg = Vh + (size_t)(kt * 64) * D_KV;
        uint32_t kbase = smem_base + (uint32_t)st * (STAGE_WORDS * 4);
        uint32_t vbase = kbase + 64 * FPAD * 4;
        #pragma unroll
        for (int p = 0; p < 8; p++) {
            int r = rr + p * 8;
            cp16(kbase + (uint32_t)(r * FPAD + j4) * 4, Kg + (size_t)r * D_KV + j4);
            cp16(vbase + (uint32_t)(r * VPAD + j4) * 4, Vg + (size_t)r * D_KV + j4);
        }
        cp_commit();
    };

    // ---- Q fragments in registers: scale by 1/8 (exact), hi/lo tf32 split ----
    issue_tile(0, 0);   // prefetch first K/V tile before Q fragment loads

    uint32_t qhi[8][4], qlo[8][4];
    {
        const float* Qg = Qb + ((size_t)(b * SEQ + q0 + w * 16)) * D_MODEL + h * HEAD_DIM;
        #pragma unroll
        for (int kk = 0; kk < 8; kk++) {
            int c0 = kk * 8 + tig;
            float v[4];
            v[0] = Qg[(size_t)gid * D_MODEL + c0] * 0.125f;
            v[1] = Qg[(size_t)(gid + 8) * D_MODEL + c0] * 0.125f;
            v[2] = Qg[(size_t)gid * D_MODEL + c0 + 4] * 0.125f;
            v[3] = Qg[(size_t)(gid + 8) * D_MODEL + c0 + 4] * 0.125f;
            #pragma unroll
            for (int e = 0; e < 4; e++) {
                uint32_t hi = f2tf32(v[e]);
                qhi[kk][e] = hi;
                qlo[kk][e] = f2tf32(v[e] - __uint_as_float(hi));
            }
        }
    }

    float m0 = -INFINITY, m1 = -INFINITY, l0 = 0.f, l1 = 0.f;
    float oacc[8][4];
    #pragma unroll
    for (int na = 0; na < 8; na++)
        #pragma unroll
        for (int c = 0; c < 4; c++) oacc[na][c] = 0.f;

    const int src1 = gid * 4 + (tig >> 1);
    const int src2 = src1 + 2;
    const bool odd = tig & 1;

    for (int kt = 0; kt <= qt; kt++) {
        // current stage's copies complete, then barrier (also fences prev compute)
        cp_wait_all();
        __syncthreads();

        // prefetch next tile into the other stage (overlaps compute below);
        // safe: after the barrier, everyone finished reading that stage (iter kt-1)
        if (kt < qt) issue_tile(kt + 1, (kt + 1) & 1);

        const uint32_t* Ks = smu + (size_t)(kt & 1) * STAGE_WORDS;
        const uint32_t* Vs = Ks + 64 * FPAD;

        // ---- S = Q K^T (tf32x2: exact Q, single-rounded K) ----
        float sacc[8][4];
        #pragma unroll
        for (int na = 0; na < 8; na++)
            #pragma unroll
            for (int c = 0; c < 4; c++) sacc[na][c] = 0.f;

        #pragma unroll
        for (int kk = 0; kk < 8; kk++) {
            int kc = kk * 8 + tig;
            #pragma unroll
            for (int na = 0; na < 8; na++) {
                int kr = na * 8 + gid;
                uint32_t bf[2] = { Ks[kr * FPAD + kc], Ks[kr * FPAD + kc + 4] };
                mma_tf32(sacc[na], qhi[kk], bf);
                mma_tf32(sacc[na], qlo[kk], bf);
            }
        }

        // ---- causal mask on the diagonal tile ----
        if (kt == qt) {
            int rbase = w * 16 + gid;
            #pragma unroll
            for (int na = 0; na < 8; na++) {
                int cbase = na * 8 + tig * 2;
                if (cbase     > rbase)     sacc[na][0] = -INFINITY;
                if (cbase + 1 > rbase)     sacc[na][1] = -INFINITY;
                if (cbase     > rbase + 8) sacc[na][2] = -INFINITY;
                if (cbase + 1 > rbase + 8) sacc[na][3] = -INFINITY;
            }
        }

        // ---- online softmax (registers + 4-lane shfl reductions) ----
        float tm0 = -INFINITY, tm1 = -INFINITY;
        #pragma unroll
        for (int na = 0; na < 8; na++) {
            tm0 = fmaxf(tm0, fmaxf(sacc[na][0], sacc[na][1]));
            tm1 = fmaxf(tm1, fmaxf(sacc[na][2], sacc[na][3]));
        }
        tm0 = fmaxf(tm0, __shfl_xor_sync(0xffffffffu, tm0, 1));
        tm0 = fmaxf(tm0, __shfl_xor_sync(0xffffffffu, tm0, 2));
        tm1 = fmaxf(tm1, __shfl_xor_sync(0xffffffffu, tm1, 1));
        tm1 = fmaxf(tm1, __shfl_xor_sync(0xffffffffu, tm1, 2));

        float mn0 = fmaxf(m0, tm0), mn1 = fmaxf(m1, tm1);
        float ts0 = 0.f, ts1 = 0.f;
        #pragma unroll
        for (int na = 0; na < 8; na++) {
            sacc[na][0] = __expf(sacc[na][0] - mn0); ts0 += sacc[na][0];
            sacc[na][1] = __expf(sacc[na][1] - mn0); ts0 += sacc[na][1];
            sacc[na][2] = __expf(sacc[na][2] - mn1); ts1 += sacc[na][2];
            sacc[na][3] = __expf(sacc[na][3] - mn1); ts1 += sacc[na][3];
        }
        ts0 += __shfl_xor_sync(0xffffffffu, ts0, 1);
        ts0 += __shfl_xor_sync(0xffffffffu, ts0, 2);
        ts1 += __shfl_xor_sync(0xffffffffu, ts1, 1);
        ts1 += __shfl_xor_sync(0xffffffffu, ts1, 2);

        float a0 = __expf(m0 - mn0), a1 = __expf(m1 - mn1);
        l0 = l0 * a0 + ts0;
        l1 = l1 * a1 + ts1;
        m0 = mn0; m1 = mn1;

        #pragma unroll
        for (int na = 0; na < 8; na++) {
            oacc[na][0] *= a0; oacc[na][1] *= a0;
            oacc[na][2] *= a1; oacc[na][3] *= a1;
        }

        // ---- O += P V : P relayout C-frag -> A-frag via shuffles ----
        #pragma unroll
        for (int kk = 0; kk < 8; kk++) {
            float e0 = __shfl_sync(0xffffffffu, sacc[kk][0], src1);
            float e1 = __shfl_sync(0xffffffffu, sacc[kk][1], src1);
            float e2 = __shfl_sync(0xffffffffu, sacc[kk][2], src1);
            float e3 = __shfl_sync(0xffffffffu, sacc[kk][3], src1);
            float f0 = __shfl_sync(0xffffffffu, sacc[kk][0], src2);
            float f1 = __shfl_sync(0xffffffffu, sacc[kk][1], src2);
            float f2 = __shfl_sync(0xffffffffu, sacc[kk][2], src2);
            float f3 = __shfl_sync(0xffffffffu, sacc[kk][3], src2);
            uint32_t ap[4];
            ap[0] = f2tf32(odd ? e1 : e0);   // P[gid][kk*8+tig]
            ap[1] = f2tf32(odd ? e3 : e2);   // P[gid+8][kk*8+tig]
            ap[2] = f2tf32(odd ? f1 : f0);   // P[gid][kk*8+tig+4]
            ap[3] = f2tf32(odd ? f3 : f2);   // P[gid+8][kk*8+tig+4]
            int vr = kk * 8 + tig;
            #pragma unroll
            for (int na = 0; na < 8; na++) {
                uint32_t bv[2] = { Vs[vr * VPAD + na * 8 + gid],
                                   Vs[(vr + 4) * VPAD + na * 8 + gid] };
                mma_tf32(oacc[na], ap, bv);
            }
        }
    }

    // ---- normalize + write out ----
    float inv0 = 1.0f / l0, inv1 = 1.0f / l1;
    float* Og = Ob + ((size_t)(b * SEQ + q0)) * D_MODEL + h * HEAD_DIM;
    int r = w * 16 + gid;
    #pragma unroll
    for (int na = 0; na < 8; na++) {
        int c = na * 8 + tig * 2;
        float2 v0 = make_float2(oacc[na][0] * inv0, oacc[na][1] * inv0);
        float2 v1 = make_float2(oacc[na][2] * inv1, oacc[na][3] * inv1);
        *(float2*)(Og + (size_t)r * D_MODEL + c) = v0;
        *(float2*)(Og + (size_t)(r + 8) * D_MODEL + c) = v1;
    }
}

// ---------------------------------------------------------------------------
// Launch
// ---------------------------------------------------------------------------
extern "C" void kernel_launch(void* const* d_in, const int* in_sizes, int n_in,
                              void* d_out, int out_size)
{
    const float* x  = (const float*)d_in[0];
    const float* Wq = (const float*)d_in[1];
    const float* bq = (const float*)d_in[2];
    const float* Wk = (const float*)d_in[3];
    const float* bk = (const float*)d_in[4];
    const float* Wv = (const float*)d_in[5];
    const float* bv = (const float*)d_in[6];
    const float* Wo = (const float*)d_in[7];
    const float* bo = (const float*)d_in[8];
    // d_in[9] = mask (causal; computed implicitly)
    float* out = (float*)d_out;

    float *Qp, *Kp, *Vp, *Op;
    cudaGetSymbolAddress((void**)&Qp, g_Q);
    cudaGetSymbolAddress((void**)&Kp, g_K);
    cudaGetSymbolAddress((void**)&Vp, g_V);
    cudaGetSymbolAddress((void**)&Op, g_O);

    // fused QKV projection (tf32 tensor cores; K/V stored tf32-rounded)
    {
        dim3 g(12, BS / GBM);   // 8 Q col-blocks + 2 K + 2 V
        gemm_qkv_fused<<<g, 256>>>(x, Wq, bq, Qp, Wk, bk, Kp, Wv, bv, Vp);
    }

    // flash attention (tensor cores, cp.async double-buffered K/V)
    {
        size_t smem = (size_t)(2 * STAGE_WORDS) * sizeof(uint32_t);   // 71680 B
        cudaFuncSetAttribute(fa_mma_kernel, cudaFuncAttributeMaxDynamicSharedMemorySize,
                             (int)smem);
        dim3 g(BATCH * N_HEADS, SEQ / 64);
        fa_mma_kernel<<<g, 128, smem>>>(Qp, Kp, Vp, Op);
    }

    // output projection (tf32 tensor cores)
    {
        dim3 go(D_MODEL / GBN, BS / GBM);
        gemm_tf32_bias<<<go, 256>>>(Op, Wo, bo, out, BS, D_MODEL, D_MODEL);
    }
}

// round 9
// speedup vs baseline: 6.0862x; 1.0011x over previous
#include <cuda_runtime.h>
#include <cuda_bf16.h>
#include <math.h>
#include <stdint.h>

// Problem constants
#define D_MODEL 1024
#define N_HEADS 16
#define N_GROUPS 4
#define HEAD_DIM 64
#define KV_HEADS 4
#define D_KV 256
#define BATCH 2
#define SEQ 2048
#define BS (BATCH * SEQ)   // 4096

// Scratch buffers (device globals: no allocation allowed)
__device__ float g_Q[BS * D_MODEL];        // 16 MB
__device__ float g_K[BS * D_KV];           // 4 MB (tf32-rounded)
__device__ float g_V[BS * D_KV];           // 4 MB (tf32-rounded)
__device__ float g_O[BS * D_MODEL];        // 16 MB (tf32-rounded)
__device__ float g_X[BS * D_MODEL];        // 16 MB (tf32-rounded x)
__device__ float g_Wq[D_MODEL * D_MODEL];  // 4 MB (tf32-rounded)
__device__ float g_Wk[D_MODEL * D_KV];     // 1 MB
__device__ float g_Wv[D_MODEL * D_KV];     // 1 MB
__device__ float g_Wo[D_MODEL * D_MODEL];  // 4 MB

// ---------------------------------------------------------------------------
// tf32 helpers
// ---------------------------------------------------------------------------
__device__ __forceinline__ uint32_t f2tf32(float f) {
    uint32_t u;
    asm("cvt.rna.tf32.f32 %0, %1;" : "=r"(u) : "f"(f));
    return u;
}

__device__ __forceinline__ void mma_tf32(float c[4], const uint32_t a[4], const uint32_t b[2]) {
    asm volatile(
        "mma.sync.aligned.m16n8k8.row.col.f32.tf32.tf32.f32 "
        "{%0,%1,%2,%3}, {%4,%5,%6,%7}, {%8,%9}, {%0,%1,%2,%3};"
        : "+f"(c[0]), "+f"(c[1]), "+f"(c[2]), "+f"(c[3])
        : "r"(a[0]), "r"(a[1]), "r"(a[2]), "r"(a[3]), "r"(b[0]), "r"(b[1]));
}

__device__ __forceinline__ void cp16(uint32_t dst_smem, const void* src) {
    asm volatile("cp.async.cg.shared.global [%0], [%1], 16;" :: "r"(dst_smem), "l"(src));
}
__device__ __forceinline__ void cp_commit() {
    asm volatile("cp.async.commit_group;");
}
__device__ __forceinline__ void cp_wait_all() {
    asm volatile("cp.async.wait_group 0;");
}
__device__ __forceinline__ void cp_wait_1() {
    asm volatile("cp.async.wait_group 1;");
}

// ---------------------------------------------------------------------------
// Pre-round: y = tf32_rna(x), float4 vectorized
// ---------------------------------------------------------------------------
__global__ __launch_bounds__(256) void round_tf32_kernel(
    const float4* __restrict__ in, float4* __restrict__ out, int n4)
{
    int i = blockIdx.x * blockDim.x + threadIdx.x;
    if (i < n4) {
        float4 v = in[i];
        float4 r;
        r.x = __uint_as_float(f2tf32(v.x));
        r.y = __uint_as_float(f2tf32(v.y));
        r.z = __uint_as_float(f2tf32(v.z));
        r.w = __uint_as_float(f2tf32(v.w));
        out[i] = r;
    }
}

// ---------------------------------------------------------------------------
// TF32 tensor-core GEMM, cp.async 3-stage pipeline.
// Inputs MUST be pre-tf32-rounded fp32 (low 13 mantissa bits zero).
// C[M,N] = A[M,K] @ B[K,N] + bias[N].
// BM=128, BN=128, BK=32. 256 threads = 8 warps (2x4). Warp tile 64x32.
// ---------------------------------------------------------------------------
#define GBM 128
#define GBN 128
#define GBK 32
#define AST 36     // A row pitch (words); 144 B, 16B-multiple, conflict-free frags
#define BST 136    // B row pitch (words); 544 B, 16B-multiple, conflict-free frags
#define A_WORDS (GBM * AST)          // 4608
#define GSTG (A_WORDS + GBK * BST)   // 8960 words = 35840 B per stage
#define GSTAGES 3

__device__ __forceinline__ void gemm_issue_tile(
    const float* __restrict__ A, const float* __restrict__ B,
    int K, int N, int row0, int col0, int kt, int st,
    uint32_t smem_base, int tid)
{
    const int k0 = kt * GBK;
    uint32_t abase = smem_base + (uint32_t)st * (GSTG * 4);
    uint32_t bbase = abase + A_WORDS * 4;
    #pragma unroll
    for (int p = 0; p < 4; p++) {
        int ch = tid + p * 256;            // 0..1023
        int ar = ch >> 3, ac = (ch & 7) * 4;
        cp16(abase + (uint32_t)(ar * AST + ac) * 4,
             A + (size_t)(row0 + ar) * K + k0 + ac);
    }
    #pragma unroll
    for (int p = 0; p < 4; p++) {
        int ch = tid + p * 256;
        int br = ch >> 5, bc = (ch & 31) * 4;
        cp16(bbase + (uint32_t)(br * BST + bc) * 4,
             B + (size_t)(k0 + br) * N + col0 + bc);
    }
    cp_commit();
}

__device__ __forceinline__ void gemm_body_async(
    const float* __restrict__ A, const float* __restrict__ B,
    const float* __restrict__ bias, float* __restrict__ C,
    int N, int K, int row0, int col0, bool round_out, uint32_t* sm)
{
    const int tid = threadIdx.x;
    const int lane = tid & 31;
    const int wid = tid >> 5;
    const int warp_m = wid & 1;
    const int warp_n = wid >> 1;
    const int gid = lane >> 2;
    const int tig = lane & 3;

    const uint32_t smem_base = (uint32_t)__cvta_generic_to_shared(sm);

    float acc[4][4][4];
    #pragma unroll
    for (int i = 0; i < 4; i++)
        #pragma unroll
        for (int j = 0; j < 4; j++)
            #pragma unroll
            for (int r = 0; r < 4; r++) acc[i][j][r] = 0.f;

    const int nk = K / GBK;
    gemm_issue_tile(A, B, K, N, row0, col0, 0, 0, smem_base, tid);
    gemm_issue_tile(A, B, K, N, row0, col0, 1, 1, smem_base, tid);

    for (int kt = 0; kt < nk; kt++) {
        cp_wait_1();        // tile kt resident
        __syncthreads();    // + everyone done reading stage (kt+2)%3 (iter kt-1)

        if (kt + 2 < nk)
            gemm_issue_tile(A, B, K, N, row0, col0, kt + 2, (kt + 2) % GSTAGES,
                            smem_base, tid);

        const uint32_t* As = sm + (kt % GSTAGES) * GSTG;
        const uint32_t* Bs = As + A_WORDS;

        #pragma unroll
        for (int kk = 0; kk < 4; kk++) {
            uint32_t afr[4][4], bfr[4][2];
            #pragma unroll
            for (int i = 0; i < 4; i++) {
                int mr = warp_m * 64 + i * 16 + gid;
                int kc = kk * 8 + tig;
                afr[i][0] = As[mr * AST + kc];
                afr[i][1] = As[(mr + 8) * AST + kc];
                afr[i][2] = As[mr * AST + kc + 4];
                afr[i][3] = As[(mr + 8) * AST + kc + 4];
            }
            #pragma unroll
            for (int j = 0; j < 4; j++) {
                int nc = warp_n * 32 + j * 8 + gid;
                int kr = kk * 8 + tig;
                bfr[j][0] = Bs[kr * BST + nc];
                bfr[j][1] = Bs[(kr + 4) * BST + nc];
            }
            #pragma unroll
            for (int i = 0; i < 4; i++)
                #pragma unroll
                for (int j = 0; j < 4; j++)
                    mma_tf32(acc[i][j], afr[i], bfr[j]);
        }
    }

    #pragma unroll
    for (int i = 0; i < 4; i++) {
        int r = row0 + warp_m * 64 + i * 16 + gid;
        #pragma unroll
        for (int j = 0; j < 4; j++) {
            int c = col0 + warp_n * 32 + j * 8 + tig * 2;
            float b0 = bias[c], b1 = bias[c + 1];
            float o00 = acc[i][j][0] + b0, o01 = acc[i][j][1] + b1;
            float o10 = acc[i][j][2] + b0, o11 = acc[i][j][3] + b1;
            if (round_out) {
                o00 = __uint_as_float(f2tf32(o00));
                o01 = __uint_as_float(f2tf32(o01));
                o10 = __uint_as_float(f2tf32(o10));
                o11 = __uint_as_float(f2tf32(o11));
            }
            *(float2*)(C + (size_t)r * N + c) = make_float2(o00, o01);
            *(float2*)(C + (size_t)(r + 8) * N + c) = make_float2(o10, o11);
        }
    }
}

// Fused QKV projection: blockIdx.x 0..7 -> Q cols, 8..9 -> K, 10..11 -> V
__global__ __launch_bounds__(256) void gemm_qkv_fused(
    const float* __restrict__ x,
    const float* __restrict__ Wq, const float* __restrict__ bq, float* __restrict__ Qo,
    const float* __restrict__ Wk, const float* __restrict__ bk, float* __restrict__ Ko,
    const float* __restrict__ Wv, const float* __restrict__ bv, float* __restrict__ Vo)
{
    extern __shared__ uint32_t sm[];
    const int bx = blockIdx.x;
    const int row0 = blockIdx.y * GBM;

    const float* B; const float* bias; float* C; int N, col0; bool rnd;
    if (bx < 8)       { B = Wq; bias = bq; C = Qo; N = D_MODEL; col0 = bx * GBN;        rnd = false; }
    else if (bx < 10) { B = Wk; bias = bk; C = Ko; N = D_KV;    col0 = (bx - 8) * GBN;  rnd = true;  }
    else              { B = Wv; bias = bv; C = Vo; N = D_KV;    col0 = (bx - 10) * GBN; rnd = true;  }

    gemm_body_async(x, B, bias, C, N, D_MODEL, row0, col0, rnd, sm);
}

// Plain GEMM (output projection)
__global__ __launch_bounds__(256) void gemm_tf32_bias(
    const float* __restrict__ A, const float* __restrict__ B,
    const float* __restrict__ bias, float* __restrict__ C,
    int M, int N, int K)
{
    extern __shared__ uint32_t sm[];
    gemm_body_async(A, B, bias, C, N, K, blockIdx.y * GBM, blockIdx.x * GBN, false, sm);
}

// ---------------------------------------------------------------------------
// Flash attention with tensor cores (causal, GQA).
// One CTA = (b, h, 64-row q-tile). 128 threads = 4 warps.
//  - QK^T tf32x2 (Q hi/lo in regs, K single tf32), PV tf32
//  - K/V pre-tf32-rounded -> cp.async double-buffered, one barrier per ktile
//  - O written tf32-rounded (feeds out-proj's cp.async path)
// ---------------------------------------------------------------------------
#define FPAD 68
#define VPAD 72
#define STAGE_WORDS (64 * FPAD + 64 * VPAD)   // 8960 words

__global__ __launch_bounds__(128, 3) void fa_mma_kernel(
    const float* __restrict__ Qb, const float* __restrict__ Kb,
    const float* __restrict__ Vb, float* __restrict__ Ob)
{
    extern __shared__ uint32_t smu[];   // [2][STAGE_WORDS]

    const int bh = blockIdx.x;
    const int b  = bh >> 4;
    const int h  = bh & 15;
    const int kh = h >> 2;
    const int qt = blockIdx.y;
    const int q0 = qt * 64;
    const int tid = threadIdx.x;
    const int lane = tid & 31;
    const int w = tid >> 5;
    const int gid = lane >> 2;
    const int tig = lane & 3;

    const uint32_t smem_base = (uint32_t)__cvta_generic_to_shared(smu);

    const float* Kh = Kb + (size_t)b * SEQ * D_KV + kh * HEAD_DIM;
    const float* Vh = Vb + (size_t)b * SEQ * D_KV + kh * HEAD_DIM;

    const int rr = tid >> 4;
    const int j4 = (tid & 15) * 4;

    auto issue_tile = [&](int kt, int st) {
        const float* Kg = Kh + (size_t)(kt * 64) * D_KV;
        const float* Vg = Vh + (size_t)(kt * 64) * D_KV;
        uint32_t kbase = smem_base + (uint32_t)st * (STAGE_WORDS * 4);
        uint32_t vbase = kbase + 64 * FPAD * 4;
        #pragma unroll
        for (int p = 0; p < 8; p++) {
            int r = rr + p * 8;
            cp16(kbase + (uint32_t)(r * FPAD + j4) * 4, Kg + (size_t)r * D_KV + j4);
            cp16(vbase + (uint32_t)(r * VPAD + j4) * 4, Vg + (size_t)r * D_KV + j4);
        }
        cp_commit();
    };

    issue_tile(0, 0);

    uint32_t qhi[8][4], qlo[8][4];
    {
        const float* Qg = Qb + ((size_t)(b * SEQ + q0 + w * 16)) * D_MODEL + h * HEAD_DIM;
        #pragma unroll
        for (int kk = 0; kk < 8; kk++) {
            int c0 = kk * 8 + tig;
            float v[4];
            v[0] = Qg[(size_t)gid * D_MODEL + c0] * 0.125f;
            v[1] = Qg[(size_t)(gid + 8) * D_MODEL + c0] * 0.125f;
            v[2] = Qg[(size_t)gid * D_MODEL + c0 + 4] * 0.125f;
            v[3] = Qg[(size_t)(gid + 8) * D_MODEL + c0 + 4] * 0.125f;
            #pragma unroll
            for (int e = 0; e < 4; e++) {
                uint32_t hi = f2tf32(v[e]);
                qhi[kk][e] = hi;
                qlo[kk][e] = f2tf32(v[e] - __uint_as_float(hi));
            }
        }
    }

    float m0 = -INFINITY, m1 = -INFINITY, l0 = 0.f, l1 = 0.f;
    float oacc[8][4];
    #pragma unroll
    for (int na = 0; na < 8; na++)
        #pragma unroll
        for (int c = 0; c < 4; c++) oacc[na][c] = 0.f;

    const int src1 = gid * 4 + (tig >> 1);
    const int src2 = src1 + 2;
    const bool odd = tig & 1;

    for (int kt = 0; kt <= qt; kt++) {
        cp_wait_all();
        __syncthreads();

        if (kt < qt) issue_tile(kt + 1, (kt + 1) & 1);

        const uint32_t* Ks = smu + (size_t)(kt & 1) * STAGE_WORDS;
        const uint32_t* Vs = Ks + 64 * FPAD;

        float sacc[8][4];
        #pragma unroll
        for (int na = 0; na < 8; na++)
            #pragma unroll
            for (int c = 0; c < 4; c++) sacc[na][c] = 0.f;

        #pragma unroll
        for (int kk = 0; kk < 8; kk++) {
            int kc = kk * 8 + tig;
            #pragma unroll
            for (int na = 0; na < 8; na++) {
                int kr = na * 8 + gid;
                uint32_t bf[2] = { Ks[kr * FPAD + kc], Ks[kr * FPAD + kc + 4] };
                mma_tf32(sacc[na], qhi[kk], bf);
                mma_tf32(sacc[na], qlo[kk], bf);
            }
        }

        if (kt == qt) {
            int rbase = w * 16 + gid;
            #pragma unroll
            for (int na = 0; na < 8; na++) {
                int cbase = na * 8 + tig * 2;
                if (cbase     > rbase)     sacc[na][0] = -INFINITY;
                if (cbase + 1 > rbase)     sacc[na][1] = -INFINITY;
                if (cbase     > rbase + 8) sacc[na][2] = -INFINITY;
                if (cbase + 1 > rbase + 8) sacc[na][3] = -INFINITY;
            }
        }

        float tm0 = -INFINITY, tm1 = -INFINITY;
        #pragma unroll
        for (int na = 0; na < 8; na++) {
            tm0 = fmaxf(tm0, fmaxf(sacc[na][0], sacc[na][1]));
            tm1 = fmaxf(tm1, fmaxf(sacc[na][2], sacc[na][3]));
        }
        tm0 = fmaxf(tm0, __shfl_xor_sync(0xffffffffu, tm0, 1));
        tm0 = fmaxf(tm0, __shfl_xor_sync(0xffffffffu, tm0, 2));
        tm1 = fmaxf(tm1, __shfl_xor_sync(0xffffffffu, tm1, 1));
        tm1 = fmaxf(tm1, __shfl_xor_sync(0xffffffffu, tm1, 2));

        float mn0 = fmaxf(m0, tm0), mn1 = fmaxf(m1, tm1);
        float ts0 = 0.f, ts1 = 0.f;
        #pragma unroll
        for (int na = 0; na < 8; na++) {
            sacc[na][0] = __expf(sacc[na][0] - mn0); ts0 += sacc[na][0];
            sacc[na][1] = __expf(sacc[na][1] - mn0); ts0 += sacc[na][1];
            sacc[na][2] = __expf(sacc[na][2] - mn1); ts1 += sacc[na][2];
            sacc[na][3] = __expf(sacc[na][3] - mn1); ts1 += sacc[na][3];
        }
        ts0 += __shfl_xor_sync(0xffffffffu, ts0, 1);
        ts0 += __shfl_xor_sync(0xffffffffu, ts0, 2);
        ts1 += __shfl_xor_sync(0xffffffffu, ts1, 1);
        ts1 += __shfl_xor_sync(0xffffffffu, ts1, 2);

        float a0 = __expf(m0 - mn0), a1 = __expf(m1 - mn1);
        l0 = l0 * a0 + ts0;
        l1 = l1 * a1 + ts1;
        m0 = mn0; m1 = mn1;

        #pragma unroll
        for (int na = 0; na < 8; na++) {
            oacc[na][0] *= a0; oacc[na][1] *= a0;
            oacc[na][2] *= a1; oacc[na][3] *= a1;
        }

        #pragma unroll
        for (int kk = 0; kk < 8; kk++) {
            float e0 = __shfl_sync(0xffffffffu, sacc[kk][0], src1);
            float e1 = __shfl_sync(0xffffffffu, sacc[kk][1], src1);
            float e2 = __shfl_sync(0xffffffffu, sacc[kk][2], src1);
            float e3 = __shfl_sync(0xffffffffu, sacc[kk][3], src1);
            float f0 = __shfl_sync(0xffffffffu, sacc[kk][0], src2);
            float f1 = __shfl_sync(0xffffffffu, sacc[kk][1], src2);
            float f2 = __shfl_sync(0xffffffffu, sacc[kk][2], src2);
            float f3 = __shfl_sync(0xffffffffu, sacc[kk][3], src2);
            uint32_t ap[4];
            ap[0] = f2tf32(odd ? e1 : e0);
            ap[1] = f2tf32(odd ? e3 : e2);
            ap[2] = f2tf32(odd ? f1 : f0);
            ap[3] = f2tf32(odd ? f3 : f2);
            int vr = kk * 8 + tig;
            #pragma unroll
            for (int na = 0; na < 8; na++) {
                uint32_t bv[2] = { Vs[vr * VPAD + na * 8 + gid],
                                   Vs[(vr + 4) * VPAD + na * 8 + gid] };
                mma_tf32(oacc[na], ap, bv);
            }
        }
    }

    // normalize + write out (tf32-rounded: out-proj consumes via cp.async)
    float inv0 = 1.0f / l0, inv1 = 1.0f / l1;
    float* Og = Ob + ((size_t)(b * SEQ + q0)) * D_MODEL + h * HEAD_DIM;
    int r = w * 16 + gid;
    #pragma unroll
    for (int na = 0; na < 8; na++) {
        int c = na * 8 + tig * 2;
        float2 v0, v1;
        v0.x = __uint_as_float(f2tf32(oacc[na][0] * inv0));
        v0.y = __uint_as_float(f2tf32(oacc[na][1] * inv0));
        v1.x = __uint_as_float(f2tf32(oacc[na][2] * inv1));
        v1.y = __uint_as_float(f2tf32(oacc[na][3] * inv1));
        *(float2*)(Og + (size_t)r * D_MODEL + c) = v0;
        *(float2*)(Og + (size_t)(r + 8) * D_MODEL + c) = v1;
    }
}

// ---------------------------------------------------------------------------
// Launch
// ---------------------------------------------------------------------------
extern "C" void kernel_launch(void* const* d_in, const int* in_sizes, int n_in,
                              void* d_out, int out_size)
{
    const float* x  = (const float*)d_in[0];
    const float* Wq = (const float*)d_in[1];
    const float* bq = (const float*)d_in[2];
    const float* Wk = (const float*)d_in[3];
    const float* bk = (const float*)d_in[4];
    const float* Wv = (const float*)d_in[5];
    const float* bv = (const float*)d_in[6];
    const float* Wo = (const float*)d_in[7];
    const float* bo = (const float*)d_in[8];
    // d_in[9] = mask (causal; computed implicitly)
    float* out = (float*)d_out;

    float *Qp, *Kp, *Vp, *Op, *Xp, *Wqp, *Wkp, *Wvp, *Wop;
    cudaGetSymbolAddress((void**)&Qp, g_Q);
    cudaGetSymbolAddress((void**)&Kp, g_K);
    cudaGetSymbolAddress((void**)&Vp, g_V);
    cudaGetSymbolAddress((void**)&Op, g_O);
    cudaGetSymbolAddress((void**)&Xp, g_X);
    cudaGetSymbolAddress((void**)&Wqp, g_Wq);
    cudaGetSymbolAddress((void**)&Wkp, g_Wk);
    cudaGetSymbolAddress((void**)&Wvp, g_Wv);
    cudaGetSymbolAddress((void**)&Wop, g_Wo);

    // pre-round inputs to tf32 (hoisted RNA rounding; bit-identical to R7)
    {
        int n4x = BS * D_MODEL / 4;
        round_tf32_kernel<<<(n4x + 255) / 256, 256>>>((const float4*)x, (float4*)Xp, n4x);
        int n4q = D_MODEL * D_MODEL / 4;
        round_tf32_kernel<<<(n4q + 255) / 256, 256>>>((const float4*)Wq, (float4*)Wqp, n4q);
        int n4k = D_MODEL * D_KV / 4;
        round_tf32_kernel<<<(n4k + 255) / 256, 256>>>((const float4*)Wk, (float4*)Wkp, n4k);
        round_tf32_kernel<<<(n4k + 255) / 256, 256>>>((const float4*)Wv, (float4*)Wvp, n4k);
        round_tf32_kernel<<<(n4q + 255) / 256, 256>>>((const float4*)Wo, (float4*)Wop, n4q);
    }

    size_t gemm_smem = (size_t)GSTAGES * GSTG * sizeof(uint32_t);   // 107520 B

    // fused QKV projection
    {
        cudaFuncSetAttribute(gemm_qkv_fused, cudaFuncAttributeMaxDynamicSharedMemorySize,
                             (int)gemm_smem);
        dim3 g(12, BS / GBM);
        gemm_qkv_fused<<<g, 256, gemm_smem>>>(Xp, Wqp, bq, Qp, Wkp, bk, Kp, Wvp, bv, Vp);
    }

    // flash attention
    {
        size_t smem = (size_t)(2 * STAGE_WORDS) * sizeof(uint32_t);   // 71680 B
        cudaFuncSetAttribute(fa_mma_kernel, cudaFuncAttributeMaxDynamicSharedMemorySize,
                             (int)smem);
        dim3 g(BATCH * N_HEADS, SEQ / 64);
        fa_mma_kernel<<<g, 128, smem>>>(Qp, Kp, Vp, Op);
    }

    // output projection
    {
        cudaFuncSetAttribute(gemm_tf32_bias, cudaFuncAttributeMaxDynamicSharedMemorySize,
                             (int)gemm_smem);
        dim3 go(D_MODEL / GBN, BS / GBM);
        gemm_tf32_bias<<<go, 256, gemm_smem>>>(Op, Wop, bo, out, BS, D_MODEL, D_MODEL);
    }
}

// round 10
// speedup vs baseline: 6.3517x; 1.0436x over previous
#include <cuda_runtime.h>
#include <cuda_bf16.h>
#include <math.h>
#include <stdint.h>

// Problem constants
#define D_MODEL 1024
#define N_HEADS 16
#define N_GROUPS 4
#define HEAD_DIM 64
#define KV_HEADS 4
#define D_KV 256
#define BATCH 2
#define SEQ 2048
#define BS (BATCH * SEQ)   // 4096

// Scratch buffers (device globals: no allocation allowed)
__device__ float g_Q[BS * D_MODEL];        // 16 MB
__device__ float g_K[BS * D_KV];           // 4 MB (tf32-rounded)
__device__ float g_V[BS * D_KV];           // 4 MB (tf32-rounded)
__device__ float g_O[BS * D_MODEL];        // 16 MB (tf32-rounded)
__device__ float g_X[BS * D_MODEL];        // 16 MB (tf32-rounded x)
__device__ float g_Wq[D_MODEL * D_MODEL];  // 4 MB (tf32-rounded)
__device__ float g_Wk[D_MODEL * D_KV];     // 1 MB
__device__ float g_Wv[D_MODEL * D_KV];     // 1 MB
__device__ float g_Wo[D_MODEL * D_MODEL];  // 4 MB

// ---------------------------------------------------------------------------
// tf32 helpers
// ---------------------------------------------------------------------------
__device__ __forceinline__ uint32_t f2tf32(float f) {
    uint32_t u;
    asm("cvt.rna.tf32.f32 %0, %1;" : "=r"(u) : "f"(f));
    return u;
}

__device__ __forceinline__ void mma_tf32(float c[4], const uint32_t a[4], const uint32_t b[2]) {
    asm volatile(
        "mma.sync.aligned.m16n8k8.row.col.f32.tf32.tf32.f32 "
        "{%0,%1,%2,%3}, {%4,%5,%6,%7}, {%8,%9}, {%0,%1,%2,%3};"
        : "+f"(c[0]), "+f"(c[1]), "+f"(c[2]), "+f"(c[3])
        : "r"(a[0]), "r"(a[1]), "r"(a[2]), "r"(a[3]), "r"(b[0]), "r"(b[1]));
}

__device__ __forceinline__ void cp16(uint32_t dst_smem, const void* src) {
    asm volatile("cp.async.cg.shared.global [%0], [%1], 16;" :: "r"(dst_smem), "l"(src));
}
__device__ __forceinline__ void cp_commit() {
    asm volatile("cp.async.commit_group;");
}
__device__ __forceinline__ void cp_wait_all() {
    asm volatile("cp.async.wait_group 0;");
}
__device__ __forceinline__ void cp_wait_1() {
    asm volatile("cp.async.wait_group 1;");
}

// ---------------------------------------------------------------------------
// Pre-round: y = tf32_rna(x), float4 vectorized
// ---------------------------------------------------------------------------
__global__ __launch_bounds__(256) void round_tf32_kernel(
    const float4* __restrict__ in, float4* __restrict__ out, int n4)
{
    int i = blockIdx.x * blockDim.x + threadIdx.x;
    if (i < n4) {
        float4 v = in[i];
        float4 r;
        r.x = __uint_as_float(f2tf32(v.x));
        r.y = __uint_as_float(f2tf32(v.y));
        r.z = __uint_as_float(f2tf32(v.z));
        r.w = __uint_as_float(f2tf32(v.w));
        out[i] = r;
    }
}

// ---------------------------------------------------------------------------
// TF32 tensor-core GEMM, cp.async 3-stage pipeline, 64x64 warp tiles.
// Inputs MUST be pre-tf32-rounded fp32.
// C[M,N] = A[M,K] @ B[K,N] + bias[N].
// BM=128, BN=128, BK=32. 128 threads = 4 warps (2x2). Warp tile 64x64
// (4 m-atoms x 8 n-atoms) -> 128 B smem traffic per MMA (was 192).
// ---------------------------------------------------------------------------
#define GBM 128
#define GBN 128
#define GBK 32
#define AST 36     // A row pitch (words)
#define BST 136    // B row pitch (words)
#define A_WORDS (GBM * AST)          // 4608
#define GSTG (A_WORDS + GBK * BST)   // 8960 words = 35840 B per stage
#define GSTAGES 3

__device__ __forceinline__ void gemm_issue_tile(
    const float* __restrict__ A, const float* __restrict__ B,
    int K, int N, int row0, int col0, int kt, int st,
    uint32_t smem_base, int tid)
{
    const int k0 = kt * GBK;
    uint32_t abase = smem_base + (uint32_t)st * (GSTG * 4);
    uint32_t bbase = abase + A_WORDS * 4;
    #pragma unroll
    for (int p = 0; p < 8; p++) {
        int ch = tid + p * 128;            // 0..1023
        int ar = ch >> 3, ac = (ch & 7) * 4;
        cp16(abase + (uint32_t)(ar * AST + ac) * 4,
             A + (size_t)(row0 + ar) * K + k0 + ac);
    }
    #pragma unroll
    for (int p = 0; p < 8; p++) {
        int ch = tid + p * 128;
        int br = ch >> 5, bc = (ch & 31) * 4;
        cp16(bbase + (uint32_t)(br * BST + bc) * 4,
             B + (size_t)(k0 + br) * N + col0 + bc);
    }
    cp_commit();
}

__device__ __forceinline__ void gemm_body_async(
    const float* __restrict__ A, const float* __restrict__ B,
    const float* __restrict__ bias, float* __restrict__ C,
    int N, int K, int row0, int col0, bool round_out, uint32_t* sm)
{
    const int tid = threadIdx.x;
    const int lane = tid & 31;
    const int wid = tid >> 5;
    const int warp_m = wid & 1;
    const int warp_n = wid >> 1;
    const int gid = lane >> 2;
    const int tig = lane & 3;

    const uint32_t smem_base = (uint32_t)__cvta_generic_to_shared(sm);

    float acc[4][8][4];
    #pragma unroll
    for (int i = 0; i < 4; i++)
        #pragma unroll
        for (int j = 0; j < 8; j++)
            #pragma unroll
            for (int r = 0; r < 4; r++) acc[i][j][r] = 0.f;

    const int nk = K / GBK;
    gemm_issue_tile(A, B, K, N, row0, col0, 0, 0, smem_base, tid);
    gemm_issue_tile(A, B, K, N, row0, col0, 1, 1, smem_base, tid);

    for (int kt = 0; kt < nk; kt++) {
        cp_wait_1();        // tile kt resident
        __syncthreads();    // + everyone done reading stage (kt+2)%3 (iter kt-1)

        if (kt + 2 < nk)
            gemm_issue_tile(A, B, K, N, row0, col0, kt + 2, (kt + 2) % GSTAGES,
                            smem_base, tid);

        const uint32_t* As = sm + (kt % GSTAGES) * GSTG;
        const uint32_t* Bs = As + A_WORDS;

        #pragma unroll
        for (int kk = 0; kk < 4; kk++) {
            uint32_t afr[4][4], bfr[8][2];
            #pragma unroll
            for (int i = 0; i < 4; i++) {
                int mr = warp_m * 64 + i * 16 + gid;
                int kc = kk * 8 + tig;
                afr[i][0] = As[mr * AST + kc];
                afr[i][1] = As[(mr + 8) * AST + kc];
                afr[i][2] = As[mr * AST + kc + 4];
                afr[i][3] = As[(mr + 8) * AST + kc + 4];
            }
            #pragma unroll
            for (int j = 0; j < 8; j++) {
                int nc = warp_n * 64 + j * 8 + gid;
                int kr = kk * 8 + tig;
                bfr[j][0] = Bs[kr * BST + nc];
                bfr[j][1] = Bs[(kr + 4) * BST + nc];
            }
            #pragma unroll
            for (int i = 0; i < 4; i++)
                #pragma unroll
                for (int j = 0; j < 8; j++)
                    mma_tf32(acc[i][j], afr[i], bfr[j]);
        }
    }

    #pragma unroll
    for (int i = 0; i < 4; i++) {
        int r = row0 + warp_m * 64 + i * 16 + gid;
        #pragma unroll
        for (int j = 0; j < 8; j++) {
            int c = col0 + warp_n * 64 + j * 8 + tig * 2;
            float b0 = bias[c], b1 = bias[c + 1];
            float o00 = acc[i][j][0] + b0, o01 = acc[i][j][1] + b1;
            float o10 = acc[i][j][2] + b0, o11 = acc[i][j][3] + b1;
            if (round_out) {
                o00 = __uint_as_float(f2tf32(o00));
                o01 = __uint_as_float(f2tf32(o01));
                o10 = __uint_as_float(f2tf32(o10));
                o11 = __uint_as_float(f2tf32(o11));
            }
            *(float2*)(C + (size_t)r * N + c) = make_float2(o00, o01);
            *(float2*)(C + (size_t)(r + 8) * N + c) = make_float2(o10, o11);
        }
    }
}

// Fused QKV projection: blockIdx.x 0..7 -> Q cols, 8..9 -> K, 10..11 -> V
__global__ __launch_bounds__(128, 2) void gemm_qkv_fused(
    const float* __restrict__ x,
    const float* __restrict__ Wq, const float* __restrict__ bq, float* __restrict__ Qo,
    const float* __restrict__ Wk, const float* __restrict__ bk, float* __restrict__ Ko,
    const float* __restrict__ Wv, const float* __restrict__ bv, float* __restrict__ Vo)
{
    extern __shared__ uint32_t sm[];
    const int bx = blockIdx.x;
    const int row0 = blockIdx.y * GBM;

    const float* B; const float* bias; float* C; int N, col0; bool rnd;
    if (bx < 8)       { B = Wq; bias = bq; C = Qo; N = D_MODEL; col0 = bx * GBN;        rnd = false; }
    else if (bx < 10) { B = Wk; bias = bk; C = Ko; N = D_KV;    col0 = (bx - 8) * GBN;  rnd = true;  }
    else              { B = Wv; bias = bv; C = Vo; N = D_KV;    col0 = (bx - 10) * GBN; rnd = true;  }

    gemm_body_async(x, B, bias, C, N, D_MODEL, row0, col0, rnd, sm);
}

// Plain GEMM (output projection)
__global__ __launch_bounds__(128, 2) void gemm_tf32_bias(
    const float* __restrict__ A, const float* __restrict__ B,
    const float* __restrict__ bias, float* __restrict__ C,
    int M, int N, int K)
{
    extern __shared__ uint32_t sm[];
    gemm_body_async(A, B, bias, C, N, K, blockIdx.y * GBM, blockIdx.x * GBN, false, sm);
}

// ---------------------------------------------------------------------------
// Flash attention with tensor cores (causal, GQA).
// One CTA = (b, h, 64-row q-tile). 128 threads = 4 warps.
//  - QK^T tf32x2 (Q hi/lo in regs, K single tf32), PV tf32
//  - K/V pre-tf32-rounded -> cp.async double-buffered, one barrier per ktile
//  - heavy q-tiles scheduled first (qt reversed) for better makespan
// ---------------------------------------------------------------------------
#define FPAD 68
#define VPAD 72
#define STAGE_WORDS (64 * FPAD + 64 * VPAD)   // 8960 words

__global__ __launch_bounds__(128, 3) void fa_mma_kernel(
    const float* __restrict__ Qb, const float* __restrict__ Kb,
    const float* __restrict__ Vb, float* __restrict__ Ob)
{
    extern __shared__ uint32_t smu[];   // [2][STAGE_WORDS]

    const int bh = blockIdx.x;
    const int b  = bh >> 4;
    const int h  = bh & 15;
    const int kh = h >> 2;
    const int qt = (SEQ / 64 - 1) - blockIdx.y;   // heavy tiles first (LPT)
    const int q0 = qt * 64;
    const int tid = threadIdx.x;
    const int lane = tid & 31;
    const int w = tid >> 5;
    const int gid = lane >> 2;
    const int tig = lane & 3;

    const uint32_t smem_base = (uint32_t)__cvta_generic_to_shared(smu);

    const float* Kh = Kb + (size_t)b * SEQ * D_KV + kh * HEAD_DIM;
    const float* Vh = Vb + (size_t)b * SEQ * D_KV + kh * HEAD_DIM;

    const int rr = tid >> 4;
    const int j4 = (tid & 15) * 4;

    auto issue_tile = [&](int kt, int st) {
        const float* Kg = Kh + (size_t)(kt * 64) * D_KV;
        const float* Vg = Vh + (size_t)(kt * 64) * D_KV;
        uint32_t kbase = smem_base + (uint32_t)st * (STAGE_WORDS * 4);
        uint32_t vbase = kbase + 64 * FPAD * 4;
        #pragma unroll
        for (int p = 0; p < 8; p++) {
            int r = rr + p * 8;
            cp16(kbase + (uint32_t)(r * FPAD + j4) * 4, Kg + (size_t)r * D_KV + j4);
            cp16(vbase + (uint32_t)(r * VPAD + j4) * 4, Vg + (size_t)r * D_KV + j4);
        }
        cp_commit();
    };

    issue_tile(0, 0);

    uint32_t qhi[8][4], qlo[8][4];
    {
        const float* Qg = Qb + ((size_t)(b * SEQ + q0 + w * 16)) * D_MODEL + h * HEAD_DIM;
        #pragma unroll
        for (int kk = 0; kk < 8; kk++) {
            int c0 = kk * 8 + tig;
            float v[4];
            v[0] = Qg[(size_t)gid * D_MODEL + c0] * 0.125f;
            v[1] = Qg[(size_t)(gid + 8) * D_MODEL + c0] * 0.125f;
            v[2] = Qg[(size_t)gid * D_MODEL + c0 + 4] * 0.125f;
            v[3] = Qg[(size_t)(gid + 8) * D_MODEL + c0 + 4] * 0.125f;
            #pragma unroll
            for (int e = 0; e < 4; e++) {
                uint32_t hi = f2tf32(v[e]);
                qhi[kk][e] = hi;
                qlo[kk][e] = f2tf32(v[e] - __uint_as_float(hi));
            }
        }
    }

    float m0 = -INFINITY, m1 = -INFINITY, l0 = 0.f, l1 = 0.f;
    float oacc[8][4];
    #pragma unroll
    for (int na = 0; na < 8; na++)
        #pragma unroll
        for (int c = 0; c < 4; c++) oacc[na][c] = 0.f;

    const int src1 = gid * 4 + (tig >> 1);
    const int src2 = src1 + 2;
    const bool odd = tig & 1;

    for (int kt = 0; kt <= qt; kt++) {
        cp_wait_all();
        __syncthreads();

        if (kt < qt) issue_tile(kt + 1, (kt + 1) & 1);

        const uint32_t* Ks = smu + (size_t)(kt & 1) * STAGE_WORDS;
        const uint32_t* Vs = Ks + 64 * FPAD;

        float sacc[8][4];
        #pragma unroll
        for (int na = 0; na < 8; na++)
            #pragma unroll
            for (int c = 0; c < 4; c++) sacc[na][c] = 0.f;

        #pragma unroll
        for (int kk = 0; kk < 8; kk++) {
            int kc = kk * 8 + tig;
            #pragma unroll
            for (int na = 0; na < 8; na++) {
                int kr = na * 8 + gid;
                uint32_t bf[2] = { Ks[kr * FPAD + kc], Ks[kr * FPAD + kc + 4] };
                mma_tf32(sacc[na], qhi[kk], bf);
                mma_tf32(sacc[na], qlo[kk], bf);
            }
        }

        if (kt == qt) {
            int rbase = w * 16 + gid;
            #pragma unroll
            for (int na = 0; na < 8; na++) {
                int cbase = na * 8 + tig * 2;
                if (cbase     > rbase)     sacc[na][0] = -INFINITY;
                if (cbase + 1 > rbase)     sacc[na][1] = -INFINITY;
                if (cbase     > rbase + 8) sacc[na][2] = -INFINITY;
                if (cbase + 1 > rbase + 8) sacc[na][3] = -INFINITY;
            }
        }

        float tm0 = -INFINITY, tm1 = -INFINITY;
        #pragma unroll
        for (int na = 0; na < 8; na++) {
            tm0 = fmaxf(tm0, fmaxf(sacc[na][0], sacc[na][1]));
            tm1 = fmaxf(tm1, fmaxf(sacc[na][2], sacc[na][3]));
        }
        tm0 = fmaxf(tm0, __shfl_xor_sync(0xffffffffu, tm0, 1));
        tm0 = fmaxf(tm0, __shfl_xor_sync(0xffffffffu, tm0, 2));
        tm1 = fmaxf(tm1, __shfl_xor_sync(0xffffffffu, tm1, 1));
        tm1 = fmaxf(tm1, __shfl_xor_sync(0xffffffffu, tm1, 2));

        float mn0 = fmaxf(m0, tm0), mn1 = fmaxf(m1, tm1);
        float ts0 = 0.f, ts1 = 0.f;
        #pragma unroll
        for (int na = 0; na < 8; na++) {
            sacc[na][0] = __expf(sacc[na][0] - mn0); ts0 += sacc[na][0];
            sacc[na][1] = __expf(sacc[na][1] - mn0); ts0 += sacc[na][1];
            sacc[na][2] = __expf(sacc[na][2] - mn1); ts1 += sacc[na][2];
            sacc[na][3] = __expf(sacc[na][3] - mn1); ts1 += sacc[na][3];
        }
        ts0 += __shfl_xor_sync(0xffffffffu, ts0, 1);
        ts0 += __shfl_xor_sync(0xffffffffu, ts0, 2);
        ts1 += __shfl_xor_sync(0xffffffffu, ts1, 1);
        ts1 += __shfl_xor_sync(0xffffffffu, ts1, 2);

        float a0 = __expf(m0 - mn0), a1 = __expf(m1 - mn1);
        l0 = l0 * a0 + ts0;
        l1 = l1 * a1 + ts1;
        m0 = mn0; m1 = mn1;

        #pragma unroll
        for (int na = 0; na < 8; na++) {
            oacc[na][0] *= a0; oacc[na][1] *= a0;
            oacc[na][2] *= a1; oacc[na][3] *= a1;
        }

        #pragma unroll
        for (int kk = 0; kk < 8; kk++) {
            float e0 = __shfl_sync(0xffffffffu, sacc[kk][0], src1);
            float e1 = __shfl_sync(0xffffffffu, sacc[kk][1], src1);
            float e2 = __shfl_sync(0xffffffffu, sacc[kk][2], src1);
            float e3 = __shfl_sync(0xffffffffu, sacc[kk][3], src1);
            float f0 = __shfl_sync(0xffffffffu, sacc[kk][0], src2);
            float f1 = __shfl_sync(0xffffffffu, sacc[kk][1], src2);
            float f2 = __shfl_sync(0xffffffffu, sacc[kk][2], src2);
            float f3 = __shfl_sync(0xffffffffu, sacc[kk][3], src2);
            uint32_t ap[4];
            ap[0] = f2tf32(odd ? e1 : e0);
            ap[1] = f2tf32(odd ? e3 : e2);
            ap[2] = f2tf32(odd ? f1 : f0);
            ap[3] = f2tf32(odd ? f3 : f2);
            int vr = kk * 8 + tig;
            #pragma unroll
            for (int na = 0; na < 8; na++) {
                uint32_t bv[2] = { Vs[vr * VPAD + na * 8 + gid],
                                   Vs[(vr + 4) * VPAD + na * 8 + gid] };
                mma_tf32(oacc[na], ap, bv);
            }
        }
    }

    // normalize + write out (tf32-rounded: out-proj consumes via cp.async)
    float inv0 = 1.0f / l0, inv1 = 1.0f / l1;
    float* Og = Ob + ((size_t)(b * SEQ + q0)) * D_MODEL + h * HEAD_DIM;
    int r = w * 16 + gid;
    #pragma unroll
    for (int na = 0; na < 8; na++) {
        int c = na * 8 + tig * 2;
        float2 v0, v1;
        v0.x = __uint_as_float(f2tf32(oacc[na][0] * inv0));
        v0.y = __uint_as_float(f2tf32(oacc[na][1] * inv0));
        v1.x = __uint_as_float(f2tf32(oacc[na][2] * inv1));
        v1.y = __uint_as_float(f2tf32(oacc[na][3] * inv1));
        *(float2*)(Og + (size_t)r * D_MODEL + c) = v0;
        *(float2*)(Og + (size_t)(r + 8) * D_MODEL + c) = v1;
    }
}

// ---------------------------------------------------------------------------
// Launch
// ---------------------------------------------------------------------------
extern "C" void kernel_launch(void* const* d_in, const int* in_sizes, int n_in,
                              void* d_out, int out_size)
{
    const float* x  = (const float*)d_in[0];
    const float* Wq = (const float*)d_in[1];
    const float* bq = (const float*)d_in[2];
    const float* Wk = (const float*)d_in[3];
    const float* bk = (const float*)d_in[4];
    const float* Wv = (const float*)d_in[5];
    const float* bv = (const float*)d_in[6];
    const float* Wo = (const float*)d_in[7];
    const float* bo = (const float*)d_in[8];
    // d_in[9] = mask (causal; computed implicitly)
    float* out = (float*)d_out;

    float *Qp, *Kp, *Vp, *Op, *Xp, *Wqp, *Wkp, *Wvp, *Wop;
    cudaGetSymbolAddress((void**)&Qp, g_Q);
    cudaGetSymbolAddress((void**)&Kp, g_K);
    cudaGetSymbolAddress((void**)&Vp, g_V);
    cudaGetSymbolAddress((void**)&Op, g_O);
    cudaGetSymbolAddress((void**)&Xp, g_X);
    cudaGetSymbolAddress((void**)&Wqp, g_Wq);
    cudaGetSymbolAddress((void**)&Wkp, g_Wk);
    cudaGetSymbolAddress((void**)&Wvp, g_Wv);
    cudaGetSymbolAddress((void**)&Wop, g_Wo);

    // pre-round inputs to tf32 (hoisted RNA rounding)
    {
        int n4x = BS * D_MODEL / 4;
        round_tf32_kernel<<<(n4x + 255) / 256, 256>>>((const float4*)x, (float4*)Xp, n4x);
        int n4q = D_MODEL * D_MODEL / 4;
        round_tf32_kernel<<<(n4q + 255) / 256, 256>>>((const float4*)Wq, (float4*)Wqp, n4q);
        int n4k = D_MODEL * D_KV / 4;
        round_tf32_kernel<<<(n4k + 255) / 256, 256>>>((const float4*)Wk, (float4*)Wkp, n4k);
        round_tf32_kernel<<<(n4k + 255) / 256, 256>>>((const float4*)Wv, (float4*)Wvp, n4k);
        round_tf32_kernel<<<(n4q + 255) / 256, 256>>>((const float4*)Wo, (float4*)Wop, n4q);
    }

    size_t gemm_smem = (size_t)GSTAGES * GSTG * sizeof(uint32_t);   // 107520 B

    // fused QKV projection
    {
        cudaFuncSetAttribute(gemm_qkv_fused, cudaFuncAttributeMaxDynamicSharedMemorySize,
                             (int)gemm_smem);
        dim3 g(12, BS / GBM);
        gemm_qkv_fused<<<g, 128, gemm_smem>>>(Xp, Wqp, bq, Qp, Wkp, bk, Kp, Wvp, bv, Vp);
    }

    // flash attention
    {
        size_t smem = (size_t)(2 * STAGE_WORDS) * sizeof(uint32_t);   // 71680 B
        cudaFuncSetAttribute(fa_mma_kernel, cudaFuncAttributeMaxDynamicSharedMemorySize,
                             (int)smem);
        dim3 g(BATCH * N_HEADS, SEQ / 64);
        fa_mma_kernel<<<g, 128, smem>>>(Qp, Kp, Vp, Op);
    }

    // output projection
    {
        cudaFuncSetAttribute(gemm_tf32_bias, cudaFuncAttributeMaxDynamicSharedMemorySize,
                             (int)gemm_smem);
        dim3 go(D_MODEL / GBN, BS / GBM);
        gemm_tf32_bias<<<go, 128, gemm_smem>>>(Op, Wop, bo, out, BS, D_MODEL, D_MODEL);
    }
}

// round 12
// speedup vs baseline: 6.9800x; 1.0989x over previous
#include <cuda_runtime.h>
#include <cuda_bf16.h>
#include <math.h>
#include <stdint.h>

// Problem constants
#define D_MODEL 1024
#define N_HEADS 16
#define N_GROUPS 4
#define HEAD_DIM 64
#define KV_HEADS 4
#define D_KV 256
#define BATCH 2
#define SEQ 2048
#define BS (BATCH * SEQ)   // 4096

// Scratch buffers (device globals: no allocation allowed)
__device__ float g_Q[BS * D_MODEL];        // 16 MB
__device__ float g_K[BS * D_KV];           // 4 MB (tf32-rounded)
__device__ float g_V[BS * D_KV];           // 4 MB (tf32-rounded)
__device__ float g_O[BS * D_MODEL];        // 16 MB (tf32-rounded)
__device__ float g_X[BS * D_MODEL];        // 16 MB (tf32-rounded x)
__device__ float g_Wq[D_MODEL * D_MODEL];  // 4 MB (tf32-rounded)
__device__ float g_Wk[D_MODEL * D_KV];     // 1 MB
__device__ float g_Wv[D_MODEL * D_KV];     // 1 MB
__device__ float g_Wo[D_MODEL * D_MODEL];  // 4 MB
// Fragment-packed K/V tiles: [b*4+kh][kt][4096 floats]
__device__ float g_Kp[BATCH * KV_HEADS * (SEQ / 64) * 4096];  // 4 MB
__device__ float g_Vp[BATCH * KV_HEADS * (SEQ / 64) * 4096];  // 4 MB

// ---------------------------------------------------------------------------
// tf32 helpers
// ---------------------------------------------------------------------------
__device__ __forceinline__ uint32_t f2tf32(float f) {
    uint32_t u;
    asm("cvt.rna.tf32.f32 %0, %1;" : "=r"(u) : "f"(f));
    return u;
}

__device__ __forceinline__ void mma_tf32(float c[4], const uint32_t a[4], const uint32_t b[2]) {
    asm volatile(
        "mma.sync.aligned.m16n8k8.row.col.f32.tf32.tf32.f32 "
        "{%0,%1,%2,%3}, {%4,%5,%6,%7}, {%8,%9}, {%0,%1,%2,%3};"
        : "+f"(c[0]), "+f"(c[1]), "+f"(c[2]), "+f"(c[3])
        : "r"(a[0]), "r"(a[1]), "r"(a[2]), "r"(a[3]), "r"(b[0]), "r"(b[1]));
}

__device__ __forceinline__ void cp16(uint32_t dst_smem, const void* src) {
    asm volatile("cp.async.cg.shared.global [%0], [%1], 16;" :: "r"(dst_smem), "l"(src));
}
__device__ __forceinline__ void cp_commit() {
    asm volatile("cp.async.commit_group;");
}
__device__ __forceinline__ void cp_wait_all() {
    asm volatile("cp.async.wait_group 0;");
}
__device__ __forceinline__ void cp_wait_1() {
    asm volatile("cp.async.wait_group 1;");
}

// ---------------------------------------------------------------------------
// Fused pre-round: X, Wq, Wk, Wv, Wo -> tf32(RNA) in one launch
// ---------------------------------------------------------------------------
#define N4_X  (BS * D_MODEL / 4)        // 1048576
#define N4_WQ (D_MODEL * D_MODEL / 4)   // 262144
#define N4_WK (D_MODEL * D_KV / 4)      // 65536
#define N4_TOTAL (N4_X + N4_WQ + 2 * N4_WK + N4_WQ)

__global__ __launch_bounds__(256) void round_all_kernel(
    const float4* __restrict__ x,  float4* __restrict__ X,
    const float4* __restrict__ wq, float4* __restrict__ WQ,
    const float4* __restrict__ wk, float4* __restrict__ WK,
    const float4* __restrict__ wv, float4* __restrict__ WV,
    const float4* __restrict__ wo, float4* __restrict__ WO)
{
    int i = blockIdx.x * blockDim.x + threadIdx.x;
    if (i >= N4_TOTAL) return;
    const float4* src; float4* dst; int j = i;
    if (j < N4_X)                  { src = x;  dst = X;  }
    else if ((j -= N4_X) < N4_WQ)  { src = wq; dst = WQ; }
    else if ((j -= N4_WQ) < N4_WK) { src = wk; dst = WK; }
    else if ((j -= N4_WK) < N4_WK) { src = wv; dst = WV; }
    else { j -= N4_WK;               src = wo; dst = WO; }
    float4 v = src[j];
    float4 r;
    r.x = __uint_as_float(f2tf32(v.x));
    r.y = __uint_as_float(f2tf32(v.y));
    r.z = __uint_as_float(f2tf32(v.z));
    r.w = __uint_as_float(f2tf32(v.w));
    dst[j] = r;
}

// ---------------------------------------------------------------------------
// Repack K/V 64x64 head-tiles into mma B-fragment order.
// K tile element (kr,kc) -> word (((kk*4+na2)*8+gid)*4+tig)*4 + r8*2 + cq
//   na2=kr>>4, r8=(kr>>3)&1, gid=kr&7; kk=kc>>3, cq=(kc>>2)&1, tig=kc&3
// V tile element (vr,vc) -> same base + c8*2 + v4
//   kk=vr>>3, v4=(vr>>2)&1, tig=vr&3; na2=vc>>4, c8=(vc>>3)&1, gid=vc&7
// ---------------------------------------------------------------------------
__global__ __launch_bounds__(128) void repack_kv_kernel(
    const float* __restrict__ K, const float* __restrict__ V,
    float* __restrict__ Kp, float* __restrict__ Vp)
{
    const int kt = blockIdx.x;              // 0..31
    const int bh = blockIdx.y;              // b*4+kh
    const int b = bh >> 2, kh = bh & 3;
    const bool isV = blockIdx.z != 0;
    const float* src = (isV ? V : K) + ((size_t)(b * SEQ + kt * 64)) * D_KV + kh * HEAD_DIM;
    float* dst = (isV ? Vp : Kp) + ((size_t)bh * 32 + kt) * 4096;
    const int tid = threadIdx.x;

    #pragma unroll
    for (int p = 0; p < 8; p++) {
        int id = tid + p * 128;             // 0..1023
        int r = id >> 4, c4 = (id & 15) * 4;
        float4 v = *(const float4*)(src + (size_t)r * D_KV + c4);
        float vv[4] = {v.x, v.y, v.z, v.w};
        #pragma unroll
        for (int q = 0; q < 4; q++) {
            int cc = c4 + q;
            int widx;
            if (!isV) {
                int na2 = r >> 4, gid = r & 7, r8 = (r >> 3) & 1;
                int kk = cc >> 3, tig = cc & 3, cq = (cc >> 2) & 1;
                widx = (((kk * 4 + na2) * 8 + gid) * 4 + tig) * 4 + r8 * 2 + cq;
            } else {
                int kk = r >> 3, tig = r & 3, v4 = (r >> 2) & 1;
                int na2 = cc >> 4, gid = cc & 7, c8 = (cc >> 3) & 1;
                widx = (((kk * 4 + na2) * 8 + gid) * 4 + tig) * 4 + c8 * 2 + v4;
            }
            dst[widx] = vv[q];
        }
    }
}

// ---------------------------------------------------------------------------
// TF32 tensor-core GEMM, cp.async 3-stage pipeline, 64x64 warp tiles.
// (unchanged from R10-passing version)
// ---------------------------------------------------------------------------
#define GBM 128
#define GBN 128
#define GBK 32
#define AST 36
#define BST 136
#define A_WORDS (GBM * AST)
#define GSTG (A_WORDS + GBK * BST)
#define GSTAGES 3

__device__ __forceinline__ void gemm_issue_tile(
    const float* __restrict__ A, const float* __restrict__ B,
    int K, int N, int row0, int col0, int kt, int st,
    uint32_t smem_base, int tid)
{
    const int k0 = kt * GBK;
    uint32_t abase = smem_base + (uint32_t)st * (GSTG * 4);
    uint32_t bbase = abase + A_WORDS * 4;
    #pragma unroll
    for (int p = 0; p < 8; p++) {
        int ch = tid + p * 128;
        int ar = ch >> 3, ac = (ch & 7) * 4;
        cp16(abase + (uint32_t)(ar * AST + ac) * 4,
             A + (size_t)(row0 + ar) * K + k0 + ac);
    }
    #pragma unroll
    for (int p = 0; p < 8; p++) {
        int ch = tid + p * 128;
        int br = ch >> 5, bc = (ch & 31) * 4;
        cp16(bbase + (uint32_t)(br * BST + bc) * 4,
             B + (size_t)(k0 + br) * N + col0 + bc);
    }
    cp_commit();
}

__device__ __forceinline__ void gemm_body_async(
    const float* __restrict__ A, const float* __restrict__ B,
    const float* __restrict__ bias, float* __restrict__ C,
    int N, int K, int row0, int col0, bool round_out, uint32_t* sm)
{
    const int tid = threadIdx.x;
    const int lane = tid & 31;
    const int wid = tid >> 5;
    const int warp_m = wid & 1;
    const int warp_n = wid >> 1;
    const int gid = lane >> 2;
    const int tig = lane & 3;

    const uint32_t smem_base = (uint32_t)__cvta_generic_to_shared(sm);

    float acc[4][8][4];
    #pragma unroll
    for (int i = 0; i < 4; i++)
        #pragma unroll
        for (int j = 0; j < 8; j++)
            #pragma unroll
            for (int r = 0; r < 4; r++) acc[i][j][r] = 0.f;

    const int nk = K / GBK;
    gemm_issue_tile(A, B, K, N, row0, col0, 0, 0, smem_base, tid);
    gemm_issue_tile(A, B, K, N, row0, col0, 1, 1, smem_base, tid);

    for (int kt = 0; kt < nk; kt++) {
        cp_wait_1();
        __syncthreads();

        if (kt + 2 < nk)
            gemm_issue_tile(A, B, K, N, row0, col0, kt + 2, (kt + 2) % GSTAGES,
                            smem_base, tid);

        const uint32_t* As = sm + (kt % GSTAGES) * GSTG;
        const uint32_t* Bs = As + A_WORDS;

        #pragma unroll
        for (int kk = 0; kk < 4; kk++) {
            uint32_t afr[4][4], bfr[8][2];
            #pragma unroll
            for (int i = 0; i < 4; i++) {
                int mr = warp_m * 64 + i * 16 + gid;
                int kc = kk * 8 + tig;
                afr[i][0] = As[mr * AST + kc];
                afr[i][1] = As[(mr + 8) * AST + kc];
                afr[i][2] = As[mr * AST + kc + 4];
                afr[i][3] = As[(mr + 8) * AST + kc + 4];
            }
            #pragma unroll
            for (int j = 0; j < 8; j++) {
                int nc = warp_n * 64 + j * 8 + gid;
                int kr = kk * 8 + tig;
                bfr[j][0] = Bs[kr * BST + nc];
                bfr[j][1] = Bs[(kr + 4) * BST + nc];
            }
            #pragma unroll
            for (int i = 0; i < 4; i++)
                #pragma unroll
                for (int j = 0; j < 8; j++)
                    mma_tf32(acc[i][j], afr[i], bfr[j]);
        }
    }

    #pragma unroll
    for (int i = 0; i < 4; i++) {
        int r = row0 + warp_m * 64 + i * 16 + gid;
        #pragma unroll
        for (int j = 0; j < 8; j++) {
            int c = col0 + warp_n * 64 + j * 8 + tig * 2;
            float b0 = bias[c], b1 = bias[c + 1];
            float o00 = acc[i][j][0] + b0, o01 = acc[i][j][1] + b1;
            float o10 = acc[i][j][2] + b0, o11 = acc[i][j][3] + b1;
            if (round_out) {
                o00 = __uint_as_float(f2tf32(o00));
                o01 = __uint_as_float(f2tf32(o01));
                o10 = __uint_as_float(f2tf32(o10));
                o11 = __uint_as_float(f2tf32(o11));
            }
            *(float2*)(C + (size_t)r * N + c) = make_float2(o00, o01);
            *(float2*)(C + (size_t)(r + 8) * N + c) = make_float2(o10, o11);
        }
    }
}

// Fused QKV projection: blockIdx.x 0..7 -> Q cols, 8..9 -> K, 10..11 -> V
__global__ __launch_bounds__(128, 2) void gemm_qkv_fused(
    const float* __restrict__ x,
    const float* __restrict__ Wq, const float* __restrict__ bq, float* __restrict__ Qo,
    const float* __restrict__ Wk, const float* __restrict__ bk, float* __restrict__ Ko,
    const float* __restrict__ Wv, const float* __restrict__ bv, float* __restrict__ Vo)
{
    extern __shared__ uint32_t sm[];
    const int bx = blockIdx.x;
    const int row0 = blockIdx.y * GBM;

    const float* B; const float* bias; float* C; int N, col0; bool rnd;
    if (bx < 8)       { B = Wq; bias = bq; C = Qo; N = D_MODEL; col0 = bx * GBN;        rnd = false; }
    else if (bx < 10) { B = Wk; bias = bk; C = Ko; N = D_KV;    col0 = (bx - 8) * GBN;  rnd = true;  }
    else              { B = Wv; bias = bv; C = Vo; N = D_KV;    col0 = (bx - 10) * GBN; rnd = true;  }

    gemm_body_async(x, B, bias, C, N, D_MODEL, row0, col0, rnd, sm);
}

// Plain GEMM (output projection)
__global__ __launch_bounds__(128, 2) void gemm_tf32_bias(
    const float* __restrict__ A, const float* __restrict__ B,
    const float* __restrict__ bias, float* __restrict__ C,
    int M, int N, int K)
{
    extern __shared__ uint32_t sm[];
    gemm_body_async(A, B, bias, C, N, K, blockIdx.y * GBM, blockIdx.x * GBN, false, sm);
}

// ---------------------------------------------------------------------------
// Flash attention (causal, GQA), mma.sync tf32.
// K/V consumed from fragment-packed tiles -> all B-fragment loads are LDS.128.
// cp.async double-buffered (32 KB/stage), 3 CTAs/SM, LPT scheduling.
// ---------------------------------------------------------------------------
#define FA_STG 8192   // words per stage: K 4096 + V 4096

__global__ __launch_bounds__(128, 3) void fa_mma_kernel(
    const float* __restrict__ Qb, const float* __restrict__ Kpk,
    const float* __restrict__ Vpk, float* __restrict__ Ob)
{
    extern __shared__ uint32_t smu[];   // [2][FA_STG]

    const int bh = blockIdx.x;
    const int b  = bh >> 4;
    const int h  = bh & 15;
    const int kh = h >> 2;
    const int qt = (SEQ / 64 - 1) - blockIdx.y;   // heavy tiles first (LPT)
    const int q0 = qt * 64;
    const int tid = threadIdx.x;
    const int lane = tid & 31;
    const int w = tid >> 5;
    const int gid = lane >> 2;
    const int tig = lane & 3;

    const uint32_t smem_base = (uint32_t)__cvta_generic_to_shared(smu);

    const float* Kt = Kpk + ((size_t)(b * 4 + kh) * 32) * 4096;
    const float* Vt = Vpk + ((size_t)(b * 4 + kh) * 32) * 4096;

    auto issue_tile = [&](int kt, int st) {
        const float* Kg = Kt + (size_t)kt * 4096;
        const float* Vg = Vt + (size_t)kt * 4096;
        uint32_t kbase = smem_base + (uint32_t)st * (FA_STG * 4);
        uint32_t vbase = kbase + 4096 * 4;
        #pragma unroll
        for (int p = 0; p < 8; p++) {
            int id = tid + p * 128;   // 0..1023 16B chunks
            cp16(kbase + (uint32_t)id * 16, Kg + (size_t)id * 4);
            cp16(vbase + (uint32_t)id * 16, Vg + (size_t)id * 4);
        }
        cp_commit();
    };

    issue_tile(0, 0);

    // Q fragments in registers: scale 1/8 (exact), hi/lo tf32 split
    uint32_t qhi[8][4], qlo[8][4];
    {
        const float* Qg = Qb + ((size_t)(b * SEQ + q0 + w * 16)) * D_MODEL + h * HEAD_DIM;
        #pragma unroll
        for (int kk = 0; kk < 8; kk++) {
            int c0 = kk * 8 + tig;
            float v[4];
            v[0] = Qg[(size_t)gid * D_MODEL + c0] * 0.125f;
            v[1] = Qg[(size_t)(gid + 8) * D_MODEL + c0] * 0.125f;
            v[2] = Qg[(size_t)gid * D_MODEL + c0 + 4] * 0.125f;
            v[3] = Qg[(size_t)(gid + 8) * D_MODEL + c0 + 4] * 0.125f;
            #pragma unroll
            for (int e = 0; e < 4; e++) {
                uint32_t hi = f2tf32(v[e]);
                qhi[kk][e] = hi;
                qlo[kk][e] = f2tf32(v[e] - __uint_as_float(hi));
            }
        }
    }

    float m0 = -INFINITY, m1 = -INFINITY, l0 = 0.f, l1 = 0.f;
    float oacc[8][4];
    #pragma unroll
    for (int na = 0; na < 8; na++)
        #pragma unroll
        for (int c = 0; c < 4; c++) oacc[na][c] = 0.f;

    const int src1 = gid * 4 + (tig >> 1);
    const int src2 = src1 + 2;
    const bool odd = tig & 1;
    const int fidx = (gid * 4 + tig) * 4;   // per-thread fragment word offset

    for (int kt = 0; kt <= qt; kt++) {
        cp_wait_all();
        __syncthreads();

        if (kt < qt) issue_tile(kt + 1, (kt + 1) & 1);

        const uint32_t* Ks = smu + (size_t)(kt & 1) * FA_STG;
        const uint32_t* Vs = Ks + 4096;

        // ---- S = Q K^T (tf32x2), B-frags via LDS.128 ----
        float sacc[8][4];
        #pragma unroll
        for (int na = 0; na < 8; na++)
            #pragma unroll
            for (int c = 0; c < 4; c++) sacc[na][c] = 0.f;

        #pragma unroll
        for (int kk = 0; kk < 8; kk++) {
            #pragma unroll
            for (int na2 = 0; na2 < 4; na2++) {
                uint4 k4 = *(const uint4*)(Ks + (kk * 4 + na2) * 128 + fidx);
                uint32_t b0[2] = { k4.x, k4.y };
                uint32_t b1[2] = { k4.z, k4.w };
                mma_tf32(sacc[2 * na2],     qhi[kk], b0);
                mma_tf32(sacc[2 * na2],     qlo[kk], b0);
                mma_tf32(sacc[2 * na2 + 1], qhi[kk], b1);
                mma_tf32(sacc[2 * na2 + 1], qlo[kk], b1);
            }
        }

        // ---- causal mask on the diagonal tile ----
        if (kt == qt) {
            int rbase = w * 16 + gid;
            #pragma unroll
            for (int na = 0; na < 8; na++) {
                int cbase = na * 8 + tig * 2;
                if (cbase     > rbase)     sacc[na][0] = -INFINITY;
                if (cbase + 1 > rbase)     sacc[na][1] = -INFINITY;
                if (cbase     > rbase + 8) sacc[na][2] = -INFINITY;
                if (cbase + 1 > rbase + 8) sacc[na][3] = -INFINITY;
            }
        }

        // ---- online softmax (registers + 4-lane shfl reductions) ----
        float tm0 = -INFINITY, tm1 = -INFINITY;
        #pragma unroll
        for (int na = 0; na < 8; na++) {
            tm0 = fmaxf(tm0, fmaxf(sacc[na][0], sacc[na][1]));
            tm1 = fmaxf(tm1, fmaxf(sacc[na][2], sacc[na][3]));
        }
        tm0 = fmaxf(tm0, __shfl_xor_sync(0xffffffffu, tm0, 1));
        tm0 = fmaxf(tm0, __shfl_xor_sync(0xffffffffu, tm0, 2));
        tm1 = fmaxf(tm1, __shfl_xor_sync(0xffffffffu, tm1, 1));
        tm1 = fmaxf(tm1, __shfl_xor_sync(0xffffffffu, tm1, 2));

        float mn0 = fmaxf(m0, tm0), mn1 = fmaxf(m1, tm1);
        float ts0 = 0.f, ts1 = 0.f;
        #pragma unroll
        for (int na = 0; na < 8; na++) {
            sacc[na][0] = __expf(sacc[na][0] - mn0); ts0 += sacc[na][0];
            sacc[na][1] = __expf(sacc[na][1] - mn0); ts0 += sacc[na][1];
            sacc[na][2] = __expf(sacc[na][2] - mn1); ts1 += sacc[na][2];
            sacc[na][3] = __expf(sacc[na][3] - mn1); ts1 += sacc[na][3];
        }
        ts0 += __shfl_xor_sync(0xffffffffu, ts0, 1);
        ts0 += __shfl_xor_sync(0xffffffffu, ts0, 2);
        ts1 += __shfl_xor_sync(0xffffffffu, ts1, 1);
        ts1 += __shfl_xor_sync(0xffffffffu, ts1, 2);

        float a0 = __expf(m0 - mn0), a1 = __expf(m1 - mn1);
        l0 = l0 * a0 + ts0;
        l1 = l1 * a1 + ts1;
        m0 = mn0; m1 = mn1;

        #pragma unroll
        for (int na = 0; na < 8; na++) {
            oacc[na][0] *= a0; oacc[na][1] *= a0;
            oacc[na][2] *= a1; oacc[na][3] *= a1;
        }

        // ---- O += P V : P relayout via shuffles; V frags via LDS.128 ----
        #pragma unroll
        for (int kk = 0; kk < 8; kk++) {
            float e0 = __shfl_sync(0xffffffffu, sacc[kk][0], src1);
            float e1 = __shfl_sync(0xffffffffu, sacc[kk][1], src1);
            float e2 = __shfl_sync(0xffffffffu, sacc[kk][2], src1);
            float e3 = __shfl_sync(0xffffffffu, sacc[kk][3], src1);
            float f0 = __shfl_sync(0xffffffffu, sacc[kk][0], src2);
            float f1 = __shfl_sync(0xffffffffu, sacc[kk][1], src2);
            float f2 = __shfl_sync(0xffffffffu, sacc[kk][2], src2);
            float f3 = __shfl_sync(0xffffffffu, sacc[kk][3], src2);
            uint32_t ap[4];
            ap[0] = f2tf32(odd ? e1 : e0);
            ap[1] = f2tf32(odd ? e3 : e2);
            ap[2] = f2tf32(odd ? f1 : f0);
            ap[3] = f2tf32(odd ? f3 : f2);
            #pragma unroll
            for (int na2 = 0; na2 < 4; na2++) {
                uint4 v4 = *(const uint4*)(Vs + (kk * 4 + na2) * 128 + fidx);
                uint32_t b0[2] = { v4.x, v4.y };
                uint32_t b1[2] = { v4.z, v4.w };
                mma_tf32(oacc[2 * na2],     ap, b0);
                mma_tf32(oacc[2 * na2 + 1], ap, b1);
            }
        }
    }

    // normalize + write out (tf32-rounded: out-proj consumes pre-rounded A)
    float inv0 = 1.0f / l0, inv1 = 1.0f / l1;
    float* Og = Ob + ((size_t)(b * SEQ + q0)) * D_MODEL + h * HEAD_DIM;
    int r = w * 16 + gid;
    #pragma unroll
    for (int na = 0; na < 8; na++) {
        int c = na * 8 + tig * 2;
        float2 v0, v1;
        v0.x = __uint_as_float(f2tf32(oacc[na][0] * inv0));
        v0.y = __uint_as_float(f2tf32(oacc[na][1] * inv0));
        v1.x = __uint_as_float(f2tf32(oacc[na][2] * inv1));
        v1.y = __uint_as_float(f2tf32(oacc[na][3] * inv1));
        *(float2*)(Og + (size_t)r * D_MODEL + c) = v0;
        *(float2*)(Og + (size_t)(r + 8) * D_MODEL + c) = v1;
    }
}

// ---------------------------------------------------------------------------
// Launch
// ---------------------------------------------------------------------------
extern "C" void kernel_launch(void* const* d_in, const int* in_sizes, int n_in,
                              void* d_out, int out_size)
{
    const float* x  = (const float*)d_in[0];
    const float* Wq = (const float*)d_in[1];
    const float* bq = (const float*)d_in[2];
    const float* Wk = (const float*)d_in[3];
    const float* bk = (const float*)d_in[4];
    const float* Wv = (const float*)d_in[5];
    const float* bv = (const float*)d_in[6];
    const float* Wo = (const float*)d_in[7];
    const float* bo = (const float*)d_in[8];
    // d_in[9] = mask (causal; computed implicitly)
    float* out = (float*)d_out;

    float *Qp, *Kp, *Vp, *Op, *Xp, *Wqp, *Wkp, *Wvp, *Wop, *Kpp, *Vpp;
    cudaGetSymbolAddress((void**)&Qp, g_Q);
    cudaGetSymbolAddress((void**)&Kp, g_K);
    cudaGetSymbolAddress((void**)&Vp, g_V);
    cudaGetSymbolAddress((void**)&Op, g_O);
    cudaGetSymbolAddress((void**)&Xp, g_X);
    cudaGetSymbolAddress((void**)&Wqp, g_Wq);
    cudaGetSymbolAddress((void**)&Wkp, g_Wk);
    cudaGetSymbolAddress((void**)&Wvp, g_Wv);
    cudaGetSymbolAddress((void**)&Wop, g_Wo);
    cudaGetSymbolAddress((void**)&Kpp, g_Kp);
    cudaGetSymbolAddress((void**)&Vpp, g_Vp);

    // fused pre-round (one launch)
    round_all_kernel<<<(N4_TOTAL + 255) / 256, 256>>>(
        (const float4*)x,  (float4*)Xp,
        (const float4*)Wq, (float4*)Wqp,
        (const float4*)Wk, (float4*)Wkp,
        (const float4*)Wv, (float4*)Wvp,
        (const float4*)Wo, (float4*)Wop);

    size_t gemm_smem = (size_t)GSTAGES * GSTG * sizeof(uint32_t);   // 107520 B

    // fused QKV projection
    {
        cudaFuncSetAttribute(gemm_qkv_fused, cudaFuncAttributeMaxDynamicSharedMemorySize,
                             (int)gemm_smem);
        dim3 g(12, BS / GBM);
        gemm_qkv_fused<<<g, 128, gemm_smem>>>(Xp, Wqp, bq, Qp, Wkp, bk, Kp, Wvp, bv, Vp);
    }

    // repack K/V into fragment order
    {
        dim3 g(SEQ / 64, BATCH * KV_HEADS, 2);
        repack_kv_kernel<<<g, 128>>>(Kp, Vp, Kpp, Vpp);
    }

    // flash attention
    {
        size_t smem = (size_t)(2 * FA_STG) * sizeof(uint32_t);   // 65536 B
        cudaFuncSetAttribute(fa_mma_kernel, cudaFuncAttributeMaxDynamicSharedMemorySize,
                             (int)smem);
        dim3 g(BATCH * N_HEADS, SEQ / 64);
        fa_mma_kernel<<<g, 128, smem>>>(Qp, Kpp, Vpp, Op);
    }

    // output projection
    {
        cudaFuncSetAttribute(gemm_tf32_bias, cudaFuncAttributeMaxDynamicSharedMemorySize,
                             (int)gemm_smem);
        dim3 go(D_MODEL / GBN, BS / GBM);
        gemm_tf32_bias<<<go, 128, gemm_smem>>>(Op, Wop, bo, out, BS, D_MODEL, D_MODEL);
    }
}

// round 13
// speedup vs baseline: 7.8893x; 1.1303x over previous
#include <cuda_runtime.h>
#include <cuda_bf16.h>
#include <math.h>
#include <stdint.h>

// Problem constants
#define D_MODEL 1024
#define N_HEADS 16
#define N_GROUPS 4
#define HEAD_DIM 64
#define KV_HEADS 4
#define D_KV 256
#define BATCH 2
#define SEQ 2048
#define BS (BATCH * SEQ)   // 4096

// Scratch buffers (device globals: no allocation allowed)
__device__ float g_Q[BS * D_MODEL];        // 16 MB
__device__ float g_K[BS * D_KV];           // 4 MB (tf32-rounded)
__device__ float g_V[BS * D_KV];           // 4 MB (tf32-rounded)
__device__ float g_O[BS * D_MODEL];        // 16 MB (tf32-rounded)
__device__ float g_X[BS * D_MODEL];        // 16 MB (tf32-rounded x)
__device__ float g_Wq[D_MODEL * D_MODEL];  // 4 MB (tf32-rounded)
__device__ float g_Wk[D_MODEL * D_KV];     // 1 MB
__device__ float g_Wv[D_MODEL * D_KV];     // 1 MB
__device__ float g_Wo[D_MODEL * D_MODEL];  // 4 MB
// Fragment-packed K/V tiles: [b*4+kh][kt][4096 floats]
__device__ float g_Kp[BATCH * KV_HEADS * (SEQ / 64) * 4096];  // 4 MB
__device__ float g_Vp[BATCH * KV_HEADS * (SEQ / 64) * 4096];  // 4 MB

// ---------------------------------------------------------------------------
// tf32 helpers
// ---------------------------------------------------------------------------
__device__ __forceinline__ uint32_t f2tf32(float f) {
    uint32_t u;
    asm("cvt.rna.tf32.f32 %0, %1;" : "=r"(u) : "f"(f));
    return u;
}

__device__ __forceinline__ void mma_tf32(float c[4], const uint32_t a[4], const uint32_t b[2]) {
    asm volatile(
        "mma.sync.aligned.m16n8k8.row.col.f32.tf32.tf32.f32 "
        "{%0,%1,%2,%3}, {%4,%5,%6,%7}, {%8,%9}, {%0,%1,%2,%3};"
        : "+f"(c[0]), "+f"(c[1]), "+f"(c[2]), "+f"(c[3])
        : "r"(a[0]), "r"(a[1]), "r"(a[2]), "r"(a[3]), "r"(b[0]), "r"(b[1]));
}

__device__ __forceinline__ void cp16(uint32_t dst_smem, const void* src) {
    asm volatile("cp.async.cg.shared.global [%0], [%1], 16;" :: "r"(dst_smem), "l"(src));
}
__device__ __forceinline__ void cp_commit() {
    asm volatile("cp.async.commit_group;");
}
__device__ __forceinline__ void cp_wait_all() {
    asm volatile("cp.async.wait_group 0;");
}
__device__ __forceinline__ void cp_wait_1() {
    asm volatile("cp.async.wait_group 1;");
}

// ---------------------------------------------------------------------------
// Fused pre-round: X, Wq, Wk, Wv, Wo -> tf32(RNA) in one launch
// ---------------------------------------------------------------------------
#define N4_X  (BS * D_MODEL / 4)        // 1048576
#define N4_WQ (D_MODEL * D_MODEL / 4)   // 262144
#define N4_WK (D_MODEL * D_KV / 4)      // 65536
#define N4_TOTAL (N4_X + N4_WQ + 2 * N4_WK + N4_WQ)

__global__ __launch_bounds__(256) void round_all_kernel(
    const float4* __restrict__ x,  float4* __restrict__ X,
    const float4* __restrict__ wq, float4* __restrict__ WQ,
    const float4* __restrict__ wk, float4* __restrict__ WK,
    const float4* __restrict__ wv, float4* __restrict__ WV,
    const float4* __restrict__ wo, float4* __restrict__ WO)
{
    int i = blockIdx.x * blockDim.x + threadIdx.x;
    if (i >= N4_TOTAL) return;
    const float4* src; float4* dst; int j = i;
    if (j < N4_X)                  { src = x;  dst = X;  }
    else if ((j -= N4_X) < N4_WQ)  { src = wq; dst = WQ; }
    else if ((j -= N4_WQ) < N4_WK) { src = wk; dst = WK; }
    else if ((j -= N4_WK) < N4_WK) { src = wv; dst = WV; }
    else { j -= N4_WK;               src = wo; dst = WO; }
    float4 v = src[j];
    float4 r;
    r.x = __uint_as_float(f2tf32(v.x));
    r.y = __uint_as_float(f2tf32(v.y));
    r.z = __uint_as_float(f2tf32(v.z));
    r.w = __uint_as_float(f2tf32(v.w));
    dst[j] = r;
}

// ---------------------------------------------------------------------------
// Repack K/V 64x64 head-tiles into mma B-fragment order (unchanged).
// ---------------------------------------------------------------------------
__global__ __launch_bounds__(128) void repack_kv_kernel(
    const float* __restrict__ K, const float* __restrict__ V,
    float* __restrict__ Kp, float* __restrict__ Vp)
{
    const int kt = blockIdx.x;              // 0..31
    const int bh = blockIdx.y;              // b*4+kh
    const int b = bh >> 2, kh = bh & 3;
    const bool isV = blockIdx.z != 0;
    const float* src = (isV ? V : K) + ((size_t)(b * SEQ + kt * 64)) * D_KV + kh * HEAD_DIM;
    float* dst = (isV ? Vp : Kp) + ((size_t)bh * 32 + kt) * 4096;
    const int tid = threadIdx.x;

    #pragma unroll
    for (int p = 0; p < 8; p++) {
        int id = tid + p * 128;             // 0..1023
        int r = id >> 4, c4 = (id & 15) * 4;
        float4 v = *(const float4*)(src + (size_t)r * D_KV + c4);
        float vv[4] = {v.x, v.y, v.z, v.w};
        #pragma unroll
        for (int q = 0; q < 4; q++) {
            int cc = c4 + q;
            int widx;
            if (!isV) {
                int na2 = r >> 4, gid = r & 7, r8 = (r >> 3) & 1;
                int kk = cc >> 3, tig = cc & 3, cq = (cc >> 2) & 1;
                widx = (((kk * 4 + na2) * 8 + gid) * 4 + tig) * 4 + r8 * 2 + cq;
            } else {
                int kk = r >> 3, tig = r & 3, v4 = (r >> 2) & 1;
                int na2 = cc >> 4, gid = cc & 7, c8 = (cc >> 3) & 1;
                widx = (((kk * 4 + na2) * 8 + gid) * 4 + tig) * 4 + c8 * 2 + v4;
            }
            dst[widx] = vv[q];
        }
    }
}

// ---------------------------------------------------------------------------
// TF32 tensor-core GEMM, cp.async 3-stage pipeline, 64x64 warp tiles.
// (unchanged from R11-passing version)
// ---------------------------------------------------------------------------
#define GBM 128
#define GBN 128
#define GBK 32
#define AST 36
#define BST 136
#define A_WORDS (GBM * AST)
#define GSTG (A_WORDS + GBK * BST)
#define GSTAGES 3

__device__ __forceinline__ void gemm_issue_tile(
    const float* __restrict__ A, const float* __restrict__ B,
    int K, int N, int row0, int col0, int kt, int st,
    uint32_t smem_base, int tid)
{
    const int k0 = kt * GBK;
    uint32_t abase = smem_base + (uint32_t)st * (GSTG * 4);
    uint32_t bbase = abase + A_WORDS * 4;
    #pragma unroll
    for (int p = 0; p < 8; p++) {
        int ch = tid + p * 128;
        int ar = ch >> 3, ac = (ch & 7) * 4;
        cp16(abase + (uint32_t)(ar * AST + ac) * 4,
             A + (size_t)(row0 + ar) * K + k0 + ac);
    }
    #pragma unroll
    for (int p = 0; p < 8; p++) {
        int ch = tid + p * 128;
        int br = ch >> 5, bc = (ch & 31) * 4;
        cp16(bbase + (uint32_t)(br * BST + bc) * 4,
             B + (size_t)(k0 + br) * N + col0 + bc);
    }
    cp_commit();
}

__device__ __forceinline__ void gemm_body_async(
    const float* __restrict__ A, const float* __restrict__ B,
    const float* __restrict__ bias, float* __restrict__ C,
    int N, int K, int row0, int col0, bool round_out, uint32_t* sm)
{
    const int tid = threadIdx.x;
    const int lane = tid & 31;
    const int wid = tid >> 5;
    const int warp_m = wid & 1;
    const int warp_n = wid >> 1;
    const int gid = lane >> 2;
    const int tig = lane & 3;

    const uint32_t smem_base = (uint32_t)__cvta_generic_to_shared(sm);

    float acc[4][8][4];
    #pragma unroll
    for (int i = 0; i < 4; i++)
        #pragma unroll
        for (int j = 0; j < 8; j++)
            #pragma unroll
            for (int r = 0; r < 4; r++) acc[i][j][r] = 0.f;

    const int nk = K / GBK;
    gemm_issue_tile(A, B, K, N, row0, col0, 0, 0, smem_base, tid);
    gemm_issue_tile(A, B, K, N, row0, col0, 1, 1, smem_base, tid);

    for (int kt = 0; kt < nk; kt++) {
        cp_wait_1();
        __syncthreads();

        if (kt + 2 < nk)
            gemm_issue_tile(A, B, K, N, row0, col0, kt + 2, (kt + 2) % GSTAGES,
                            smem_base, tid);

        const uint32_t* As = sm + (kt % GSTAGES) * GSTG;
        const uint32_t* Bs = As + A_WORDS;

        #pragma unroll
        for (int kk = 0; kk < 4; kk++) {
            uint32_t afr[4][4], bfr[8][2];
            #pragma unroll
            for (int i = 0; i < 4; i++) {
                int mr = warp_m * 64 + i * 16 + gid;
                int kc = kk * 8 + tig;
                afr[i][0] = As[mr * AST + kc];
                afr[i][1] = As[(mr + 8) * AST + kc];
                afr[i][2] = As[mr * AST + kc + 4];
                afr[i][3] = As[(mr + 8) * AST + kc + 4];
            }
            #pragma unroll
            for (int j = 0; j < 8; j++) {
                int nc = warp_n * 64 + j * 8 + gid;
                int kr = kk * 8 + tig;
                bfr[j][0] = Bs[kr * BST + nc];
                bfr[j][1] = Bs[(kr + 4) * BST + nc];
            }
            #pragma unroll
            for (int i = 0; i < 4; i++)
                #pragma unroll
                for (int j = 0; j < 8; j++)
                    mma_tf32(acc[i][j], afr[i], bfr[j]);
        }
    }

    #pragma unroll
    for (int i = 0; i < 4; i++) {
        int r = row0 + warp_m * 64 + i * 16 + gid;
        #pragma unroll
        for (int j = 0; j < 8; j++) {
            int c = col0 + warp_n * 64 + j * 8 + tig * 2;
            float b0 = bias[c], b1 = bias[c + 1];
            float o00 = acc[i][j][0] + b0, o01 = acc[i][j][1] + b1;
            float o10 = acc[i][j][2] + b0, o11 = acc[i][j][3] + b1;
            if (round_out) {
                o00 = __uint_as_float(f2tf32(o00));
                o01 = __uint_as_float(f2tf32(o01));
                o10 = __uint_as_float(f2tf32(o10));
                o11 = __uint_as_float(f2tf32(o11));
            }
            *(float2*)(C + (size_t)r * N + c) = make_float2(o00, o01);
            *(float2*)(C + (size_t)(r + 8) * N + c) = make_float2(o10, o11);
        }
    }
}

// Fused QKV projection: blockIdx.x 0..7 -> Q cols, 8..9 -> K, 10..11 -> V
__global__ __launch_bounds__(128, 2) void gemm_qkv_fused(
    const float* __restrict__ x,
    const float* __restrict__ Wq, const float* __restrict__ bq, float* __restrict__ Qo,
    const float* __restrict__ Wk, const float* __restrict__ bk, float* __restrict__ Ko,
    const float* __restrict__ Wv, const float* __restrict__ bv, float* __restrict__ Vo)
{
    extern __shared__ uint32_t sm[];
    const int bx = blockIdx.x;
    const int row0 = blockIdx.y * GBM;

    const float* B; const float* bias; float* C; int N, col0; bool rnd;
    if (bx < 8)       { B = Wq; bias = bq; C = Qo; N = D_MODEL; col0 = bx * GBN;        rnd = false; }
    else if (bx < 10) { B = Wk; bias = bk; C = Ko; N = D_KV;    col0 = (bx - 8) * GBN;  rnd = true;  }
    else              { B = Wv; bias = bv; C = Vo; N = D_KV;    col0 = (bx - 10) * GBN; rnd = true;  }

    gemm_body_async(x, B, bias, C, N, D_MODEL, row0, col0, rnd, sm);
}

// Plain GEMM (output projection)
__global__ __launch_bounds__(128, 2) void gemm_tf32_bias(
    const float* __restrict__ A, const float* __restrict__ B,
    const float* __restrict__ bias, float* __restrict__ C,
    int M, int N, int K)
{
    extern __shared__ uint32_t sm[];
    gemm_body_async(A, B, bias, C, N, K, blockIdx.y * GBM, blockIdx.x * GBN, false, sm);
}

// ---------------------------------------------------------------------------
// Flash attention (causal, GQA), mma.sync tf32x1.
// Q and K both single-RNA-rounded; K/V from fragment-packed tiles (LDS.128).
// cp.async double-buffered, 3 CTAs/SM, LPT scheduling.
// ---------------------------------------------------------------------------
#define FA_STG 8192   // words per stage: K 4096 + V 4096

__global__ __launch_bounds__(128, 3) void fa_mma_kernel(
    const float* __restrict__ Qb, const float* __restrict__ Kpk,
    const float* __restrict__ Vpk, float* __restrict__ Ob)
{
    extern __shared__ uint32_t smu[];   // [2][FA_STG]

    const int bh = blockIdx.x;
    const int b  = bh >> 4;
    const int h  = bh & 15;
    const int kh = h >> 2;
    const int qt = (SEQ / 64 - 1) - blockIdx.y;   // heavy tiles first (LPT)
    const int q0 = qt * 64;
    const int tid = threadIdx.x;
    const int lane = tid & 31;
    const int w = tid >> 5;
    const int gid = lane >> 2;
    const int tig = lane & 3;

    const uint32_t smem_base = (uint32_t)__cvta_generic_to_shared(smu);

    const float* Kt = Kpk + ((size_t)(b * 4 + kh) * 32) * 4096;
    const float* Vt = Vpk + ((size_t)(b * 4 + kh) * 32) * 4096;

    auto issue_tile = [&](int kt, int st) {
        const float* Kg = Kt + (size_t)kt * 4096;
        const float* Vg = Vt + (size_t)kt * 4096;
        uint32_t kbase = smem_base + (uint32_t)st * (FA_STG * 4);
        uint32_t vbase = kbase + 4096 * 4;
        #pragma unroll
        for (int p = 0; p < 8; p++) {
            int id = tid + p * 128;   // 0..1023 16B chunks
            cp16(kbase + (uint32_t)id * 16, Kg + (size_t)id * 4);
            cp16(vbase + (uint32_t)id * 16, Vg + (size_t)id * 4);
        }
        cp_commit();
    };

    issue_tile(0, 0);

    // Q fragments in registers: scale 1/8 (exact), single RNA rounding
    uint32_t qfr[8][4];
    {
        const float* Qg = Qb + ((size_t)(b * SEQ + q0 + w * 16)) * D_MODEL + h * HEAD_DIM;
        #pragma unroll
        for (int kk = 0; kk < 8; kk++) {
            int c0 = kk * 8 + tig;
            qfr[kk][0] = f2tf32(Qg[(size_t)gid * D_MODEL + c0] * 0.125f);
            qfr[kk][1] = f2tf32(Qg[(size_t)(gid + 8) * D_MODEL + c0] * 0.125f);
            qfr[kk][2] = f2tf32(Qg[(size_t)gid * D_MODEL + c0 + 4] * 0.125f);
            qfr[kk][3] = f2tf32(Qg[(size_t)(gid + 8) * D_MODEL + c0 + 4] * 0.125f);
        }
    }

    float m0 = -INFINITY, m1 = -INFINITY, l0 = 0.f, l1 = 0.f;
    float oacc[8][4];
    #pragma unroll
    for (int na = 0; na < 8; na++)
        #pragma unroll
        for (int c = 0; c < 4; c++) oacc[na][c] = 0.f;

    const int src1 = gid * 4 + (tig >> 1);
    const int src2 = src1 + 2;
    const bool odd = tig & 1;
    const int fidx = (gid * 4 + tig) * 4;   // per-thread fragment word offset

    for (int kt = 0; kt <= qt; kt++) {
        cp_wait_all();
        __syncthreads();

        if (kt < qt) issue_tile(kt + 1, (kt + 1) & 1);

        const uint32_t* Ks = smu + (size_t)(kt & 1) * FA_STG;
        const uint32_t* Vs = Ks + 4096;

        // ---- S = Q K^T (tf32x1), B-frags via LDS.128 ----
        float sacc[8][4];
        #pragma unroll
        for (int na = 0; na < 8; na++)
            #pragma unroll
            for (int c = 0; c < 4; c++) sacc[na][c] = 0.f;

        #pragma unroll
        for (int kk = 0; kk < 8; kk++) {
            #pragma unroll
            for (int na2 = 0; na2 < 4; na2++) {
                uint4 k4 = *(const uint4*)(Ks + (kk * 4 + na2) * 128 + fidx);
                uint32_t b0[2] = { k4.x, k4.y };
                uint32_t b1[2] = { k4.z, k4.w };
                mma_tf32(sacc[2 * na2],     qfr[kk], b0);
                mma_tf32(sacc[2 * na2 + 1], qfr[kk], b1);
            }
        }

        // ---- causal mask on the diagonal tile ----
        if (kt == qt) {
            int rbase = w * 16 + gid;
            #pragma unroll
            for (int na = 0; na < 8; na++) {
                int cbase = na * 8 + tig * 2;
                if (cbase     > rbase)     sacc[na][0] = -INFINITY;
                if (cbase + 1 > rbase)     sacc[na][1] = -INFINITY;
                if (cbase     > rbase + 8) sacc[na][2] = -INFINITY;
                if (cbase + 1 > rbase + 8) sacc[na][3] = -INFINITY;
            }
        }

        // ---- online softmax (registers + 4-lane shfl reductions) ----
        float tm0 = -INFINITY, tm1 = -INFINITY;
        #pragma unroll
        for (int na = 0; na < 8; na++) {
            tm0 = fmaxf(tm0, fmaxf(sacc[na][0], sacc[na][1]));
            tm1 = fmaxf(tm1, fmaxf(sacc[na][2], sacc[na][3]));
        }
        tm0 = fmaxf(tm0, __shfl_xor_sync(0xffffffffu, tm0, 1));
        tm0 = fmaxf(tm0, __shfl_xor_sync(0xffffffffu, tm0, 2));
        tm1 = fmaxf(tm1, __shfl_xor_sync(0xffffffffu, tm1, 1));
        tm1 = fmaxf(tm1, __shfl_xor_sync(0xffffffffu, tm1, 2));

        float mn0 = fmaxf(m0, tm0), mn1 = fmaxf(m1, tm1);
        float ts0 = 0.f, ts1 = 0.f;
        #pragma unroll
        for (int na = 0; na < 8; na++) {
            sacc[na][0] = __expf(sacc[na][0] - mn0); ts0 += sacc[na][0];
            sacc[na][1] = __expf(sacc[na][1] - mn0); ts0 += sacc[na][1];
            sacc[na][2] = __expf(sacc[na][2] - mn1); ts1 += sacc[na][2];
            sacc[na][3] = __expf(sacc[na][3] - mn1); ts1 += sacc[na][3];
        }
        ts0 += __shfl_xor_sync(0xffffffffu, ts0, 1);
        ts0 += __shfl_xor_sync(0xffffffffu, ts0, 2);
        ts1 += __shfl_xor_sync(0xffffffffu, ts1, 1);
        ts1 += __shfl_xor_sync(0xffffffffu, ts1, 2);

        float a0 = __expf(m0 - mn0), a1 = __expf(m1 - mn1);
        l0 = l0 * a0 + ts0;
        l1 = l1 * a1 + ts1;
        m0 = mn0; m1 = mn1;

        #pragma unroll
        for (int na = 0; na < 8; na++) {
            oacc[na][0] *= a0; oacc[na][1] *= a0;
            oacc[na][2] *= a1; oacc[na][3] *= a1;
        }

        // ---- O += P V : P relayout via shuffles; V frags via LDS.128 ----
        #pragma unroll
        for (int kk = 0; kk < 8; kk++) {
            float e0 = __shfl_sync(0xffffffffu, sacc[kk][0], src1);
            float e1 = __shfl_sync(0xffffffffu, sacc[kk][1], src1);
            float e2 = __shfl_sync(0xffffffffu, sacc[kk][2], src1);
            float e3 = __shfl_sync(0xffffffffu, sacc[kk][3], src1);
            float f0 = __shfl_sync(0xffffffffu, sacc[kk][0], src2);
            float f1 = __shfl_sync(0xffffffffu, sacc[kk][1], src2);
            float f2 = __shfl_sync(0xffffffffu, sacc[kk][2], src2);
            float f3 = __shfl_sync(0xffffffffu, sacc[kk][3], src2);
            uint32_t ap[4];
            ap[0] = f2tf32(odd ? e1 : e0);
            ap[1] = f2tf32(odd ? e3 : e2);
            ap[2] = f2tf32(odd ? f1 : f0);
            ap[3] = f2tf32(odd ? f3 : f2);
            #pragma unroll
            for (int na2 = 0; na2 < 4; na2++) {
                uint4 v4 = *(const uint4*)(Vs + (kk * 4 + na2) * 128 + fidx);
                uint32_t b0[2] = { v4.x, v4.y };
                uint32_t b1[2] = { v4.z, v4.w };
                mma_tf32(oacc[2 * na2],     ap, b0);
                mma_tf32(oacc[2 * na2 + 1], ap, b1);
            }
        }
    }

    // normalize + write out (tf32-rounded: out-proj consumes pre-rounded A)
    float inv0 = 1.0f / l0, inv1 = 1.0f / l1;
    float* Og = Ob + ((size_t)(b * SEQ + q0)) * D_MODEL + h * HEAD_DIM;
    int r = w * 16 + gid;
    #pragma unroll
    for (int na = 0; na < 8; na++) {
        int c = na * 8 + tig * 2;
        float2 v0, v1;
        v0.x = __uint_as_float(f2tf32(oacc[na][0] * inv0));
        v0.y = __uint_as_float(f2tf32(oacc[na][1] * inv0));
        v1.x = __uint_as_float(f2tf32(oacc[na][2] * inv1));
        v1.y = __uint_as_float(f2tf32(oacc[na][3] * inv1));
        *(float2*)(Og + (size_t)r * D_MODEL + c) = v0;
        *(float2*)(Og + (size_t)(r + 8) * D_MODEL + c) = v1;
    }
}

// ---------------------------------------------------------------------------
// Launch
// ---------------------------------------------------------------------------
extern "C" void kernel_launch(void* const* d_in, const int* in_sizes, int n_in,
                              void* d_out, int out_size)
{
    const float* x  = (const float*)d_in[0];
    const float* Wq = (const float*)d_in[1];
    const float* bq = (const float*)d_in[2];
    const float* Wk = (const float*)d_in[3];
    const float* bk = (const float*)d_in[4];
    const float* Wv = (const float*)d_in[5];
    const float* bv = (const float*)d_in[6];
    const float* Wo = (const float*)d_in[7];
    const float* bo = (const float*)d_in[8];
    // d_in[9] = mask (causal; computed implicitly)
    float* out = (float*)d_out;

    float *Qp, *Kp, *Vp, *Op, *Xp, *Wqp, *Wkp, *Wvp, *Wop, *Kpp, *Vpp;
    cudaGetSymbolAddress((void**)&Qp, g_Q);
    cudaGetSymbolAddress((void**)&Kp, g_K);
    cudaGetSymbolAddress((void**)&Vp, g_V);
    cudaGetSymbolAddress((void**)&Op, g_O);
    cudaGetSymbolAddress((void**)&Xp, g_X);
    cudaGetSymbolAddress((void**)&Wqp, g_Wq);
    cudaGetSymbolAddress((void**)&Wkp, g_Wk);
    cudaGetSymbolAddress((void**)&Wvp, g_Wv);
    cudaGetSymbolAddress((void**)&Wop, g_Wo);
    cudaGetSymbolAddress((void**)&Kpp, g_Kp);
    cudaGetSymbolAddress((void**)&Vpp, g_Vp);

    // fused pre-round (one launch)
    round_all_kernel<<<(N4_TOTAL + 255) / 256, 256>>>(
        (const float4*)x,  (float4*)Xp,
        (const float4*)Wq, (float4*)Wqp,
        (const float4*)Wk, (float4*)Wkp,
        (const float4*)Wv, (float4*)Wvp,
        (const float4*)Wo, (float4*)Wop);

    size_t gemm_smem = (size_t)GSTAGES * GSTG * sizeof(uint32_t);   // 107520 B

    // fused QKV projection
    {
        cudaFuncSetAttribute(gemm_qkv_fused, cudaFuncAttributeMaxDynamicSharedMemorySize,
                             (int)gemm_smem);
        dim3 g(12, BS / GBM);
        gemm_qkv_fused<<<g, 128, gemm_smem>>>(Xp, Wqp, bq, Qp, Wkp, bk, Kp, Wvp, bv, Vp);
    }

    // repack K/V into fragment order
    {
        dim3 g(SEQ / 64, BATCH * KV_HEADS, 2);
        repack_kv_kernel<<<g, 128>>>(Kp, Vp, Kpp, Vpp);
    }

    // flash attention
    {
        size_t smem = (size_t)(2 * FA_STG) * sizeof(uint32_t);   // 65536 B
        cudaFuncSetAttribute(fa_mma_kernel, cudaFuncAttributeMaxDynamicSharedMemorySize,
                             (int)smem);
        dim3 g(BATCH * N_HEADS, SEQ / 64);
        fa_mma_kernel<<<g, 128, smem>>>(Qp, Kpp, Vpp, Op);
    }

    // output projection
    {
        cudaFuncSetAttribute(gemm_tf32_bias, cudaFuncAttributeMaxDynamicSharedMemorySize,
                             (int)gemm_smem);
        dim3 go(D_MODEL / GBN, BS / GBM);
        gemm_tf32_bias<<<go, 128, gemm_smem>>>(Op, Wop, bo, out, BS, D_MODEL, D_MODEL);
    }
}